// round 6
// baseline (speedup 1.0000x reference)
#include <cuda_runtime.h>
#include <cuda_bf16.h>
#include <cstdint>

// ---------------------------------------------------------------------------
// SpatialEncoder: bi-level routing attention.
// GEMMs: mma.sync bf16 split-precision (3-product), register-prefetch pipeline.
// attend: fused attention + lepe (depthwise 3x3 over cross-branch V).
// pool: one thread per channel, 16 sector accumulators.
// ---------------------------------------------------------------------------

#define NB    4
#define HH    128
#define WW    128
#define DIM   256
#define QK    256
#define CKV   512
#define QKVC  768
#define NW    8
#define P2    64
#define W2    256
#define W2KV  16
#define TOPK  4
#define HEADS 8
#define DH    32
#define TOK   (NB*P2*W2)
#define SCALEF 0.0625f

typedef unsigned long long u64;
typedef unsigned int u32;

// ---- packed f32x2 helpers --------------------------------------------------
__device__ __forceinline__ u64 pack2(float x, float y){
    u64 r; asm("mov.b64 %0,{%1,%2};" : "=l"(r) : "f"(x), "f"(y)); return r;
}
__device__ __forceinline__ u64 dup2(float x){
    u64 r; asm("mov.b64 %0,{%1,%1};" : "=l"(r) : "f"(x)); return r;
}
__device__ __forceinline__ void fma2(u64 &a, u64 b, u64 c){
    asm("fma.rn.f32x2 %0,%1,%2,%0;" : "+l"(a) : "l"(b), "l"(c));
}
__device__ __forceinline__ u64 mul2(u64 a, u64 b){
    u64 r; asm("mul.rn.f32x2 %0,%1,%2;" : "=l"(r) : "l"(a), "l"(b)); return r;
}
__device__ __forceinline__ float2 unp2(u64 v){
    float lo, hi; asm("mov.b64 {%0,%1},%2;" : "=f"(lo), "=f"(hi) : "l"(v));
    return make_float2(lo, hi);
}

__device__ __forceinline__ u32 smem_u32(const void* p){
    u32 a; asm("{ .reg .u64 t; cvta.to.shared.u64 t, %1; cvt.u32.u64 %0, t; }"
               : "=r"(a) : "l"(p));
    return a;
}

// fp32 -> (bf16 hi, bf16 lo) for a float4, packed as two u64 (4 bf16 each)
__device__ __forceinline__ void cvt4(float4 v, u64& hi, u64& lo){
    float f0=v.x, f1=v.y, f2=v.z, f3=v.w;
    __nv_bfloat16 h0=__float2bfloat16_rn(f0), h1=__float2bfloat16_rn(f1);
    __nv_bfloat16 h2=__float2bfloat16_rn(f2), h3=__float2bfloat16_rn(f3);
    unsigned short a0=__bfloat16_as_ushort(h0), a1=__bfloat16_as_ushort(h1);
    unsigned short a2=__bfloat16_as_ushort(h2), a3=__bfloat16_as_ushort(h3);
    hi = (u64)a0 | ((u64)a1<<16) | ((u64)a2<<32) | ((u64)a3<<48);
    unsigned short b0=__bfloat16_as_ushort(__float2bfloat16_rn(f0-__bfloat162float(h0)));
    unsigned short b1=__bfloat16_as_ushort(__float2bfloat16_rn(f1-__bfloat162float(h1)));
    unsigned short b2=__bfloat16_as_ushort(__float2bfloat16_rn(f2-__bfloat162float(h2)));
    unsigned short b3=__bfloat16_as_ushort(__float2bfloat16_rn(f3-__bfloat162float(h3)));
    lo = (u64)b0 | ((u64)b1<<16) | ((u64)b2<<32) | ((u64)b3<<48);
}

__device__ __forceinline__ void ldmx4(u32 addr, u32& r0, u32& r1, u32& r2, u32& r3){
    asm volatile("ldmatrix.sync.aligned.m8n8.x4.shared.b16 {%0,%1,%2,%3},[%4];"
                 : "=r"(r0),"=r"(r1),"=r"(r2),"=r"(r3) : "r"(addr));
}
__device__ __forceinline__ void mma16816(float* c, const u32* a, const u32* b){
    asm volatile("mma.sync.aligned.m16n8k16.row.col.f32.bf16.bf16.f32 "
        "{%0,%1,%2,%3},{%4,%5,%6,%7},{%8,%9},{%0,%1,%2,%3};"
        : "+f"(c[0]),"+f"(c[1]),"+f"(c[2]),"+f"(c[3])
        : "r"(a[0]),"r"(a[1]),"r"(a[2]),"r"(a[3]),"r"(b[0]),"r"(b[1]));
}

// -------- scratch -----------------------------------------------------------
__device__ float g_qkv [2][(size_t)TOK*QKVC];
__device__ float g_pool[2][NB*P2*W2KV*CKV];
__device__ float g_qwin[2][NB*P2*QK];
__device__ float g_kwin[2][NB*P2*QK];
__device__ int   g_idx [2][NB*P2*TOPK];
__device__ float g_att [2][(size_t)NB*HH*WW*DIM];

// ------------------------- HMMA split-bf16 GEMM -----------------------------
// BM=BN=128, BK=32; 8 warps (2 m x 4 n), warp tile 64x32.
// D += Ah*Bh + Ah*Bl + Al*Bh (fp32 accumulate). Register-prefetch pipeline.
#define PAD 40

__global__ __launch_bounds__(256) void k_mma_gemm(
    const float* __restrict__ Aext, int a_sel,
    const float* __restrict__ Wm, const float* __restrict__ bias,
    float* __restrict__ Oext, int o_sel, int ostride)
{
    __shared__ __nv_bfloat16 sAh[128*PAD], sAl[128*PAD];
    __shared__ __nv_bfloat16 sBh[128*PAD], sBl[128*PAD];

    const int tid = threadIdx.x;
    const int wid = tid >> 5;
    const int lid = tid & 31;
    const int t0  = blockIdx.y * 128;
    const int jn0 = blockIdx.x * 128;

    const float* A = (a_sel == 0) ? Aext : g_att[a_sel - 1];
    float* O = (o_sel < 2) ? g_qkv[o_sel] : Oext;

    const int m_base = (wid >> 2) * 64;
    const int n_base = (wid & 3) * 32;

    const int lrow = tid >> 3;
    const int lcg  = tid & 7;

    const float* arow[4];
    #pragma unroll
    for (int i = 0; i < 4; i++) {
        const int row = lrow + i * 32;
        if (a_sel == 0) {
            const int ltok = t0 + row;
            const int n = ltok >> 14, r = ltok & 16383;
            const int win = r >> 8, pix = r & 255;
            const int h = ((win >> 3) << 4) | (pix >> 4);
            const int w = ((win & 7) << 4) | (pix & 15);
            arow[i] = A + ((size_t)(((n << 7) + h) << 7) + w) * DIM + lcg * 4;
        } else {
            arow[i] = A + (size_t)(t0 + row) * DIM + lcg * 4;
        }
    }
    const float* brow[4];
    #pragma unroll
    for (int i = 0; i < 4; i++)
        brow[i] = Wm + (size_t)(jn0 + lrow + i * 32) * 256 + lcg * 4;

    const u32 uAh = smem_u32(sAh), uAl = smem_u32(sAl);
    const u32 uBh = smem_u32(sBh), uBl = smem_u32(sBl);

    const int a_r  = lid & 15;
    const int a_kh = lid >> 4;
    const int b_r  = (lid & 7) | ((lid >> 4) << 3);
    const int b_kh = (lid >> 3) & 1;

    float acc[4][4][4];
    #pragma unroll
    for (int mt = 0; mt < 4; mt++)
        #pragma unroll
        for (int nt = 0; nt < 4; nt++)
            #pragma unroll
            for (int r = 0; r < 4; r++) acc[mt][nt][r] = 0.f;

    // prefetch chunk 0
    float4 ra[4], rb[4];
    #pragma unroll
    for (int i = 0; i < 4; i++) { ra[i] = *(const float4*)(arow[i]); rb[i] = *(const float4*)(brow[i]); }

    for (int ch = 0; ch < 8; ch++) {
        __syncthreads();
        #pragma unroll
        for (int i = 0; i < 4; i++) {
            const int off = (lrow + i * 32) * PAD + lcg * 4;
            u64 hi, lo;
            cvt4(ra[i], hi, lo);
            *(u64*)(sAh + off) = hi;  *(u64*)(sAl + off) = lo;
            cvt4(rb[i], hi, lo);
            *(u64*)(sBh + off) = hi;  *(u64*)(sBl + off) = lo;
        }
        __syncthreads();
        if (ch < 7) {
            const int k1 = (ch + 1) * 32;
            #pragma unroll
            for (int i = 0; i < 4; i++) {
                ra[i] = *(const float4*)(arow[i] + k1);
                rb[i] = *(const float4*)(brow[i] + k1);
            }
        }
        #pragma unroll
        for (int s = 0; s < 2; s++) {
            const int koff = s * 16;
            u32 ah[4][4], al[4][4], bh[4][2], bl[4][2];
            #pragma unroll
            for (int mt = 0; mt < 4; mt++) {
                const u32 eoff = (u32)((m_base + mt*16 + a_r) * PAD + koff + a_kh*8) * 2;
                ldmx4(uAh + eoff, ah[mt][0], ah[mt][1], ah[mt][2], ah[mt][3]);
                ldmx4(uAl + eoff, al[mt][0], al[mt][1], al[mt][2], al[mt][3]);
            }
            #pragma unroll
            for (int p = 0; p < 2; p++) {
                const u32 eoff = (u32)((n_base + p*16 + b_r) * PAD + koff + b_kh*8) * 2;
                ldmx4(uBh + eoff, bh[2*p][0], bh[2*p][1], bh[2*p+1][0], bh[2*p+1][1]);
                ldmx4(uBl + eoff, bl[2*p][0], bl[2*p][1], bl[2*p+1][0], bl[2*p+1][1]);
            }
            #pragma unroll
            for (int mt = 0; mt < 4; mt++)
                #pragma unroll
                for (int nt = 0; nt < 4; nt++) {
                    mma16816(acc[mt][nt], ah[mt], bh[nt]);
                    mma16816(acc[mt][nt], ah[mt], bl[nt]);
                    mma16816(acc[mt][nt], al[mt], bh[nt]);
                }
        }
    }

    const int qr = lid >> 2;
    const int qc = (lid & 3) * 2;
    #pragma unroll
    for (int mt = 0; mt < 4; mt++) {
        const int row0 = t0 + m_base + mt*16 + qr;
        #pragma unroll
        for (int nt = 0; nt < 4; nt++) {
            const int col = jn0 + n_base + nt*8 + qc;
            const float b0 = bias[col], b1 = bias[col+1];
            float2 v0 = make_float2(acc[mt][nt][0] + b0, acc[mt][nt][1] + b1);
            float2 v1 = make_float2(acc[mt][nt][2] + b0, acc[mt][nt][3] + b1);
            *(float2*)(O + (size_t)row0 * ostride + col)       = v0;
            *(float2*)(O + (size_t)(row0+8) * ostride + col)   = v1;
        }
    }
}

// ------------------------------ pooling ------------------------------------
// one block per window, 768 threads (one per qkv channel), 16 sector accums.
__global__ __launch_bounds__(768) void k_pool(int b)
{
    const int nwin = blockIdx.x;
    const int tid = threadIdx.x;
    const float* base = g_qkv[b] + (size_t)nwin * W2 * QKVC + tid;

    float s[16];
    #pragma unroll
    for (int i = 0; i < 16; i++) s[i] = 0.f;
    #pragma unroll 4
    for (int py = 0; py < 16; py++) {
        const int sr = (py >> 2) << 2;
        #pragma unroll
        for (int px = 0; px < 16; px++)
            s[sr + (px >> 2)] += base[(size_t)(py*16 + px) * QKVC];
    }
    float tot = 0.f;
    #pragma unroll
    for (int i = 0; i < 16; i++) tot += s[i];

    if (tid < QK) {
        g_qwin[b][nwin*QK + tid] = tot * (1.f/256.f);
    } else {
        const int c = tid - QK;            // kv channel 0..511
        #pragma unroll
        for (int i = 0; i < 16; i++)
            g_pool[b][(size_t)(nwin*W2KV + i)*CKV + c] = s[i] * (1.f/16.f);
        if (c < QK)
            g_kwin[b][nwin*QK + c] = tot * (1.f/256.f);
    }
}

// ------------------------------ routing ------------------------------------
__global__ void k_route(int qb, int kb, int ib)
{
    const int i = blockIdx.x;
    const int n = blockIdx.y;
    const int j = threadIdx.x;
    const float* qp = g_qwin[qb] + (size_t)(n*P2 + i)*QK;
    const float* kp = g_kwin[kb] + (size_t)(n*P2 + j)*QK;
    float s = 0.f;
    for (int c = 0; c < QK; c++) s += qp[c]*kp[c];
    s *= SCALEF;
    if (j == i) s = 1.0f;
    __shared__ float lg[P2];
    lg[j] = s;
    __syncthreads();
    if (j == 0) {
        #pragma unroll
        for (int t = 0; t < TOPK; t++) {
            float best = -1e30f; int bi = 0;
            for (int u = 0; u < P2; u++)
                if (lg[u] > best) { best = lg[u]; bi = u; }
            g_idx[ib][(n*P2 + i)*TOPK + t] = bi;
            lg[bi] = -1e30f;
        }
    }
}

// ------------------- attention + fused lepe ---------------------------------
// one block per (window, head); thread = query pixel; 64 gathered KV tokens.
// epilogue adds depthwise 3x3 over V of the kv branch (channels head*32..+32).
__global__ __launch_bounds__(256) void k_attend(int qb, int kvb, int ib, int ob,
    const float* __restrict__ lw, const float* __restrict__ lb)
{
    const int nwin = blockIdx.x;
    const int head = blockIdx.y;
    const int n   = nwin >> 6;
    const int win = nwin & 63;
    const int tid = threadIdx.x;

    __shared__ float ks[64][32];
    __shared__ float vs[64][32];
    __shared__ float swt[DH*9];     // 288 > blockDim: grid-stride load!
    __shared__ float sbias[DH];
    __shared__ int sel[TOPK];
    if (tid < TOPK) sel[tid] = g_idx[ib][nwin*TOPK + tid];
    for (int e = tid; e < DH*9; e += 256) swt[e] = lw[head*DH*9 + e];
    if (tid < DH) sbias[tid] = lb[head*DH + tid];
    __syncthreads();

    for (int e = tid; e < 64*32; e += 256) {
        const int tkn = e >> 5, c = e & 31;
        const int sw  = sel[tkn >> 4];
        const float* pp = g_pool[kvb] + (size_t)((n*P2 + sw)*W2KV + (tkn & 15))*CKV;
        ks[tkn][c] = pp[head*DH + c];
        vs[tkn][c] = pp[QK + head*DH + c];
    }
    __syncthreads();

    const int pix = tid;
    const float* qp = g_qkv[qb] + (size_t)(nwin*W2 + pix)*QKVC + head*DH;
    u64 qd[16];
    #pragma unroll
    for (int c = 0; c < 16; c++)
        qd[c] = pack2(qp[2*c] * SCALEF, qp[2*c+1] * SCALEF);

    float lg[64];
    float mx = -1e30f;
    #pragma unroll
    for (int t = 0; t < 64; t++) {
        const u64* kr = (const u64*)ks[t];
        u64 ac = 0ull;
        #pragma unroll
        for (int c = 0; c < 16; c++) fma2(ac, qd[c], kr[c]);
        const float2 pr = unp2(ac);
        const float s = pr.x + pr.y;
        lg[t] = s;
        mx = fmaxf(mx, s);
    }
    float den = 0.f;
    #pragma unroll
    for (int t = 0; t < 64; t++) { lg[t] = expf(lg[t] - mx); den += lg[t]; }
    const float inv = 1.f / den;

    u64 o[16];
    #pragma unroll
    for (int c = 0; c < 16; c++) o[c] = 0ull;
    #pragma unroll
    for (int t = 0; t < 64; t++) {
        const u64 pd = dup2(lg[t]);
        const u64* vr = (const u64*)vs[t];
        #pragma unroll
        for (int c = 0; c < 16; c++) fma2(o[c], pd, vr[c]);
    }

    // ---- epilogue: res = attn*inv + bias + depthwise3x3(V_kvb) ----
    float res[DH];
    #pragma unroll
    for (int c = 0; c < 16; c++) {
        const float2 pr = unp2(o[c]);
        res[2*c]   = pr.x * inv + sbias[2*c];
        res[2*c+1] = pr.y * inv + sbias[2*c+1];
    }

    const int h = ((win >> 3) << 4) | (pix >> 4);
    const int w = ((win & 7)  << 4) | (pix & 15);

    #pragma unroll
    for (int dy = 0; dy < 3; dy++) {
        const int hh = h + dy - 1;
        if ((unsigned)hh >= (unsigned)HH) continue;
        #pragma unroll
        for (int dx = 0; dx < 3; dx++) {
            const int ww2 = w + dx - 1;
            if ((unsigned)ww2 >= (unsigned)WW) continue;
            const int vwin = ((hh >> 4) << 3) | (ww2 >> 4);
            const int vpix = ((hh & 15) << 4) | (ww2 & 15);
            const float* vp = g_qkv[kvb]
                + (size_t)(((n << 6) | vwin)*W2 + vpix)*QKVC + CKV + head*DH;
            const int j = dy*3 + dx;
            #pragma unroll
            for (int cg = 0; cg < 8; cg++) {
                const float4 v = *(const float4*)(vp + cg*4);
                res[cg*4]   += v.x * swt[(cg*4)  *9 + j];
                res[cg*4+1] += v.y * swt[(cg*4+1)*9 + j];
                res[cg*4+2] += v.z * swt[(cg*4+2)*9 + j];
                res[cg*4+3] += v.w * swt[(cg*4+3)*9 + j];
            }
        }
    }

    float* op = g_att[ob] + (size_t)(((n << 7) + h)*WW + w)*DIM + head*DH;
    #pragma unroll
    for (int cg = 0; cg < 8; cg++)
        *(float4*)(op + cg*4) = make_float4(res[cg*4], res[cg*4+1], res[cg*4+2], res[cg*4+3]);
}

// ------------------------------- launch ------------------------------------
extern "C" void kernel_launch(void* const* d_in, const int* in_sizes, int n_in,
                              void* d_out, int out_size)
{
    const float* x1   = (const float*)d_in[0];
    const float* x2   = (const float*)d_in[1];
    const float* Wqkv = (const float*)d_in[2];
    const float* bqkv = (const float*)d_in[3];
    const float* lw   = (const float*)d_in[4];
    const float* lb   = (const float*)d_in[5];
    const float* Wo   = (const float*)d_in[6];
    const float* bo   = (const float*)d_in[7];
    float* out = (float*)d_out;

    const dim3 gq(QKVC/128, TOK/128);   // (6, 512)
    k_mma_gemm<<<gq, 256>>>(x1, 0, Wqkv, bqkv, nullptr, 0, QKVC);
    k_mma_gemm<<<gq, 256>>>(x2, 0, Wqkv, bqkv, nullptr, 1, QKVC);

    k_pool<<<NB*P2, 768>>>(0);
    k_pool<<<NB*P2, 768>>>(1);

    k_route<<<dim3(P2, NB), 64>>>(1, 0, 0);
    k_route<<<dim3(P2, NB), 64>>>(0, 1, 1);

    // out1 = attend(q2, kv1, idx1) + lepe(v1);  out2 = attend(q1, kv2, idx2) + lepe(v2)
    k_attend<<<dim3(NB*P2, HEADS), 256>>>(1, 0, 0, 0, lw, lb);
    k_attend<<<dim3(NB*P2, HEADS), 256>>>(0, 1, 1, 1, lw, lb);

    const dim3 gp(DIM/128, TOK/128);    // (2, 512)
    const size_t half = (size_t)NB*HH*WW*DIM;
    k_mma_gemm<<<gp, 256>>>(nullptr, 1, Wo, bo, out, 2, DIM);
    k_mma_gemm<<<gp, 256>>>(nullptr, 2, Wo, bo, out + half, 2, DIM);
}

// round 7
// speedup vs baseline: 1.1145x; 1.1145x over previous
#include <cuda_runtime.h>
#include <cuda_bf16.h>
#include <cstdint>

// ---------------------------------------------------------------------------
// SpatialEncoder: bi-level routing attention.
// GEMMs: mma.sync bf16 split-precision (3-product) + register prefetch.
// pool: 768 threads, 16 sector accumulators.  lepe: 4-pixel blocks, coalesced.
// ---------------------------------------------------------------------------

#define NB    4
#define HH    128
#define WW    128
#define DIM   256
#define QK    256
#define CKV   512
#define QKVC  768
#define NW    8
#define P2    64
#define W2    256
#define W2KV  16
#define TOPK  4
#define HEADS 8
#define DH    32
#define TOK   (NB*P2*W2)
#define SCALEF 0.0625f

typedef unsigned long long u64;
typedef unsigned int u32;

// ---- packed f32x2 helpers --------------------------------------------------
__device__ __forceinline__ u64 pack2(float x, float y){
    u64 r; asm("mov.b64 %0,{%1,%2};" : "=l"(r) : "f"(x), "f"(y)); return r;
}
__device__ __forceinline__ u64 dup2(float x){
    u64 r; asm("mov.b64 %0,{%1,%1};" : "=l"(r) : "f"(x)); return r;
}
__device__ __forceinline__ void fma2(u64 &a, u64 b, u64 c){
    asm("fma.rn.f32x2 %0,%1,%2,%0;" : "+l"(a) : "l"(b), "l"(c));
}
__device__ __forceinline__ u64 mul2(u64 a, u64 b){
    u64 r; asm("mul.rn.f32x2 %0,%1,%2;" : "=l"(r) : "l"(a), "l"(b)); return r;
}
__device__ __forceinline__ float2 unp2(u64 v){
    float lo, hi; asm("mov.b64 {%0,%1},%2;" : "=f"(lo), "=f"(hi) : "l"(v));
    return make_float2(lo, hi);
}

__device__ __forceinline__ u32 smem_u32(const void* p){
    u32 a; asm("{ .reg .u64 t; cvta.to.shared.u64 t, %1; cvt.u32.u64 %0, t; }"
               : "=r"(a) : "l"(p));
    return a;
}

// fp32 -> (bf16 hi, bf16 lo) for a float4, packed as two u64 (4 bf16 each)
__device__ __forceinline__ void cvt4(float4 v, u64& hi, u64& lo){
    float f0=v.x, f1=v.y, f2=v.z, f3=v.w;
    __nv_bfloat16 h0=__float2bfloat16_rn(f0), h1=__float2bfloat16_rn(f1);
    __nv_bfloat16 h2=__float2bfloat16_rn(f2), h3=__float2bfloat16_rn(f3);
    unsigned short a0=__bfloat16_as_ushort(h0), a1=__bfloat16_as_ushort(h1);
    unsigned short a2=__bfloat16_as_ushort(h2), a3=__bfloat16_as_ushort(h3);
    hi = (u64)a0 | ((u64)a1<<16) | ((u64)a2<<32) | ((u64)a3<<48);
    unsigned short b0=__bfloat16_as_ushort(__float2bfloat16_rn(f0-__bfloat162float(h0)));
    unsigned short b1=__bfloat16_as_ushort(__float2bfloat16_rn(f1-__bfloat162float(h1)));
    unsigned short b2=__bfloat16_as_ushort(__float2bfloat16_rn(f2-__bfloat162float(h2)));
    unsigned short b3=__bfloat16_as_ushort(__float2bfloat16_rn(f3-__bfloat162float(h3)));
    lo = (u64)b0 | ((u64)b1<<16) | ((u64)b2<<32) | ((u64)b3<<48);
}

__device__ __forceinline__ void ldmx4(u32 addr, u32& r0, u32& r1, u32& r2, u32& r3){
    asm volatile("ldmatrix.sync.aligned.m8n8.x4.shared.b16 {%0,%1,%2,%3},[%4];"
                 : "=r"(r0),"=r"(r1),"=r"(r2),"=r"(r3) : "r"(addr));
}
__device__ __forceinline__ void mma16816(float* c, const u32* a, const u32* b){
    asm volatile("mma.sync.aligned.m16n8k16.row.col.f32.bf16.bf16.f32 "
        "{%0,%1,%2,%3},{%4,%5,%6,%7},{%8,%9},{%0,%1,%2,%3};"
        : "+f"(c[0]),"+f"(c[1]),"+f"(c[2]),"+f"(c[3])
        : "r"(a[0]),"r"(a[1]),"r"(a[2]),"r"(a[3]),"r"(b[0]),"r"(b[1]));
}

// -------- scratch -----------------------------------------------------------
__device__ float g_qkv [2][(size_t)TOK*QKVC];
__device__ float g_pool[2][NB*P2*W2KV*CKV];
__device__ float g_qwin[2][NB*P2*QK];
__device__ float g_kwin[2][NB*P2*QK];
__device__ int   g_idx [2][NB*P2*TOPK];
__device__ float g_att [2][(size_t)NB*HH*WW*DIM];

// ------------------------- HMMA split-bf16 GEMM -----------------------------
#define PAD 40

__global__ __launch_bounds__(256) void k_mma_gemm(
    const float* __restrict__ Aext, int a_sel,
    const float* __restrict__ Wm, const float* __restrict__ bias,
    float* __restrict__ Oext, int o_sel, int ostride)
{
    __shared__ __nv_bfloat16 sAh[128*PAD], sAl[128*PAD];
    __shared__ __nv_bfloat16 sBh[128*PAD], sBl[128*PAD];

    const int tid = threadIdx.x;
    const int wid = tid >> 5;
    const int lid = tid & 31;
    const int t0  = blockIdx.y * 128;
    const int jn0 = blockIdx.x * 128;

    const float* A = (a_sel == 0) ? Aext : g_att[a_sel - 1];
    float* O = (o_sel < 2) ? g_qkv[o_sel] : Oext;

    const int m_base = (wid >> 2) * 64;
    const int n_base = (wid & 3) * 32;

    const int lrow = tid >> 3;
    const int lcg  = tid & 7;

    const float* arow[4];
    #pragma unroll
    for (int i = 0; i < 4; i++) {
        const int row = lrow + i * 32;
        if (a_sel == 0) {
            const int ltok = t0 + row;
            const int n = ltok >> 14, r = ltok & 16383;
            const int win = r >> 8, pix = r & 255;
            const int h = ((win >> 3) << 4) | (pix >> 4);
            const int w = ((win & 7) << 4) | (pix & 15);
            arow[i] = A + ((size_t)(((n << 7) + h) << 7) + w) * DIM + lcg * 4;
        } else {
            arow[i] = A + (size_t)(t0 + row) * DIM + lcg * 4;
        }
    }
    const float* brow[4];
    #pragma unroll
    for (int i = 0; i < 4; i++)
        brow[i] = Wm + (size_t)(jn0 + lrow + i * 32) * 256 + lcg * 4;

    const u32 uAh = smem_u32(sAh), uAl = smem_u32(sAl);
    const u32 uBh = smem_u32(sBh), uBl = smem_u32(sBl);

    const int a_r  = lid & 15;
    const int a_kh = lid >> 4;
    const int b_r  = (lid & 7) | ((lid >> 4) << 3);
    const int b_kh = (lid >> 3) & 1;

    float acc[4][4][4];
    #pragma unroll
    for (int mt = 0; mt < 4; mt++)
        #pragma unroll
        for (int nt = 0; nt < 4; nt++)
            #pragma unroll
            for (int r = 0; r < 4; r++) acc[mt][nt][r] = 0.f;

    float4 ra[4], rb[4];
    #pragma unroll
    for (int i = 0; i < 4; i++) { ra[i] = *(const float4*)(arow[i]); rb[i] = *(const float4*)(brow[i]); }

    for (int ch = 0; ch < 8; ch++) {
        __syncthreads();
        #pragma unroll
        for (int i = 0; i < 4; i++) {
            const int off = (lrow + i * 32) * PAD + lcg * 4;
            u64 hi, lo;
            cvt4(ra[i], hi, lo);
            *(u64*)(sAh + off) = hi;  *(u64*)(sAl + off) = lo;
            cvt4(rb[i], hi, lo);
            *(u64*)(sBh + off) = hi;  *(u64*)(sBl + off) = lo;
        }
        __syncthreads();
        if (ch < 7) {
            const int k1 = (ch + 1) * 32;
            #pragma unroll
            for (int i = 0; i < 4; i++) {
                ra[i] = *(const float4*)(arow[i] + k1);
                rb[i] = *(const float4*)(brow[i] + k1);
            }
        }
        #pragma unroll
        for (int s = 0; s < 2; s++) {
            const int koff = s * 16;
            u32 ah[4][4], al[4][4], bh[4][2], bl[4][2];
            #pragma unroll
            for (int mt = 0; mt < 4; mt++) {
                const u32 eoff = (u32)((m_base + mt*16 + a_r) * PAD + koff + a_kh*8) * 2;
                ldmx4(uAh + eoff, ah[mt][0], ah[mt][1], ah[mt][2], ah[mt][3]);
                ldmx4(uAl + eoff, al[mt][0], al[mt][1], al[mt][2], al[mt][3]);
            }
            #pragma unroll
            for (int p = 0; p < 2; p++) {
                const u32 eoff = (u32)((n_base + p*16 + b_r) * PAD + koff + b_kh*8) * 2;
                ldmx4(uBh + eoff, bh[2*p][0], bh[2*p][1], bh[2*p+1][0], bh[2*p+1][1]);
                ldmx4(uBl + eoff, bl[2*p][0], bl[2*p][1], bl[2*p+1][0], bl[2*p+1][1]);
            }
            #pragma unroll
            for (int mt = 0; mt < 4; mt++)
                #pragma unroll
                for (int nt = 0; nt < 4; nt++) {
                    mma16816(acc[mt][nt], ah[mt], bh[nt]);
                    mma16816(acc[mt][nt], ah[mt], bl[nt]);
                    mma16816(acc[mt][nt], al[mt], bh[nt]);
                }
        }
    }

    const int qr = lid >> 2;
    const int qc = (lid & 3) * 2;
    #pragma unroll
    for (int mt = 0; mt < 4; mt++) {
        const int row0 = t0 + m_base + mt*16 + qr;
        #pragma unroll
        for (int nt = 0; nt < 4; nt++) {
            const int col = jn0 + n_base + nt*8 + qc;
            const float b0 = bias[col], b1 = bias[col+1];
            float2 v0 = make_float2(acc[mt][nt][0] + b0, acc[mt][nt][1] + b1);
            float2 v1 = make_float2(acc[mt][nt][2] + b0, acc[mt][nt][3] + b1);
            *(float2*)(O + (size_t)row0 * ostride + col)       = v0;
            *(float2*)(O + (size_t)(row0+8) * ostride + col)   = v1;
        }
    }
}

// ------------------------------ pooling ------------------------------------
__global__ __launch_bounds__(768) void k_pool(int b)
{
    const int nwin = blockIdx.x;
    const int tid = threadIdx.x;
    const float* base = g_qkv[b] + (size_t)nwin * W2 * QKVC + tid;

    float s[16];
    #pragma unroll
    for (int i = 0; i < 16; i++) s[i] = 0.f;
    #pragma unroll 4
    for (int py = 0; py < 16; py++) {
        const int sr = (py >> 2) << 2;
        #pragma unroll
        for (int px = 0; px < 16; px++)
            s[sr + (px >> 2)] += base[(size_t)(py*16 + px) * QKVC];
    }
    float tot = 0.f;
    #pragma unroll
    for (int i = 0; i < 16; i++) tot += s[i];

    if (tid < QK) {
        g_qwin[b][nwin*QK + tid] = tot * (1.f/256.f);
    } else {
        const int c = tid - QK;
        #pragma unroll
        for (int i = 0; i < 16; i++)
            g_pool[b][(size_t)(nwin*W2KV + i)*CKV + c] = s[i] * (1.f/16.f);
        if (c < QK)
            g_kwin[b][nwin*QK + c] = tot * (1.f/256.f);
    }
}

// ------------------------------ routing ------------------------------------
__global__ void k_route(int qb, int kb, int ib)
{
    const int i = blockIdx.x;
    const int n = blockIdx.y;
    const int j = threadIdx.x;
    const float* qp = g_qwin[qb] + (size_t)(n*P2 + i)*QK;
    const float* kp = g_kwin[kb] + (size_t)(n*P2 + j)*QK;
    float s = 0.f;
    for (int c = 0; c < QK; c++) s += qp[c]*kp[c];
    s *= SCALEF;
    if (j == i) s = 1.0f;
    __shared__ float lg[P2];
    lg[j] = s;
    __syncthreads();
    if (j == 0) {
        #pragma unroll
        for (int t = 0; t < TOPK; t++) {
            float best = -1e30f; int bi = 0;
            for (int u = 0; u < P2; u++)
                if (lg[u] > best) { best = lg[u]; bi = u; }
            g_idx[ib][(n*P2 + i)*TOPK + t] = bi;
            lg[bi] = -1e30f;
        }
    }
}

// ----------------------------- attention -----------------------------------
__global__ __launch_bounds__(256) void k_attend(int qb, int kvb, int ib, int ob)
{
    const int nwin = blockIdx.x;
    const int head = blockIdx.y;
    const int n   = nwin >> 6;
    const int win = nwin & 63;
    const int tid = threadIdx.x;

    __shared__ float ks[64][32];
    __shared__ float vs[64][32];
    __shared__ int sel[TOPK];
    if (tid < TOPK) sel[tid] = g_idx[ib][nwin*TOPK + tid];
    __syncthreads();

    for (int e = tid; e < 64*32; e += 256) {
        const int tkn = e >> 5, c = e & 31;
        const int sw  = sel[tkn >> 4];
        const float* pp = g_pool[kvb] + (size_t)((n*P2 + sw)*W2KV + (tkn & 15))*CKV;
        ks[tkn][c] = pp[head*DH + c];
        vs[tkn][c] = pp[QK + head*DH + c];
    }
    __syncthreads();

    const int pix = tid;
    const float* qp = g_qkv[qb] + (size_t)(nwin*W2 + pix)*QKVC + head*DH;
    u64 qd[16];
    #pragma unroll
    for (int c = 0; c < 16; c++)
        qd[c] = pack2(qp[2*c] * SCALEF, qp[2*c+1] * SCALEF);

    float lg[64];
    float mx = -1e30f;
    #pragma unroll
    for (int t = 0; t < 64; t++) {
        const u64* kr = (const u64*)ks[t];
        u64 ac = 0ull;
        #pragma unroll
        for (int c = 0; c < 16; c++) fma2(ac, qd[c], kr[c]);
        const float2 pr = unp2(ac);
        const float s = pr.x + pr.y;
        lg[t] = s;
        mx = fmaxf(mx, s);
    }
    float den = 0.f;
    #pragma unroll
    for (int t = 0; t < 64; t++) { lg[t] = expf(lg[t] - mx); den += lg[t]; }
    const float inv = 1.f / den;

    u64 o[16];
    #pragma unroll
    for (int c = 0; c < 16; c++) o[c] = 0ull;
    #pragma unroll
    for (int t = 0; t < 64; t++) {
        const u64 pd = dup2(lg[t]);
        const u64* vr = (const u64*)vs[t];
        #pragma unroll
        for (int c = 0; c < 16; c++) fma2(o[c], pd, vr[c]);
    }

    const int h = ((win >> 3) << 4) | (pix >> 4);
    const int w = ((win & 7)  << 4) | (pix & 15);
    float* op = g_att[ob] + (size_t)(((n << 7) + h)*WW + w)*DIM + head*DH;
    const u64 invd = dup2(inv);
    #pragma unroll
    for (int c = 0; c < 16; c++)
        *(u64*)(op + 2*c) = mul2(o[c], invd);
}

// --------------------------- lepe (depthwise 3x3) --------------------------
// one block per 4 consecutive w-pixels; thread = channel. Halo 3x6 shared.
__global__ __launch_bounds__(256) void k_lepe(int vb, int ob,
    const float* __restrict__ lw, const float* __restrict__ lb)
{
    __shared__ float swt[DIM*9];
    const int blk = blockIdx.x;               // n*4096 + h*32 + (w0/4)
    const int c = threadIdx.x;
    for (int e = c; e < DIM*9; e += 256) swt[e] = lw[e];
    __syncthreads();

    const int n  = blk >> 12;
    const int r  = blk & 4095;
    const int h  = r >> 5;
    const int w0 = (r & 31) << 2;

    const float* wrow = &swt[c*9];
    float acc[4];
    {
        float* op = g_att[ob] + (size_t)((((n << 7) + h) << 7) + w0)*DIM + c;
        const float bb = lb[c];
        #pragma unroll
        for (int k = 0; k < 4; k++) acc[k] = op[k*DIM] + bb;
    }

    #pragma unroll
    for (int dy = 0; dy < 3; dy++) {
        const int hh = h + dy - 1;
        if ((unsigned)hh >= (unsigned)HH) continue;
        #pragma unroll
        for (int cc = 0; cc < 6; cc++) {
            const int ww = w0 - 1 + cc;
            if ((unsigned)ww >= (unsigned)WW) continue;
            const int vwin = ((hh >> 4) << 3) | (ww >> 4);
            const int vpix = ((hh & 15) << 4) | (ww & 15);
            const float v = g_qkv[vb]
                [(size_t)(((n << 6) | vwin)*W2 + vpix)*QKVC + CKV + c];
            #pragma unroll
            for (int k = 0; k < 4; k++) {
                const int dx = cc - k;
                if (dx >= 0 && dx <= 2)
                    acc[k] += v * wrow[dy*3 + dx];
            }
        }
    }

    float* op = g_att[ob] + (size_t)((((n << 7) + h) << 7) + w0)*DIM + c;
    #pragma unroll
    for (int k = 0; k < 4; k++) op[k*DIM] = acc[k];
}

// ------------------------------- launch ------------------------------------
extern "C" void kernel_launch(void* const* d_in, const int* in_sizes, int n_in,
                              void* d_out, int out_size)
{
    const float* x1   = (const float*)d_in[0];
    const float* x2   = (const float*)d_in[1];
    const float* Wqkv = (const float*)d_in[2];
    const float* bqkv = (const float*)d_in[3];
    const float* lw   = (const float*)d_in[4];
    const float* lb   = (const float*)d_in[5];
    const float* Wo   = (const float*)d_in[6];
    const float* bo   = (const float*)d_in[7];
    float* out = (float*)d_out;

    const dim3 gq(QKVC/128, TOK/128);   // (6, 512)
    k_mma_gemm<<<gq, 256>>>(x1, 0, Wqkv, bqkv, nullptr, 0, QKVC);
    k_mma_gemm<<<gq, 256>>>(x2, 0, Wqkv, bqkv, nullptr, 1, QKVC);

    k_pool<<<NB*P2, 768>>>(0);
    k_pool<<<NB*P2, 768>>>(1);

    k_route<<<dim3(P2, NB), 64>>>(1, 0, 0);
    k_route<<<dim3(P2, NB), 64>>>(0, 1, 1);

    k_attend<<<dim3(NB*P2, HEADS), 256>>>(1, 0, 0, 0);
    k_attend<<<dim3(NB*P2, HEADS), 256>>>(0, 1, 1, 1);

    k_lepe<<<NB*HH*WW/4, 256>>>(0, 0, lw, lb);
    k_lepe<<<NB*HH*WW/4, 256>>>(1, 1, lw, lb);

    const dim3 gp(DIM/128, TOK/128);    // (2, 512)
    const size_t half = (size_t)NB*HH*WW*DIM;
    k_mma_gemm<<<gp, 256>>>(nullptr, 1, Wo, bo, out, 2, DIM);
    k_mma_gemm<<<gp, 256>>>(nullptr, 2, Wo, bo, out + half, 2, DIM);
}

// round 8
// speedup vs baseline: 1.1460x; 1.0283x over previous
#include <cuda_runtime.h>
#include <cuda_bf16.h>
#include <cstdint>

// ---------------------------------------------------------------------------
// SpatialEncoder: bi-level routing attention.
// GEMMs: mma.sync bf16 split-precision (3-product), double-buffered smem.
// All branch pairs merged into single launches via blockIdx.z.
// ---------------------------------------------------------------------------

#define NB    4
#define HH    128
#define WW    128
#define DIM   256
#define QK    256
#define CKV   512
#define QKVC  768
#define NW    8
#define P2    64
#define W2    256
#define W2KV  16
#define TOPK  4
#define HEADS 8
#define DH    32
#define TOK   (NB*P2*W2)
#define SCALEF 0.0625f

typedef unsigned long long u64;
typedef unsigned int u32;

// ---- packed f32x2 helpers --------------------------------------------------
__device__ __forceinline__ u64 pack2(float x, float y){
    u64 r; asm("mov.b64 %0,{%1,%2};" : "=l"(r) : "f"(x), "f"(y)); return r;
}
__device__ __forceinline__ u64 dup2(float x){
    u64 r; asm("mov.b64 %0,{%1,%1};" : "=l"(r) : "f"(x)); return r;
}
__device__ __forceinline__ void fma2(u64 &a, u64 b, u64 c){
    asm("fma.rn.f32x2 %0,%1,%2,%0;" : "+l"(a) : "l"(b), "l"(c));
}
__device__ __forceinline__ u64 mul2(u64 a, u64 b){
    u64 r; asm("mul.rn.f32x2 %0,%1,%2;" : "=l"(r) : "l"(a), "l"(b)); return r;
}
__device__ __forceinline__ float2 unp2(u64 v){
    float lo, hi; asm("mov.b64 {%0,%1},%2;" : "=f"(lo), "=f"(hi) : "l"(v));
    return make_float2(lo, hi);
}

__device__ __forceinline__ u32 smem_u32(const void* p){
    u32 a; asm("{ .reg .u64 t; cvta.to.shared.u64 t, %1; cvt.u32.u64 %0, t; }"
               : "=r"(a) : "l"(p));
    return a;
}

// fp32 -> (bf16 hi, bf16 lo) for a float4, packed as two u64 (4 bf16 each)
__device__ __forceinline__ void cvt4(float4 v, u64& hi, u64& lo){
    float f0=v.x, f1=v.y, f2=v.z, f3=v.w;
    __nv_bfloat16 h0=__float2bfloat16_rn(f0), h1=__float2bfloat16_rn(f1);
    __nv_bfloat16 h2=__float2bfloat16_rn(f2), h3=__float2bfloat16_rn(f3);
    unsigned short a0=__bfloat16_as_ushort(h0), a1=__bfloat16_as_ushort(h1);
    unsigned short a2=__bfloat16_as_ushort(h2), a3=__bfloat16_as_ushort(h3);
    hi = (u64)a0 | ((u64)a1<<16) | ((u64)a2<<32) | ((u64)a3<<48);
    unsigned short b0=__bfloat16_as_ushort(__float2bfloat16_rn(f0-__bfloat162float(h0)));
    unsigned short b1=__bfloat16_as_ushort(__float2bfloat16_rn(f1-__bfloat162float(h1)));
    unsigned short b2=__bfloat16_as_ushort(__float2bfloat16_rn(f2-__bfloat162float(h2)));
    unsigned short b3=__bfloat16_as_ushort(__float2bfloat16_rn(f3-__bfloat162float(h3)));
    lo = (u64)b0 | ((u64)b1<<16) | ((u64)b2<<32) | ((u64)b3<<48);
}

__device__ __forceinline__ void ldmx4(u32 addr, u32& r0, u32& r1, u32& r2, u32& r3){
    asm volatile("ldmatrix.sync.aligned.m8n8.x4.shared.b16 {%0,%1,%2,%3},[%4];"
                 : "=r"(r0),"=r"(r1),"=r"(r2),"=r"(r3) : "r"(addr));
}
__device__ __forceinline__ void mma16816(float* c, const u32* a, const u32* b){
    asm volatile("mma.sync.aligned.m16n8k16.row.col.f32.bf16.bf16.f32 "
        "{%0,%1,%2,%3},{%4,%5,%6,%7},{%8,%9},{%0,%1,%2,%3};"
        : "+f"(c[0]),"+f"(c[1]),"+f"(c[2]),"+f"(c[3])
        : "r"(a[0]),"r"(a[1]),"r"(a[2]),"r"(a[3]),"r"(b[0]),"r"(b[1]));
}

// -------- scratch -----------------------------------------------------------
__device__ float g_qkv [2][(size_t)TOK*QKVC];
__device__ float g_pool[2][NB*P2*W2KV*CKV];
__device__ float g_qwin[2][NB*P2*QK];
__device__ float g_kwin[2][NB*P2*QK];
__device__ int   g_idx [2][NB*P2*TOPK];
__device__ float g_att [2][(size_t)NB*HH*WW*DIM];

// ------------------------- HMMA split-bf16 GEMM -----------------------------
// BM=BN=128, BK=32; 8 warps (2m x 4n), warp tile 64x32; double-buffered smem.
#define PAD    40
#define TILE_E (128*PAD)               // 5120 bf16 per tile
#define STAGE_B (4*TILE_E*2)           // 40960 B per stage
#define GEMM_SMEM (2*STAGE_B)          // 80 KB

__global__ __launch_bounds__(256) void k_mma_gemm(
    const float* __restrict__ A0, const float* __restrict__ A1, int mode,
    const float* __restrict__ Wm, const float* __restrict__ bias,
    float* __restrict__ Oext, int ostride)
{
    extern __shared__ __nv_bfloat16 smx[];

    const int z   = blockIdx.z;
    const int tid = threadIdx.x;
    const int wid = tid >> 5;
    const int lid = tid & 31;
    const int t0  = blockIdx.y * 128;
    const int jn0 = blockIdx.x * 128;

    const float* A;
    float* O;
    if (mode == 0) { A = z ? A1 : A0; O = g_qkv[z]; }
    else           { A = g_att[z];    O = Oext + (size_t)z * ((size_t)TOK * DIM); }

    const int m_base = (wid >> 2) * 64;
    const int n_base = (wid & 3) * 32;

    const int lrow = tid >> 3;
    const int lcg  = tid & 7;

    const float* arow[4];
    #pragma unroll
    for (int i = 0; i < 4; i++) {
        const int row = lrow + i * 32;
        if (mode == 0) {
            const int ltok = t0 + row;
            const int n = ltok >> 14, r = ltok & 16383;
            const int win = r >> 8, pix = r & 255;
            const int h = ((win >> 3) << 4) | (pix >> 4);
            const int w = ((win & 7) << 4) | (pix & 15);
            arow[i] = A + ((size_t)(((n << 7) + h) << 7) + w) * DIM + lcg * 4;
        } else {
            arow[i] = A + (size_t)(t0 + row) * DIM + lcg * 4;
        }
    }
    const float* brow[4];
    #pragma unroll
    for (int i = 0; i < 4; i++)
        brow[i] = Wm + (size_t)(jn0 + lrow + i * 32) * 256 + lcg * 4;

    const u32 su = smem_u32(smx);

    const int a_r  = lid & 15;
    const int a_kh = lid >> 4;
    const int b_r  = (lid & 7) | ((lid >> 4) << 3);
    const int b_kh = (lid >> 3) & 1;

    float acc[4][4][4];
    #pragma unroll
    for (int mt = 0; mt < 4; mt++)
        #pragma unroll
        for (int nt = 0; nt < 4; nt++)
            #pragma unroll
            for (int r = 0; r < 4; r++) acc[mt][nt][r] = 0.f;

    float4 ra[4], rb[4];
    #pragma unroll
    for (int i = 0; i < 4; i++) { ra[i] = *(const float4*)(arow[i]); rb[i] = *(const float4*)(brow[i]); }

    // store chunk 0 into stage 0
    {
        __nv_bfloat16* st = smx;
        #pragma unroll
        for (int i = 0; i < 4; i++) {
            const int off = (lrow + i * 32) * PAD + lcg * 4;
            u64 hi, lo;
            cvt4(ra[i], hi, lo);
            *(u64*)(st + off) = hi;  *(u64*)(st + TILE_E + off) = lo;
            cvt4(rb[i], hi, lo);
            *(u64*)(st + 2*TILE_E + off) = hi;  *(u64*)(st + 3*TILE_E + off) = lo;
        }
    }
    __syncthreads();

    for (int ch = 0; ch < 8; ch++) {
        const int cur = ch & 1;
        if (ch < 7) {
            const int k1 = (ch + 1) * 32;
            #pragma unroll
            for (int i = 0; i < 4; i++) {
                ra[i] = *(const float4*)(arow[i] + k1);
                rb[i] = *(const float4*)(brow[i] + k1);
            }
        }
        const u32 sb = su + cur * STAGE_B;
        #pragma unroll
        for (int s = 0; s < 2; s++) {
            const int koff = s * 16;
            u32 ah[4][4], al[4][4], bh[4][2], bl[4][2];
            #pragma unroll
            for (int mt = 0; mt < 4; mt++) {
                const u32 eoff = (u32)((m_base + mt*16 + a_r) * PAD + koff + a_kh*8) * 2;
                ldmx4(sb + eoff,              ah[mt][0], ah[mt][1], ah[mt][2], ah[mt][3]);
                ldmx4(sb + TILE_E*2 + eoff,   al[mt][0], al[mt][1], al[mt][2], al[mt][3]);
            }
            #pragma unroll
            for (int p = 0; p < 2; p++) {
                const u32 eoff = (u32)((n_base + p*16 + b_r) * PAD + koff + b_kh*8) * 2;
                ldmx4(sb + TILE_E*4 + eoff, bh[2*p][0], bh[2*p][1], bh[2*p+1][0], bh[2*p+1][1]);
                ldmx4(sb + TILE_E*6 + eoff, bl[2*p][0], bl[2*p][1], bl[2*p+1][0], bl[2*p+1][1]);
            }
            #pragma unroll
            for (int mt = 0; mt < 4; mt++)
                #pragma unroll
                for (int nt = 0; nt < 4; nt++) {
                    mma16816(acc[mt][nt], ah[mt], bh[nt]);
                    mma16816(acc[mt][nt], ah[mt], bl[nt]);
                    mma16816(acc[mt][nt], al[mt], bh[nt]);
                }
        }
        if (ch < 7) {
            __nv_bfloat16* st = smx + (cur ^ 1) * (4*TILE_E);
            #pragma unroll
            for (int i = 0; i < 4; i++) {
                const int off = (lrow + i * 32) * PAD + lcg * 4;
                u64 hi, lo;
                cvt4(ra[i], hi, lo);
                *(u64*)(st + off) = hi;  *(u64*)(st + TILE_E + off) = lo;
                cvt4(rb[i], hi, lo);
                *(u64*)(st + 2*TILE_E + off) = hi;  *(u64*)(st + 3*TILE_E + off) = lo;
            }
            __syncthreads();
        }
    }

    const int qr = lid >> 2;
    const int qc = (lid & 3) * 2;
    #pragma unroll
    for (int mt = 0; mt < 4; mt++) {
        const int row0 = t0 + m_base + mt*16 + qr;
        #pragma unroll
        for (int nt = 0; nt < 4; nt++) {
            const int col = jn0 + n_base + nt*8 + qc;
            const float b0 = bias[col], b1 = bias[col+1];
            float2 v0 = make_float2(acc[mt][nt][0] + b0, acc[mt][nt][1] + b1);
            float2 v1 = make_float2(acc[mt][nt][2] + b0, acc[mt][nt][3] + b1);
            *(float2*)(O + (size_t)row0 * ostride + col)       = v0;
            *(float2*)(O + (size_t)(row0+8) * ostride + col)   = v1;
        }
    }
}

// ------------------------------ pooling ------------------------------------
__global__ __launch_bounds__(768) void k_pool()
{
    const int b = blockIdx.y;
    const int nwin = blockIdx.x;
    const int tid = threadIdx.x;
    const float* base = g_qkv[b] + (size_t)nwin * W2 * QKVC + tid;

    float s[16];
    #pragma unroll
    for (int i = 0; i < 16; i++) s[i] = 0.f;
    #pragma unroll 4
    for (int py = 0; py < 16; py++) {
        const int sr = (py >> 2) << 2;
        #pragma unroll
        for (int px = 0; px < 16; px++)
            s[sr + (px >> 2)] += base[(size_t)(py*16 + px) * QKVC];
    }
    float tot = 0.f;
    #pragma unroll
    for (int i = 0; i < 16; i++) tot += s[i];

    if (tid < QK) {
        g_qwin[b][nwin*QK + tid] = tot * (1.f/256.f);
    } else {
        const int c = tid - QK;
        #pragma unroll
        for (int i = 0; i < 16; i++)
            g_pool[b][(size_t)(nwin*W2KV + i)*CKV + c] = s[i] * (1.f/16.f);
        if (c < QK)
            g_kwin[b][nwin*QK + c] = tot * (1.f/256.f);
    }
}

// ------------------------------ routing ------------------------------------
__global__ void k_route()
{
    const int ib = blockIdx.z;         // 0: q2/k1, 1: q1/k2
    const int qb = 1 ^ ib, kb = ib;
    const int i = blockIdx.x;
    const int n = blockIdx.y;
    const int j = threadIdx.x;
    const float* qp = g_qwin[qb] + (size_t)(n*P2 + i)*QK;
    const float* kp = g_kwin[kb] + (size_t)(n*P2 + j)*QK;
    float s = 0.f;
    for (int c = 0; c < QK; c++) s += qp[c]*kp[c];
    s *= SCALEF;
    if (j == i) s = 1.0f;
    __shared__ float lg[P2];
    lg[j] = s;
    __syncthreads();
    if (j == 0) {
        #pragma unroll
        for (int t = 0; t < TOPK; t++) {
            float best = -1e30f; int bi = 0;
            for (int u = 0; u < P2; u++)
                if (lg[u] > best) { best = lg[u]; bi = u; }
            g_idx[ib][(n*P2 + i)*TOPK + t] = bi;
            lg[bi] = -1e30f;
        }
    }
}

// ----------------------------- attention -----------------------------------
__global__ __launch_bounds__(256) void k_attend()
{
    const int z = blockIdx.z;          // 0: out1=attend(q2,kv1,idx1), 1: out2
    const int qb = 1 ^ z, kvb = z, ib = z, ob = z;
    const int nwin = blockIdx.x;
    const int head = blockIdx.y;
    const int n   = nwin >> 6;
    const int win = nwin & 63;
    const int tid = threadIdx.x;

    __shared__ float ks[64][32];
    __shared__ float vs[64][32];
    __shared__ int sel[TOPK];
    if (tid < TOPK) sel[tid] = g_idx[ib][nwin*TOPK + tid];
    __syncthreads();

    for (int e = tid; e < 64*32; e += 256) {
        const int tkn = e >> 5, c = e & 31;
        const int sw  = sel[tkn >> 4];
        const float* pp = g_pool[kvb] + (size_t)((n*P2 + sw)*W2KV + (tkn & 15))*CKV;
        ks[tkn][c] = pp[head*DH + c];
        vs[tkn][c] = pp[QK + head*DH + c];
    }
    __syncthreads();

    const int pix = tid;
    const float* qp = g_qkv[qb] + (size_t)(nwin*W2 + pix)*QKVC + head*DH;
    u64 qd[16];
    #pragma unroll
    for (int c = 0; c < 16; c++)
        qd[c] = pack2(qp[2*c] * SCALEF, qp[2*c+1] * SCALEF);

    float lg[64];
    float mx = -1e30f;
    #pragma unroll
    for (int t = 0; t < 64; t++) {
        const u64* kr = (const u64*)ks[t];
        u64 ac = 0ull;
        #pragma unroll
        for (int c = 0; c < 16; c++) fma2(ac, qd[c], kr[c]);
        const float2 pr = unp2(ac);
        const float s = pr.x + pr.y;
        lg[t] = s;
        mx = fmaxf(mx, s);
    }
    float den = 0.f;
    #pragma unroll
    for (int t = 0; t < 64; t++) { lg[t] = expf(lg[t] - mx); den += lg[t]; }
    const float inv = 1.f / den;

    u64 o[16];
    #pragma unroll
    for (int c = 0; c < 16; c++) o[c] = 0ull;
    #pragma unroll
    for (int t = 0; t < 64; t++) {
        const u64 pd = dup2(lg[t]);
        const u64* vr = (const u64*)vs[t];
        #pragma unroll
        for (int c = 0; c < 16; c++) fma2(o[c], pd, vr[c]);
    }

    const int h = ((win >> 3) << 4) | (pix >> 4);
    const int w = ((win & 7)  << 4) | (pix & 15);
    float* op = g_att[ob] + (size_t)(((n << 7) + h)*WW + w)*DIM + head*DH;
    const u64 invd = dup2(inv);
    #pragma unroll
    for (int c = 0; c < 16; c++)
        *(u64*)(op + 2*c) = mul2(o[c], invd);
}

// --------------------------- lepe (depthwise 3x3) --------------------------
__global__ __launch_bounds__(256) void k_lepe(
    const float* __restrict__ lw, const float* __restrict__ lb)
{
    const int vb = blockIdx.z, ob = blockIdx.z;
    __shared__ float swt[DIM*9];
    const int blk = blockIdx.x;
    const int c = threadIdx.x;
    for (int e = c; e < DIM*9; e += 256) swt[e] = lw[e];
    __syncthreads();

    const int n  = blk >> 12;
    const int r  = blk & 4095;
    const int h  = r >> 5;
    const int w0 = (r & 31) << 2;

    const float* wrow = &swt[c*9];
    float acc[4];
    {
        float* op = g_att[ob] + (size_t)((((n << 7) + h) << 7) + w0)*DIM + c;
        const float bb = lb[c];
        #pragma unroll
        for (int k = 0; k < 4; k++) acc[k] = op[k*DIM] + bb;
    }

    #pragma unroll
    for (int dy = 0; dy < 3; dy++) {
        const int hh = h + dy - 1;
        if ((unsigned)hh >= (unsigned)HH) continue;
        #pragma unroll
        for (int cc = 0; cc < 6; cc++) {
            const int ww = w0 - 1 + cc;
            if ((unsigned)ww >= (unsigned)WW) continue;
            const int vwin = ((hh >> 4) << 3) | (ww >> 4);
            const int vpix = ((hh & 15) << 4) | (ww & 15);
            const float v = g_qkv[vb]
                [(size_t)(((n << 6) | vwin)*W2 + vpix)*QKVC + CKV + c];
            #pragma unroll
            for (int k = 0; k < 4; k++) {
                const int dx = cc - k;
                if (dx >= 0 && dx <= 2)
                    acc[k] += v * wrow[dy*3 + dx];
            }
        }
    }

    float* op = g_att[ob] + (size_t)((((n << 7) + h) << 7) + w0)*DIM + c;
    #pragma unroll
    for (int k = 0; k < 4; k++) op[k*DIM] = acc[k];
}

// ------------------------------- launch ------------------------------------
extern "C" void kernel_launch(void* const* d_in, const int* in_sizes, int n_in,
                              void* d_out, int out_size)
{
    const float* x1   = (const float*)d_in[0];
    const float* x2   = (const float*)d_in[1];
    const float* Wqkv = (const float*)d_in[2];
    const float* bqkv = (const float*)d_in[3];
    const float* lw   = (const float*)d_in[4];
    const float* lb   = (const float*)d_in[5];
    const float* Wo   = (const float*)d_in[6];
    const float* bo   = (const float*)d_in[7];
    float* out = (float*)d_out;

    cudaFuncSetAttribute(k_mma_gemm,
        cudaFuncAttributeMaxDynamicSharedMemorySize, GEMM_SMEM);

    // QKV for both branches
    k_mma_gemm<<<dim3(QKVC/128, TOK/128, 2), 256, GEMM_SMEM>>>(
        x1, x2, 0, Wqkv, bqkv, nullptr, QKVC);

    k_pool<<<dim3(NB*P2, 2), 768>>>();

    k_route<<<dim3(P2, NB, 2), 64>>>();

    k_attend<<<dim3(NB*P2, HEADS, 2), 256>>>();

    k_lepe<<<dim3(NB*HH*WW/4, 1, 2), 256>>>(lw, lb);

    // output projections for both branches
    k_mma_gemm<<<dim3(DIM/128, TOK/128, 2), 256, GEMM_SMEM>>>(
        nullptr, nullptr, 1, Wo, bo, out, DIM);
}

// round 9
// speedup vs baseline: 1.2584x; 1.0980x over previous
#include <cuda_runtime.h>
#include <cuda_bf16.h>
#include <cstdint>

// ---------------------------------------------------------------------------
// SpatialEncoder: bi-level routing attention.
// GEMMs: mma.sync bf16 split-precision (3-product), double-buffered smem.
// attend: single-pass no-max softmax (logits ~0.1), low register pressure.
// ---------------------------------------------------------------------------

#define NB    4
#define HH    128
#define WW    128
#define DIM   256
#define QK    256
#define CKV   512
#define QKVC  768
#define NW    8
#define P2    64
#define W2    256
#define W2KV  16
#define TOPK  4
#define HEADS 8
#define DH    32
#define TOK   (NB*P2*W2)
#define SCALEF 0.0625f

typedef unsigned long long u64;
typedef unsigned int u32;

// ---- packed f32x2 helpers --------------------------------------------------
__device__ __forceinline__ u64 pack2(float x, float y){
    u64 r; asm("mov.b64 %0,{%1,%2};" : "=l"(r) : "f"(x), "f"(y)); return r;
}
__device__ __forceinline__ u64 dup2(float x){
    u64 r; asm("mov.b64 %0,{%1,%1};" : "=l"(r) : "f"(x)); return r;
}
__device__ __forceinline__ void fma2(u64 &a, u64 b, u64 c){
    asm("fma.rn.f32x2 %0,%1,%2,%0;" : "+l"(a) : "l"(b), "l"(c));
}
__device__ __forceinline__ u64 mul2(u64 a, u64 b){
    u64 r; asm("mul.rn.f32x2 %0,%1,%2;" : "=l"(r) : "l"(a), "l"(b)); return r;
}
__device__ __forceinline__ float2 unp2(u64 v){
    float lo, hi; asm("mov.b64 {%0,%1},%2;" : "=f"(lo), "=f"(hi) : "l"(v));
    return make_float2(lo, hi);
}

__device__ __forceinline__ u32 smem_u32(const void* p){
    u32 a; asm("{ .reg .u64 t; cvta.to.shared.u64 t, %1; cvt.u32.u64 %0, t; }"
               : "=r"(a) : "l"(p));
    return a;
}

// fp32 -> (bf16 hi, bf16 lo) for a float4, packed as two u64 (4 bf16 each)
__device__ __forceinline__ void cvt4(float4 v, u64& hi, u64& lo){
    float f0=v.x, f1=v.y, f2=v.z, f3=v.w;
    __nv_bfloat16 h0=__float2bfloat16_rn(f0), h1=__float2bfloat16_rn(f1);
    __nv_bfloat16 h2=__float2bfloat16_rn(f2), h3=__float2bfloat16_rn(f3);
    unsigned short a0=__bfloat16_as_ushort(h0), a1=__bfloat16_as_ushort(h1);
    unsigned short a2=__bfloat16_as_ushort(h2), a3=__bfloat16_as_ushort(h3);
    hi = (u64)a0 | ((u64)a1<<16) | ((u64)a2<<32) | ((u64)a3<<48);
    unsigned short b0=__bfloat16_as_ushort(__float2bfloat16_rn(f0-__bfloat162float(h0)));
    unsigned short b1=__bfloat16_as_ushort(__float2bfloat16_rn(f1-__bfloat162float(h1)));
    unsigned short b2=__bfloat16_as_ushort(__float2bfloat16_rn(f2-__bfloat162float(h2)));
    unsigned short b3=__bfloat16_as_ushort(__float2bfloat16_rn(f3-__bfloat162float(h3)));
    lo = (u64)b0 | ((u64)b1<<16) | ((u64)b2<<32) | ((u64)b3<<48);
}

__device__ __forceinline__ void ldmx4(u32 addr, u32& r0, u32& r1, u32& r2, u32& r3){
    asm volatile("ldmatrix.sync.aligned.m8n8.x4.shared.b16 {%0,%1,%2,%3},[%4];"
                 : "=r"(r0),"=r"(r1),"=r"(r2),"=r"(r3) : "r"(addr));
}
__device__ __forceinline__ void mma16816(float* c, const u32* a, const u32* b){
    asm volatile("mma.sync.aligned.m16n8k16.row.col.f32.bf16.bf16.f32 "
        "{%0,%1,%2,%3},{%4,%5,%6,%7},{%8,%9},{%0,%1,%2,%3};"
        : "+f"(c[0]),"+f"(c[1]),"+f"(c[2]),"+f"(c[3])
        : "r"(a[0]),"r"(a[1]),"r"(a[2]),"r"(a[3]),"r"(b[0]),"r"(b[1]));
}

// -------- scratch -----------------------------------------------------------
__device__ float g_qkv [2][(size_t)TOK*QKVC];
__device__ float g_pool[2][NB*P2*W2KV*CKV];
__device__ float g_qwin[2][NB*P2*QK];
__device__ float g_kwin[2][NB*P2*QK];
__device__ int   g_idx [2][NB*P2*TOPK];
__device__ float g_att [2][(size_t)NB*HH*WW*DIM];

// ------------------------- HMMA split-bf16 GEMM -----------------------------
#define PAD    40
#define TILE_E (128*PAD)
#define STAGE_B (4*TILE_E*2)
#define GEMM_SMEM (2*STAGE_B)

__global__ __launch_bounds__(256) void k_mma_gemm(
    const float* __restrict__ A0, const float* __restrict__ A1, int mode,
    const float* __restrict__ Wm, const float* __restrict__ bias,
    float* __restrict__ Oext, int ostride)
{
    extern __shared__ __nv_bfloat16 smx[];

    const int z   = blockIdx.z;
    const int tid = threadIdx.x;
    const int wid = tid >> 5;
    const int lid = tid & 31;
    const int t0  = blockIdx.y * 128;
    const int jn0 = blockIdx.x * 128;

    const float* A;
    float* O;
    if (mode == 0) { A = z ? A1 : A0; O = g_qkv[z]; }
    else           { A = g_att[z];    O = Oext + (size_t)z * ((size_t)TOK * DIM); }

    const int m_base = (wid >> 2) * 64;
    const int n_base = (wid & 3) * 32;

    const int lrow = tid >> 3;
    const int lcg  = tid & 7;

    const float* arow[4];
    #pragma unroll
    for (int i = 0; i < 4; i++) {
        const int row = lrow + i * 32;
        if (mode == 0) {
            const int ltok = t0 + row;
            const int n = ltok >> 14, r = ltok & 16383;
            const int win = r >> 8, pix = r & 255;
            const int h = ((win >> 3) << 4) | (pix >> 4);
            const int w = ((win & 7) << 4) | (pix & 15);
            arow[i] = A + ((size_t)(((n << 7) + h) << 7) + w) * DIM + lcg * 4;
        } else {
            arow[i] = A + (size_t)(t0 + row) * DIM + lcg * 4;
        }
    }
    const float* brow[4];
    #pragma unroll
    for (int i = 0; i < 4; i++)
        brow[i] = Wm + (size_t)(jn0 + lrow + i * 32) * 256 + lcg * 4;

    const u32 su = smem_u32(smx);

    const int a_r  = lid & 15;
    const int a_kh = lid >> 4;
    const int b_r  = (lid & 7) | ((lid >> 4) << 3);
    const int b_kh = (lid >> 3) & 1;

    float acc[4][4][4];
    #pragma unroll
    for (int mt = 0; mt < 4; mt++)
        #pragma unroll
        for (int nt = 0; nt < 4; nt++)
            #pragma unroll
            for (int r = 0; r < 4; r++) acc[mt][nt][r] = 0.f;

    float4 ra[4], rb[4];
    #pragma unroll
    for (int i = 0; i < 4; i++) { ra[i] = *(const float4*)(arow[i]); rb[i] = *(const float4*)(brow[i]); }

    {
        __nv_bfloat16* st = smx;
        #pragma unroll
        for (int i = 0; i < 4; i++) {
            const int off = (lrow + i * 32) * PAD + lcg * 4;
            u64 hi, lo;
            cvt4(ra[i], hi, lo);
            *(u64*)(st + off) = hi;  *(u64*)(st + TILE_E + off) = lo;
            cvt4(rb[i], hi, lo);
            *(u64*)(st + 2*TILE_E + off) = hi;  *(u64*)(st + 3*TILE_E + off) = lo;
        }
    }
    __syncthreads();

    for (int ch = 0; ch < 8; ch++) {
        const int cur = ch & 1;
        if (ch < 7) {
            const int k1 = (ch + 1) * 32;
            #pragma unroll
            for (int i = 0; i < 4; i++) {
                ra[i] = *(const float4*)(arow[i] + k1);
                rb[i] = *(const float4*)(brow[i] + k1);
            }
        }
        const u32 sb = su + cur * STAGE_B;
        #pragma unroll
        for (int s = 0; s < 2; s++) {
            const int koff = s * 16;
            u32 ah[4][4], al[4][4], bh[4][2], bl[4][2];
            #pragma unroll
            for (int mt = 0; mt < 4; mt++) {
                const u32 eoff = (u32)((m_base + mt*16 + a_r) * PAD + koff + a_kh*8) * 2;
                ldmx4(sb + eoff,              ah[mt][0], ah[mt][1], ah[mt][2], ah[mt][3]);
                ldmx4(sb + TILE_E*2 + eoff,   al[mt][0], al[mt][1], al[mt][2], al[mt][3]);
            }
            #pragma unroll
            for (int p = 0; p < 2; p++) {
                const u32 eoff = (u32)((n_base + p*16 + b_r) * PAD + koff + b_kh*8) * 2;
                ldmx4(sb + TILE_E*4 + eoff, bh[2*p][0], bh[2*p][1], bh[2*p+1][0], bh[2*p+1][1]);
                ldmx4(sb + TILE_E*6 + eoff, bl[2*p][0], bl[2*p][1], bl[2*p+1][0], bl[2*p+1][1]);
            }
            #pragma unroll
            for (int mt = 0; mt < 4; mt++)
                #pragma unroll
                for (int nt = 0; nt < 4; nt++) {
                    mma16816(acc[mt][nt], ah[mt], bh[nt]);
                    mma16816(acc[mt][nt], ah[mt], bl[nt]);
                    mma16816(acc[mt][nt], al[mt], bh[nt]);
                }
        }
        if (ch < 7) {
            __nv_bfloat16* st = smx + (cur ^ 1) * (4*TILE_E);
            #pragma unroll
            for (int i = 0; i < 4; i++) {
                const int off = (lrow + i * 32) * PAD + lcg * 4;
                u64 hi, lo;
                cvt4(ra[i], hi, lo);
                *(u64*)(st + off) = hi;  *(u64*)(st + TILE_E + off) = lo;
                cvt4(rb[i], hi, lo);
                *(u64*)(st + 2*TILE_E + off) = hi;  *(u64*)(st + 3*TILE_E + off) = lo;
            }
            __syncthreads();
        }
    }

    const int qr = lid >> 2;
    const int qc = (lid & 3) * 2;
    #pragma unroll
    for (int mt = 0; mt < 4; mt++) {
        const int row0 = t0 + m_base + mt*16 + qr;
        #pragma unroll
        for (int nt = 0; nt < 4; nt++) {
            const int col = jn0 + n_base + nt*8 + qc;
            const float b0 = bias[col], b1 = bias[col+1];
            float2 v0 = make_float2(acc[mt][nt][0] + b0, acc[mt][nt][1] + b1);
            float2 v1 = make_float2(acc[mt][nt][2] + b0, acc[mt][nt][3] + b1);
            *(float2*)(O + (size_t)row0 * ostride + col)       = v0;
            *(float2*)(O + (size_t)(row0+8) * ostride + col)   = v1;
        }
    }
}

// ------------------------------ pooling ------------------------------------
__global__ __launch_bounds__(768) void k_pool()
{
    const int b = blockIdx.y;
    const int nwin = blockIdx.x;
    const int tid = threadIdx.x;
    const float* base = g_qkv[b] + (size_t)nwin * W2 * QKVC + tid;

    float s[16];
    #pragma unroll
    for (int i = 0; i < 16; i++) s[i] = 0.f;
    #pragma unroll 4
    for (int py = 0; py < 16; py++) {
        const int sr = (py >> 2) << 2;
        #pragma unroll
        for (int px = 0; px < 16; px++)
            s[sr + (px >> 2)] += base[(size_t)(py*16 + px) * QKVC];
    }
    float tot = 0.f;
    #pragma unroll
    for (int i = 0; i < 16; i++) tot += s[i];

    if (tid < QK) {
        g_qwin[b][nwin*QK + tid] = tot * (1.f/256.f);
    } else {
        const int c = tid - QK;
        #pragma unroll
        for (int i = 0; i < 16; i++)
            g_pool[b][(size_t)(nwin*W2KV + i)*CKV + c] = s[i] * (1.f/16.f);
        if (c < QK)
            g_kwin[b][nwin*QK + c] = tot * (1.f/256.f);
    }
}

// ------------------------------ routing ------------------------------------
__global__ void k_route()
{
    const int ib = blockIdx.z;
    const int qb = 1 ^ ib, kb = ib;
    const int i = blockIdx.x;
    const int n = blockIdx.y;
    const int j = threadIdx.x;
    const float* qp = g_qwin[qb] + (size_t)(n*P2 + i)*QK;
    const float* kp = g_kwin[kb] + (size_t)(n*P2 + j)*QK;
    float s = 0.f;
    for (int c = 0; c < QK; c++) s += qp[c]*kp[c];
    s *= SCALEF;
    if (j == i) s = 1.0f;
    __shared__ float lg[P2];
    lg[j] = s;
    __syncthreads();
    if (j == 0) {
        #pragma unroll
        for (int t = 0; t < TOPK; t++) {
            float best = -1e30f; int bi = 0;
            for (int u = 0; u < P2; u++)
                if (lg[u] > best) { best = lg[u]; bi = u; }
            g_idx[ib][(n*P2 + i)*TOPK + t] = bi;
            lg[bi] = -1e30f;
        }
    }
}

// ----------------------------- attention -----------------------------------
// single-pass softmax without max subtraction (logits ~|0.1| << 88).
__global__ __launch_bounds__(256) void k_attend()
{
    const int z = blockIdx.z;
    const int qb = 1 ^ z, kvb = z, ib = z, ob = z;
    const int nwin = blockIdx.x;
    const int head = blockIdx.y;
    const int n   = nwin >> 6;
    const int win = nwin & 63;
    const int tid = threadIdx.x;

    __shared__ float ks[64][32];
    __shared__ float vs[64][32];
    __shared__ int sel[TOPK];
    if (tid < TOPK) sel[tid] = g_idx[ib][nwin*TOPK + tid];
    __syncthreads();

    for (int e = tid; e < 64*32; e += 256) {
        const int tkn = e >> 5, c = e & 31;
        const int sw  = sel[tkn >> 4];
        const float* pp = g_pool[kvb] + (size_t)((n*P2 + sw)*W2KV + (tkn & 15))*CKV;
        ks[tkn][c] = pp[head*DH + c];
        vs[tkn][c] = pp[QK + head*DH + c];
    }
    __syncthreads();

    const int pix = tid;
    const float* qp = g_qkv[qb] + (size_t)(nwin*W2 + pix)*QKVC + head*DH;
    u64 qd[16];
    #pragma unroll
    for (int c = 0; c < 16; c++)
        qd[c] = pack2(qp[2*c] * SCALEF, qp[2*c+1] * SCALEF);

    u64 o[16];
    #pragma unroll
    for (int c = 0; c < 16; c++) o[c] = 0ull;
    float den = 0.f;

    #pragma unroll 4
    for (int t = 0; t < 64; t++) {
        const u64* kr = (const u64*)ks[t];
        u64 a0 = 0ull, a1 = 0ull, a2 = 0ull, a3 = 0ull;
        #pragma unroll
        for (int c = 0; c < 4; c++) {
            fma2(a0, qd[c],    kr[c]);
            fma2(a1, qd[c+4],  kr[c+4]);
            fma2(a2, qd[c+8],  kr[c+8]);
            fma2(a3, qd[c+12], kr[c+12]);
        }
        const float2 p0 = unp2(a0), p1 = unp2(a1), p2 = unp2(a2), p3 = unp2(a3);
        const float s = ((p0.x + p0.y) + (p1.x + p1.y))
                      + ((p2.x + p2.y) + (p3.x + p3.y));
        const float p = __expf(s);
        den += p;
        const u64 pd = dup2(p);
        const u64* vr = (const u64*)vs[t];
        #pragma unroll
        for (int c = 0; c < 16; c++) fma2(o[c], pd, vr[c]);
    }
    const float inv = 1.f / den;

    const int h = ((win >> 3) << 4) | (pix >> 4);
    const int w = ((win & 7)  << 4) | (pix & 15);
    float* op = g_att[ob] + (size_t)(((n << 7) + h)*WW + w)*DIM + head*DH;
    const u64 invd = dup2(inv);
    #pragma unroll
    for (int c = 0; c < 16; c++)
        *(u64*)(op + 2*c) = mul2(o[c], invd);
}

// --------------------------- lepe (depthwise 3x3) --------------------------
__global__ __launch_bounds__(256) void k_lepe(
    const float* __restrict__ lw, const float* __restrict__ lb)
{
    const int vb = blockIdx.z, ob = blockIdx.z;
    __shared__ float swt[DIM*9];
    const int blk = blockIdx.x;
    const int c = threadIdx.x;
    for (int e = c; e < DIM*9; e += 256) swt[e] = lw[e];
    __syncthreads();

    const int n  = blk >> 12;
    const int r  = blk & 4095;
    const int h  = r >> 5;
    const int w0 = (r & 31) << 2;

    const float* wrow = &swt[c*9];
    float acc[4];
    {
        float* op = g_att[ob] + (size_t)((((n << 7) + h) << 7) + w0)*DIM + c;
        const float bb = lb[c];
        #pragma unroll
        for (int k = 0; k < 4; k++) acc[k] = op[k*DIM] + bb;
    }

    #pragma unroll
    for (int dy = 0; dy < 3; dy++) {
        const int hh = h + dy - 1;
        if ((unsigned)hh >= (unsigned)HH) continue;
        #pragma unroll
        for (int cc = 0; cc < 6; cc++) {
            const int ww = w0 - 1 + cc;
            if ((unsigned)ww >= (unsigned)WW) continue;
            const int vwin = ((hh >> 4) << 3) | (ww >> 4);
            const int vpix = ((hh & 15) << 4) | (ww & 15);
            const float v = g_qkv[vb]
                [(size_t)(((n << 6) | vwin)*W2 + vpix)*QKVC + CKV + c];
            #pragma unroll
            for (int k = 0; k < 4; k++) {
                const int dx = cc - k;
                if (dx >= 0 && dx <= 2)
                    acc[k] += v * wrow[dy*3 + dx];
            }
        }
    }

    float* op = g_att[ob] + (size_t)((((n << 7) + h) << 7) + w0)*DIM + c;
    #pragma unroll
    for (int k = 0; k < 4; k++) op[k*DIM] = acc[k];
}

// ------------------------------- launch ------------------------------------
extern "C" void kernel_launch(void* const* d_in, const int* in_sizes, int n_in,
                              void* d_out, int out_size)
{
    const float* x1   = (const float*)d_in[0];
    const float* x2   = (const float*)d_in[1];
    const float* Wqkv = (const float*)d_in[2];
    const float* bqkv = (const float*)d_in[3];
    const float* lw   = (const float*)d_in[4];
    const float* lb   = (const float*)d_in[5];
    const float* Wo   = (const float*)d_in[6];
    const float* bo   = (const float*)d_in[7];
    float* out = (float*)d_out;

    cudaFuncSetAttribute(k_mma_gemm,
        cudaFuncAttributeMaxDynamicSharedMemorySize, GEMM_SMEM);

    k_mma_gemm<<<dim3(QKVC/128, TOK/128, 2), 256, GEMM_SMEM>>>(
        x1, x2, 0, Wqkv, bqkv, nullptr, QKVC);

    k_pool<<<dim3(NB*P2, 2), 768>>>();

    k_route<<<dim3(P2, NB, 2), 64>>>();

    k_attend<<<dim3(NB*P2, HEADS, 2), 256>>>();

    k_lepe<<<dim3(NB*HH*WW/4, 1, 2), 256>>>(lw, lb);

    k_mma_gemm<<<dim3(DIM/128, TOK/128, 2), 256, GEMM_SMEM>>>(
        nullptr, nullptr, 1, Wo, bo, out, DIM);
}

// round 11
// speedup vs baseline: 1.5176x; 1.2060x over previous
#include <cuda_runtime.h>
#include <cuda_bf16.h>
#include <cstdint>

// ---------------------------------------------------------------------------
// SpatialEncoder: bi-level routing attention.
// GEMMs: mma.sync bf16 split-precision (3-product), double-buffered smem.
// attend: HMMA flash-style (S=QK^T and O=PV on tensor pipe, fragment reuse).
// ---------------------------------------------------------------------------

#define NB    4
#define HH    128
#define WW    128
#define DIM   256
#define QK    256
#define CKV   512
#define QKVC  768
#define NW    8
#define P2    64
#define W2    256
#define W2KV  16
#define TOPK  4
#define HEADS 8
#define DH    32
#define TOK   (NB*P2*W2)
#define SCALEF 0.0625f

typedef unsigned long long u64;
typedef unsigned int u32;

// ---- packed f32x2 helpers --------------------------------------------------
__device__ __forceinline__ u64 pack2(float x, float y){
    u64 r; asm("mov.b64 %0,{%1,%2};" : "=l"(r) : "f"(x), "f"(y)); return r;
}
__device__ __forceinline__ u64 dup2(float x){
    u64 r; asm("mov.b64 %0,{%1,%1};" : "=l"(r) : "f"(x)); return r;
}
__device__ __forceinline__ void fma2(u64 &a, u64 b, u64 c){
    asm("fma.rn.f32x2 %0,%1,%2,%0;" : "+l"(a) : "l"(b), "l"(c));
}
__device__ __forceinline__ u64 mul2(u64 a, u64 b){
    u64 r; asm("mul.rn.f32x2 %0,%1,%2;" : "=l"(r) : "l"(a), "l"(b)); return r;
}
__device__ __forceinline__ float2 unp2(u64 v){
    float lo, hi; asm("mov.b64 {%0,%1},%2;" : "=f"(lo), "=f"(hi) : "l"(v));
    return make_float2(lo, hi);
}

__device__ __forceinline__ u32 smem_u32(const void* p){
    u32 a; asm("{ .reg .u64 t; cvta.to.shared.u64 t, %1; cvt.u32.u64 %0, t; }"
               : "=r"(a) : "l"(p));
    return a;
}

// fp32 -> (bf16 hi, bf16 lo) for a float4, packed as two u64 (4 bf16 each)
__device__ __forceinline__ void cvt4(float4 v, u64& hi, u64& lo){
    float f0=v.x, f1=v.y, f2=v.z, f3=v.w;
    __nv_bfloat16 h0=__float2bfloat16_rn(f0), h1=__float2bfloat16_rn(f1);
    __nv_bfloat16 h2=__float2bfloat16_rn(f2), h3=__float2bfloat16_rn(f3);
    unsigned short a0=__bfloat16_as_ushort(h0), a1=__bfloat16_as_ushort(h1);
    unsigned short a2=__bfloat16_as_ushort(h2), a3=__bfloat16_as_ushort(h3);
    hi = (u64)a0 | ((u64)a1<<16) | ((u64)a2<<32) | ((u64)a3<<48);
    unsigned short b0=__bfloat16_as_ushort(__float2bfloat16_rn(f0-__bfloat162float(h0)));
    unsigned short b1=__bfloat16_as_ushort(__float2bfloat16_rn(f1-__bfloat162float(h1)));
    unsigned short b2=__bfloat16_as_ushort(__float2bfloat16_rn(f2-__bfloat162float(h2)));
    unsigned short b3=__bfloat16_as_ushort(__float2bfloat16_rn(f3-__bfloat162float(h3)));
    lo = (u64)b0 | ((u64)b1<<16) | ((u64)b2<<32) | ((u64)b3<<48);
}

// pack two f32 into bf16x2: low half = lo, high half = hi
__device__ __forceinline__ u32 pkbf(float lo, float hi){
    u32 d; asm("cvt.rn.bf16x2.f32 %0,%1,%2;" : "=r"(d) : "f"(hi), "f"(lo));
    return d;
}

__device__ __forceinline__ void ldmx4(u32 addr, u32& r0, u32& r1, u32& r2, u32& r3){
    asm volatile("ldmatrix.sync.aligned.m8n8.x4.shared.b16 {%0,%1,%2,%3},[%4];"
                 : "=r"(r0),"=r"(r1),"=r"(r2),"=r"(r3) : "r"(addr));
}
__device__ __forceinline__ void mma16816(float* c, const u32* a, const u32* b){
    asm volatile("mma.sync.aligned.m16n8k16.row.col.f32.bf16.bf16.f32 "
        "{%0,%1,%2,%3},{%4,%5,%6,%7},{%8,%9},{%0,%1,%2,%3};"
        : "+f"(c[0]),"+f"(c[1]),"+f"(c[2]),"+f"(c[3])
        : "r"(a[0]),"r"(a[1]),"r"(a[2]),"r"(a[3]),"r"(b[0]),"r"(b[1]));
}

// -------- scratch -----------------------------------------------------------
__device__ float g_qkv [2][(size_t)TOK*QKVC];
__device__ float g_pool[2][NB*P2*W2KV*CKV];
__device__ float g_qwin[2][NB*P2*QK];
__device__ float g_kwin[2][NB*P2*QK];
__device__ int   g_idx [2][NB*P2*TOPK];
__device__ float g_att [2][(size_t)NB*HH*WW*DIM];

// ------------------------- HMMA split-bf16 GEMM -----------------------------
#define PAD    40
#define TILE_E (128*PAD)
#define STAGE_B (4*TILE_E*2)
#define GEMM_SMEM (2*STAGE_B)

__global__ __launch_bounds__(256) void k_mma_gemm(
    const float* __restrict__ A0, const float* __restrict__ A1, int mode,
    const float* __restrict__ Wm, const float* __restrict__ bias,
    float* __restrict__ Oext, int ostride)
{
    extern __shared__ __nv_bfloat16 smx[];

    const int z   = blockIdx.z;
    const int tid = threadIdx.x;
    const int wid = tid >> 5;
    const int lid = tid & 31;
    const int t0  = blockIdx.y * 128;
    const int jn0 = blockIdx.x * 128;

    const float* A;
    float* O;
    if (mode == 0) { A = z ? A1 : A0; O = g_qkv[z]; }
    else           { A = g_att[z];    O = Oext + (size_t)z * ((size_t)TOK * DIM); }

    const int m_base = (wid >> 2) * 64;
    const int n_base = (wid & 3) * 32;

    const int lrow = tid >> 3;
    const int lcg  = tid & 7;

    const float* arow[4];
    #pragma unroll
    for (int i = 0; i < 4; i++) {
        const int row = lrow + i * 32;
        if (mode == 0) {
            const int ltok = t0 + row;
            const int n = ltok >> 14, r = ltok & 16383;
            const int win = r >> 8, pix = r & 255;
            const int h = ((win >> 3) << 4) | (pix >> 4);
            const int w = ((win & 7) << 4) | (pix & 15);
            arow[i] = A + ((size_t)(((n << 7) + h) << 7) + w) * DIM + lcg * 4;
        } else {
            arow[i] = A + (size_t)(t0 + row) * DIM + lcg * 4;
        }
    }
    const float* brow[4];
    #pragma unroll
    for (int i = 0; i < 4; i++)
        brow[i] = Wm + (size_t)(jn0 + lrow + i * 32) * 256 + lcg * 4;

    const u32 su = smem_u32(smx);

    const int a_r  = lid & 15;
    const int a_kh = lid >> 4;
    const int b_r  = (lid & 7) | ((lid >> 4) << 3);
    const int b_kh = (lid >> 3) & 1;

    float acc[4][4][4];
    #pragma unroll
    for (int mt = 0; mt < 4; mt++)
        #pragma unroll
        for (int nt = 0; nt < 4; nt++)
            #pragma unroll
            for (int r = 0; r < 4; r++) acc[mt][nt][r] = 0.f;

    float4 ra[4], rb[4];
    #pragma unroll
    for (int i = 0; i < 4; i++) { ra[i] = *(const float4*)(arow[i]); rb[i] = *(const float4*)(brow[i]); }

    {
        __nv_bfloat16* st = smx;
        #pragma unroll
        for (int i = 0; i < 4; i++) {
            const int off = (lrow + i * 32) * PAD + lcg * 4;
            u64 hi, lo;
            cvt4(ra[i], hi, lo);
            *(u64*)(st + off) = hi;  *(u64*)(st + TILE_E + off) = lo;
            cvt4(rb[i], hi, lo);
            *(u64*)(st + 2*TILE_E + off) = hi;  *(u64*)(st + 3*TILE_E + off) = lo;
        }
    }
    __syncthreads();

    for (int ch = 0; ch < 8; ch++) {
        const int cur = ch & 1;
        if (ch < 7) {
            const int k1 = (ch + 1) * 32;
            #pragma unroll
            for (int i = 0; i < 4; i++) {
                ra[i] = *(const float4*)(arow[i] + k1);
                rb[i] = *(const float4*)(brow[i] + k1);
            }
        }
        const u32 sb = su + cur * STAGE_B;
        #pragma unroll
        for (int s = 0; s < 2; s++) {
            const int koff = s * 16;
            u32 ah[4][4], al[4][4], bh[4][2], bl[4][2];
            #pragma unroll
            for (int mt = 0; mt < 4; mt++) {
                const u32 eoff = (u32)((m_base + mt*16 + a_r) * PAD + koff + a_kh*8) * 2;
                ldmx4(sb + eoff,              ah[mt][0], ah[mt][1], ah[mt][2], ah[mt][3]);
                ldmx4(sb + TILE_E*2 + eoff,   al[mt][0], al[mt][1], al[mt][2], al[mt][3]);
            }
            #pragma unroll
            for (int p = 0; p < 2; p++) {
                const u32 eoff = (u32)((n_base + p*16 + b_r) * PAD + koff + b_kh*8) * 2;
                ldmx4(sb + TILE_E*4 + eoff, bh[2*p][0], bh[2*p][1], bh[2*p+1][0], bh[2*p+1][1]);
                ldmx4(sb + TILE_E*6 + eoff, bl[2*p][0], bl[2*p][1], bl[2*p+1][0], bl[2*p+1][1]);
            }
            #pragma unroll
            for (int mt = 0; mt < 4; mt++)
                #pragma unroll
                for (int nt = 0; nt < 4; nt++) {
                    mma16816(acc[mt][nt], ah[mt], bh[nt]);
                    mma16816(acc[mt][nt], ah[mt], bl[nt]);
                    mma16816(acc[mt][nt], al[mt], bh[nt]);
                }
        }
        if (ch < 7) {
            __nv_bfloat16* st = smx + (cur ^ 1) * (4*TILE_E);
            #pragma unroll
            for (int i = 0; i < 4; i++) {
                const int off = (lrow + i * 32) * PAD + lcg * 4;
                u64 hi, lo;
                cvt4(ra[i], hi, lo);
                *(u64*)(st + off) = hi;  *(u64*)(st + TILE_E + off) = lo;
                cvt4(rb[i], hi, lo);
                *(u64*)(st + 2*TILE_E + off) = hi;  *(u64*)(st + 3*TILE_E + off) = lo;
            }
            __syncthreads();
        }
    }

    const int qr = lid >> 2;
    const int qc = (lid & 3) * 2;
    #pragma unroll
    for (int mt = 0; mt < 4; mt++) {
        const int row0 = t0 + m_base + mt*16 + qr;
        #pragma unroll
        for (int nt = 0; nt < 4; nt++) {
            const int col = jn0 + n_base + nt*8 + qc;
            const float b0 = bias[col], b1 = bias[col+1];
            float2 v0 = make_float2(acc[mt][nt][0] + b0, acc[mt][nt][1] + b1);
            float2 v1 = make_float2(acc[mt][nt][2] + b0, acc[mt][nt][3] + b1);
            *(float2*)(O + (size_t)row0 * ostride + col)       = v0;
            *(float2*)(O + (size_t)(row0+8) * ostride + col)   = v1;
        }
    }
}

// ------------------------------ pooling ------------------------------------
__global__ __launch_bounds__(768) void k_pool()
{
    const int b = blockIdx.y;
    const int nwin = blockIdx.x;
    const int tid = threadIdx.x;
    const float* base = g_qkv[b] + (size_t)nwin * W2 * QKVC + tid;

    float s[16];
    #pragma unroll
    for (int i = 0; i < 16; i++) s[i] = 0.f;
    #pragma unroll 4
    for (int py = 0; py < 16; py++) {
        const int sr = (py >> 2) << 2;
        #pragma unroll
        for (int px = 0; px < 16; px++)
            s[sr + (px >> 2)] += base[(size_t)(py*16 + px) * QKVC];
    }
    float tot = 0.f;
    #pragma unroll
    for (int i = 0; i < 16; i++) tot += s[i];

    if (tid < QK) {
        g_qwin[b][nwin*QK + tid] = tot * (1.f/256.f);
    } else {
        const int c = tid - QK;
        #pragma unroll
        for (int i = 0; i < 16; i++)
            g_pool[b][(size_t)(nwin*W2KV + i)*CKV + c] = s[i] * (1.f/16.f);
        if (c < QK)
            g_kwin[b][nwin*QK + c] = tot * (1.f/256.f);
    }
}

// ------------------------------ routing ------------------------------------
__global__ void k_route()
{
    const int ib = blockIdx.z;
    const int qb = 1 ^ ib, kb = ib;
    const int i = blockIdx.x;
    const int n = blockIdx.y;
    const int j = threadIdx.x;
    const float* qp = g_qwin[qb] + (size_t)(n*P2 + i)*QK;
    const float* kp = g_kwin[kb] + (size_t)(n*P2 + j)*QK;
    float s = 0.f;
    for (int c = 0; c < QK; c++) s += qp[c]*kp[c];
    s *= SCALEF;
    if (j == i) s = 1.0f;
    __shared__ float lg[P2];
    lg[j] = s;
    __syncthreads();
    if (j == 0) {
        #pragma unroll
        for (int t = 0; t < TOPK; t++) {
            float best = -1e30f; int bi = 0;
            for (int u = 0; u < P2; u++)
                if (lg[u] > best) { best = lg[u]; bi = u; }
            g_idx[ib][(n*P2 + i)*TOPK + t] = bi;
            lg[bi] = -1e30f;
        }
    }
}

// ----------------------------- attention (HMMA) -----------------------------
// per block (window, head, z): Q[256,32] x K[64,32]^T, softmax (no-max), x V.
// smem element offsets (bf16). All ldmatrix row strides must be 16B multiples:
// APQ/APK = 40 elems (80B), APV = 72 elems (144B).
#define APQ 40
#define APK 40
#define APV 72
#define OQ_H 0
#define OQ_L (OQ_H + 256*APQ)
#define OK_HH (OQ_L + 256*APQ)
#define OK_LL (OK_HH + 64*APK)
#define OV_HH (OK_LL + 64*APK)
#define OV_LL (OV_HH + 32*APV)
#define ATT_SMEM ((OV_LL + 32*APV)*2)

__global__ __launch_bounds__(256, 2) void k_attend()
{
    extern __shared__ __nv_bfloat16 sma[];
    __shared__ int sel[TOPK];

    const int z = blockIdx.z;
    const int qb = 1 ^ z, kvb = z, ib = z;
    const int nwin = blockIdx.x;
    const int head = blockIdx.y;
    const int n   = nwin >> 6;
    const int win = nwin & 63;
    const int tid = threadIdx.x;
    const int wid = tid >> 5;
    const int lid = tid & 31;

    if (tid < TOPK) sel[tid] = g_idx[ib][nwin*TOPK + tid];
    __syncthreads();

    // ---- stage K (token-major) and V^T (dh-major), bf16 hi/lo ----
    for (int e = tid; e < 64*32; e += 256) {
        const int tkn = e >> 5, c = e & 31;
        const int sw  = sel[tkn >> 4];
        const float* pp = g_pool[kvb] + (size_t)((n*P2 + sw)*W2KV + (tkn & 15))*CKV;
        const float kv = pp[head*DH + c];
        const float vv = pp[QK + head*DH + c];
        const __nv_bfloat16 kh = __float2bfloat16_rn(kv);
        sma[OK_HH + tkn*APK + c] = kh;
        sma[OK_LL + tkn*APK + c] = __float2bfloat16_rn(kv - __bfloat162float(kh));
        const __nv_bfloat16 vh = __float2bfloat16_rn(vv);
        sma[OV_HH + c*APV + tkn] = vh;
        sma[OV_LL + c*APV + tkn] = __float2bfloat16_rn(vv - __bfloat162float(vh));
    }
    // ---- stage Q (scaled), bf16 hi/lo ----
    {
        const float* qp = g_qkv[qb] + (size_t)(nwin*W2 + tid)*QKVC + head*DH;
        #pragma unroll
        for (int cg = 0; cg < 8; cg++) {
            float4 v = *(const float4*)(qp + cg*4);
            v.x *= SCALEF; v.y *= SCALEF; v.z *= SCALEF; v.w *= SCALEF;
            u64 hi, lo; cvt4(v, hi, lo);
            *(u64*)(&sma[OQ_H + tid*APQ + cg*4]) = hi;
            *(u64*)(&sma[OQ_L + tid*APQ + cg*4]) = lo;
        }
    }
    __syncthreads();

    const u32 su = smem_u32(sma);
    const int a_r  = lid & 15;
    const int a_kh = lid >> 4;
    const int b_r  = (lid & 7) | ((lid >> 4) << 3);
    const int b_kh = (lid >> 3) & 1;
    const int m_base = wid * 32;

    float oacc[2][4][4];
    #pragma unroll
    for (int mt = 0; mt < 2; mt++)
        #pragma unroll
        for (int nt = 0; nt < 4; nt++)
            #pragma unroll
            for (int r = 0; r < 4; r++) oacc[mt][nt][r] = 0.f;
    float den0[2] = {0.f, 0.f}, den1[2] = {0.f, 0.f};

    for (int chn = 0; chn < 4; chn++) {
        // ---- S = Q K^T over this 16-token chunk ----
        float sacc[2][2][4];
        #pragma unroll
        for (int mt = 0; mt < 2; mt++)
            #pragma unroll
            for (int p = 0; p < 2; p++)
                #pragma unroll
                for (int r = 0; r < 4; r++) sacc[mt][p][r] = 0.f;

        #pragma unroll
        for (int ks = 0; ks < 2; ks++) {
            u32 qh[2][4], ql[2][4];
            #pragma unroll
            for (int mt = 0; mt < 2; mt++) {
                const u32 qoff = (u32)((m_base + mt*16 + a_r)*APQ + ks*16 + a_kh*8) * 2;
                ldmx4(su + OQ_H*2 + qoff, qh[mt][0], qh[mt][1], qh[mt][2], qh[mt][3]);
                ldmx4(su + OQ_L*2 + qoff, ql[mt][0], ql[mt][1], ql[mt][2], ql[mt][3]);
            }
            u32 kh[2][2], kl[2][2];
            const u32 koff = (u32)((chn*16 + b_r)*APK + ks*16 + b_kh*8) * 2;
            ldmx4(su + OK_HH*2 + koff, kh[0][0], kh[0][1], kh[1][0], kh[1][1]);
            ldmx4(su + OK_LL*2 + koff, kl[0][0], kl[0][1], kl[1][0], kl[1][1]);
            #pragma unroll
            for (int mt = 0; mt < 2; mt++)
                #pragma unroll
                for (int p = 0; p < 2; p++) {
                    mma16816(sacc[mt][p], qh[mt], kh[p]);
                    mma16816(sacc[mt][p], qh[mt], kl[p]);
                    mma16816(sacc[mt][p], ql[mt], kh[p]);
                }
        }

        // ---- exp, den, P fragments (C m16n8 -> A m16n8k16 correspondence) ----
        u32 pa_h[2][4], pa_l[2][4];
        #pragma unroll
        for (int mt = 0; mt < 2; mt++) {
            float e[2][4];
            #pragma unroll
            for (int p = 0; p < 2; p++)
                #pragma unroll
                for (int r = 0; r < 4; r++)
                    e[p][r] = __expf(sacc[mt][p][r]);
            den0[mt] += (e[0][0] + e[0][1]) + (e[1][0] + e[1][1]);
            den1[mt] += (e[0][2] + e[0][3]) + (e[1][2] + e[1][3]);
            float hf[2][4], lf[2][4];
            #pragma unroll
            for (int p = 0; p < 2; p++)
                #pragma unroll
                for (int r = 0; r < 4; r++) {
                    hf[p][r] = __bfloat162float(__float2bfloat16_rn(e[p][r]));
                    lf[p][r] = e[p][r] - hf[p][r];
                }
            pa_h[mt][0] = pkbf(hf[0][0], hf[0][1]);
            pa_h[mt][1] = pkbf(hf[0][2], hf[0][3]);
            pa_h[mt][2] = pkbf(hf[1][0], hf[1][1]);
            pa_h[mt][3] = pkbf(hf[1][2], hf[1][3]);
            pa_l[mt][0] = pkbf(lf[0][0], lf[0][1]);
            pa_l[mt][1] = pkbf(lf[0][2], lf[0][3]);
            pa_l[mt][2] = pkbf(lf[1][0], lf[1][1]);
            pa_l[mt][3] = pkbf(lf[1][2], lf[1][3]);
        }

        // ---- O += P V ----
        u32 vh[4][2], vl[4][2];
        #pragma unroll
        for (int p = 0; p < 2; p++) {
            const u32 voff = (u32)((p*16 + b_r)*APV + chn*16 + b_kh*8) * 2;
            ldmx4(su + OV_HH*2 + voff, vh[2*p][0], vh[2*p][1], vh[2*p+1][0], vh[2*p+1][1]);
            ldmx4(su + OV_LL*2 + voff, vl[2*p][0], vl[2*p][1], vl[2*p+1][0], vl[2*p+1][1]);
        }
        #pragma unroll
        for (int mt = 0; mt < 2; mt++)
            #pragma unroll
            for (int nt = 0; nt < 4; nt++) {
                mma16816(oacc[mt][nt], pa_h[mt], vh[nt]);
                mma16816(oacc[mt][nt], pa_h[mt], vl[nt]);
                mma16816(oacc[mt][nt], pa_l[mt], vh[nt]);
            }
    }

    // ---- quad-reduce denominators, scale, store ----
    #pragma unroll
    for (int mt = 0; mt < 2; mt++) {
        den0[mt] += __shfl_xor_sync(0xffffffffu, den0[mt], 1);
        den0[mt] += __shfl_xor_sync(0xffffffffu, den0[mt], 2);
        den1[mt] += __shfl_xor_sync(0xffffffffu, den1[mt], 1);
        den1[mt] += __shfl_xor_sync(0xffffffffu, den1[mt], 2);
    }

    const int g = lid >> 2;
    const int t = lid & 3;
    #pragma unroll
    for (int mt = 0; mt < 2; mt++) {
        const float i0 = 1.f / den0[mt];
        const float i1 = 1.f / den1[mt];
        const int pr0 = m_base + mt*16 + g;
        const int pr1 = pr0 + 8;
        const int h0 = ((win >> 3) << 4) | (pr0 >> 4);
        const int w0 = ((win & 7)  << 4) | (pr0 & 15);
        const int h1 = ((win >> 3) << 4) | (pr1 >> 4);
        const int w1 = ((win & 7)  << 4) | (pr1 & 15);
        float* op0 = g_att[z] + (size_t)(((n << 7) + h0)*WW + w0)*DIM + head*DH;
        float* op1 = g_att[z] + (size_t)(((n << 7) + h1)*WW + w1)*DIM + head*DH;
        #pragma unroll
        for (int nt = 0; nt < 4; nt++) {
            *(float2*)(op0 + nt*8 + 2*t) =
                make_float2(oacc[mt][nt][0] * i0, oacc[mt][nt][1] * i0);
            *(float2*)(op1 + nt*8 + 2*t) =
                make_float2(oacc[mt][nt][2] * i1, oacc[mt][nt][3] * i1);
        }
    }
}

// --------------------------- lepe (depthwise 3x3) --------------------------
__global__ __launch_bounds__(256) void k_lepe(
    const float* __restrict__ lw, const float* __restrict__ lb)
{
    const int vb = blockIdx.z, ob = blockIdx.z;
    __shared__ float swt[DIM*9];
    const int blk = blockIdx.x;
    const int c = threadIdx.x;
    for (int e = c; e < DIM*9; e += 256) swt[e] = lw[e];
    __syncthreads();

    const int n  = blk >> 12;
    const int r  = blk & 4095;
    const int h  = r >> 5;
    const int w0 = (r & 31) << 2;

    const float* wrow = &swt[c*9];
    float acc[4];
    {
        float* op = g_att[ob] + (size_t)((((n << 7) + h) << 7) + w0)*DIM + c;
        const float bb = lb[c];
        #pragma unroll
        for (int k = 0; k < 4; k++) acc[k] = op[k*DIM] + bb;
    }

    #pragma unroll
    for (int dy = 0; dy < 3; dy++) {
        const int hh = h + dy - 1;
        if ((unsigned)hh >= (unsigned)HH) continue;
        #pragma unroll
        for (int cc = 0; cc < 6; cc++) {
            const int ww = w0 - 1 + cc;
            if ((unsigned)ww >= (unsigned)WW) continue;
            const int vwin = ((hh >> 4) << 3) | (ww >> 4);
            const int vpix = ((hh & 15) << 4) | (ww & 15);
            const float v = g_qkv[vb]
                [(size_t)(((n << 6) | vwin)*W2 + vpix)*QKVC + CKV + c];
            #pragma unroll
            for (int k = 0; k < 4; k++) {
                const int dx = cc - k;
                if (dx >= 0 && dx <= 2)
                    acc[k] += v * wrow[dy*3 + dx];
            }
        }
    }

    float* op = g_att[ob] + (size_t)((((n << 7) + h) << 7) + w0)*DIM + c;
    #pragma unroll
    for (int k = 0; k < 4; k++) op[k*DIM] = acc[k];
}

// ------------------------------- launch ------------------------------------
extern "C" void kernel_launch(void* const* d_in, const int* in_sizes, int n_in,
                              void* d_out, int out_size)
{
    const float* x1   = (const float*)d_in[0];
    const float* x2   = (const float*)d_in[1];
    const float* Wqkv = (const float*)d_in[2];
    const float* bqkv = (const float*)d_in[3];
    const float* lw   = (const float*)d_in[4];
    const float* lb   = (const float*)d_in[5];
    const float* Wo   = (const float*)d_in[6];
    const float* bo   = (const float*)d_in[7];
    float* out = (float*)d_out;

    cudaFuncSetAttribute(k_mma_gemm,
        cudaFuncAttributeMaxDynamicSharedMemorySize, GEMM_SMEM);
    cudaFuncSetAttribute(k_attend,
        cudaFuncAttributeMaxDynamicSharedMemorySize, ATT_SMEM);

    k_mma_gemm<<<dim3(QKVC/128, TOK/128, 2), 256, GEMM_SMEM>>>(
        x1, x2, 0, Wqkv, bqkv, nullptr, QKVC);

    k_pool<<<dim3(NB*P2, 2), 768>>>();

    k_route<<<dim3(P2, NB, 2), 64>>>();

    k_attend<<<dim3(NB*P2, HEADS, 2), 256, ATT_SMEM>>>();

    k_lepe<<<dim3(NB*HH*WW/4, 1, 2), 256>>>(lw, lb);

    k_mma_gemm<<<dim3(DIM/128, TOK/128, 2), 256, GEMM_SMEM>>>(
        nullptr, nullptr, 1, Wo, bo, out, DIM);
}

// round 12
// speedup vs baseline: 1.5333x; 1.0104x over previous
#include <cuda_runtime.h>
#include <cuda_bf16.h>
#include <cstdint>

// ---------------------------------------------------------------------------
// SpatialEncoder: bi-level routing attention.
// GEMMs: mma.sync bf16 split-precision (3-product), double-buffered smem,
//        PRODUCT-MAJOR mma order (same-acc reuse distance 16 -> latency hidden).
// attend: HMMA flash-style, product-major order likewise.
// ---------------------------------------------------------------------------

#define NB    4
#define HH    128
#define WW    128
#define DIM   256
#define QK    256
#define CKV   512
#define QKVC  768
#define NW    8
#define P2    64
#define W2    256
#define W2KV  16
#define TOPK  4
#define HEADS 8
#define DH    32
#define TOK   (NB*P2*W2)
#define SCALEF 0.0625f

typedef unsigned long long u64;
typedef unsigned int u32;

// ---- packed f32x2 helpers --------------------------------------------------
__device__ __forceinline__ u64 pack2(float x, float y){
    u64 r; asm("mov.b64 %0,{%1,%2};" : "=l"(r) : "f"(x), "f"(y)); return r;
}
__device__ __forceinline__ u64 dup2(float x){
    u64 r; asm("mov.b64 %0,{%1,%1};" : "=l"(r) : "f"(x)); return r;
}
__device__ __forceinline__ void fma2(u64 &a, u64 b, u64 c){
    asm("fma.rn.f32x2 %0,%1,%2,%0;" : "+l"(a) : "l"(b), "l"(c));
}
__device__ __forceinline__ u64 mul2(u64 a, u64 b){
    u64 r; asm("mul.rn.f32x2 %0,%1,%2;" : "=l"(r) : "l"(a), "l"(b)); return r;
}
__device__ __forceinline__ float2 unp2(u64 v){
    float lo, hi; asm("mov.b64 {%0,%1},%2;" : "=f"(lo), "=f"(hi) : "l"(v));
    return make_float2(lo, hi);
}

__device__ __forceinline__ u32 smem_u32(const void* p){
    u32 a; asm("{ .reg .u64 t; cvta.to.shared.u64 t, %1; cvt.u32.u64 %0, t; }"
               : "=r"(a) : "l"(p));
    return a;
}

// fp32 -> (bf16 hi, bf16 lo) for a float4, packed as two u64 (4 bf16 each)
__device__ __forceinline__ void cvt4(float4 v, u64& hi, u64& lo){
    float f0=v.x, f1=v.y, f2=v.z, f3=v.w;
    __nv_bfloat16 h0=__float2bfloat16_rn(f0), h1=__float2bfloat16_rn(f1);
    __nv_bfloat16 h2=__float2bfloat16_rn(f2), h3=__float2bfloat16_rn(f3);
    unsigned short a0=__bfloat16_as_ushort(h0), a1=__bfloat16_as_ushort(h1);
    unsigned short a2=__bfloat16_as_ushort(h2), a3=__bfloat16_as_ushort(h3);
    hi = (u64)a0 | ((u64)a1<<16) | ((u64)a2<<32) | ((u64)a3<<48);
    unsigned short b0=__bfloat16_as_ushort(__float2bfloat16_rn(f0-__bfloat162float(h0)));
    unsigned short b1=__bfloat16_as_ushort(__float2bfloat16_rn(f1-__bfloat162float(h1)));
    unsigned short b2=__bfloat16_as_ushort(__float2bfloat16_rn(f2-__bfloat162float(h2)));
    unsigned short b3=__bfloat16_as_ushort(__float2bfloat16_rn(f3-__bfloat162float(h3)));
    lo = (u64)b0 | ((u64)b1<<16) | ((u64)b2<<32) | ((u64)b3<<48);
}

// pack two f32 into bf16x2: low half = lo, high half = hi
__device__ __forceinline__ u32 pkbf(float lo, float hi){
    u32 d; asm("cvt.rn.bf16x2.f32 %0,%1,%2;" : "=r"(d) : "f"(hi), "f"(lo));
    return d;
}

__device__ __forceinline__ void ldmx4(u32 addr, u32& r0, u32& r1, u32& r2, u32& r3){
    asm volatile("ldmatrix.sync.aligned.m8n8.x4.shared.b16 {%0,%1,%2,%3},[%4];"
                 : "=r"(r0),"=r"(r1),"=r"(r2),"=r"(r3) : "r"(addr));
}
__device__ __forceinline__ void mma16816(float* c, const u32* a, const u32* b){
    asm volatile("mma.sync.aligned.m16n8k16.row.col.f32.bf16.bf16.f32 "
        "{%0,%1,%2,%3},{%4,%5,%6,%7},{%8,%9},{%0,%1,%2,%3};"
        : "+f"(c[0]),"+f"(c[1]),"+f"(c[2]),"+f"(c[3])
        : "r"(a[0]),"r"(a[1]),"r"(a[2]),"r"(a[3]),"r"(b[0]),"r"(b[1]));
}

// -------- scratch -----------------------------------------------------------
__device__ float g_qkv [2][(size_t)TOK*QKVC];
__device__ float g_pool[2][NB*P2*W2KV*CKV];
__device__ float g_qwin[2][NB*P2*QK];
__device__ float g_kwin[2][NB*P2*QK];
__device__ int   g_idx [2][NB*P2*TOPK];
__device__ float g_att [2][(size_t)NB*HH*WW*DIM];

// ------------------------- HMMA split-bf16 GEMM -----------------------------
#define PAD    40
#define TILE_E (128*PAD)
#define STAGE_B (4*TILE_E*2)
#define GEMM_SMEM (2*STAGE_B)

__global__ __launch_bounds__(256) void k_mma_gemm(
    const float* __restrict__ A0, const float* __restrict__ A1, int mode,
    const float* __restrict__ Wm, const float* __restrict__ bias,
    float* __restrict__ Oext, int ostride)
{
    extern __shared__ __nv_bfloat16 smx[];

    const int z   = blockIdx.z;
    const int tid = threadIdx.x;
    const int wid = tid >> 5;
    const int lid = tid & 31;
    const int t0  = blockIdx.y * 128;
    const int jn0 = blockIdx.x * 128;

    const float* A;
    float* O;
    if (mode == 0) { A = z ? A1 : A0; O = g_qkv[z]; }
    else           { A = g_att[z];    O = Oext + (size_t)z * ((size_t)TOK * DIM); }

    const int m_base = (wid >> 2) * 64;
    const int n_base = (wid & 3) * 32;

    const int lrow = tid >> 3;
    const int lcg  = tid & 7;

    const float* arow[4];
    #pragma unroll
    for (int i = 0; i < 4; i++) {
        const int row = lrow + i * 32;
        if (mode == 0) {
            const int ltok = t0 + row;
            const int n = ltok >> 14, r = ltok & 16383;
            const int win = r >> 8, pix = r & 255;
            const int h = ((win >> 3) << 4) | (pix >> 4);
            const int w = ((win & 7) << 4) | (pix & 15);
            arow[i] = A + ((size_t)(((n << 7) + h) << 7) + w) * DIM + lcg * 4;
        } else {
            arow[i] = A + (size_t)(t0 + row) * DIM + lcg * 4;
        }
    }
    const float* brow[4];
    #pragma unroll
    for (int i = 0; i < 4; i++)
        brow[i] = Wm + (size_t)(jn0 + lrow + i * 32) * 256 + lcg * 4;

    const u32 su = smem_u32(smx);

    const int a_r  = lid & 15;
    const int a_kh = lid >> 4;
    const int b_r  = (lid & 7) | ((lid >> 4) << 3);
    const int b_kh = (lid >> 3) & 1;

    float acc[4][4][4];
    #pragma unroll
    for (int mt = 0; mt < 4; mt++)
        #pragma unroll
        for (int nt = 0; nt < 4; nt++)
            #pragma unroll
            for (int r = 0; r < 4; r++) acc[mt][nt][r] = 0.f;

    float4 ra[4], rb[4];
    #pragma unroll
    for (int i = 0; i < 4; i++) { ra[i] = *(const float4*)(arow[i]); rb[i] = *(const float4*)(brow[i]); }

    {
        __nv_bfloat16* st = smx;
        #pragma unroll
        for (int i = 0; i < 4; i++) {
            const int off = (lrow + i * 32) * PAD + lcg * 4;
            u64 hi, lo;
            cvt4(ra[i], hi, lo);
            *(u64*)(st + off) = hi;  *(u64*)(st + TILE_E + off) = lo;
            cvt4(rb[i], hi, lo);
            *(u64*)(st + 2*TILE_E + off) = hi;  *(u64*)(st + 3*TILE_E + off) = lo;
        }
    }
    __syncthreads();

    for (int ch = 0; ch < 8; ch++) {
        const int cur = ch & 1;
        if (ch < 7) {
            const int k1 = (ch + 1) * 32;
            #pragma unroll
            for (int i = 0; i < 4; i++) {
                ra[i] = *(const float4*)(arow[i] + k1);
                rb[i] = *(const float4*)(brow[i] + k1);
            }
        }
        const u32 sb = su + cur * STAGE_B;
        #pragma unroll
        for (int s = 0; s < 2; s++) {
            const int koff = s * 16;
            u32 ah[4][4], al[4][4], bh[4][2], bl[4][2];
            #pragma unroll
            for (int mt = 0; mt < 4; mt++) {
                const u32 eoff = (u32)((m_base + mt*16 + a_r) * PAD + koff + a_kh*8) * 2;
                ldmx4(sb + eoff,              ah[mt][0], ah[mt][1], ah[mt][2], ah[mt][3]);
                ldmx4(sb + TILE_E*2 + eoff,   al[mt][0], al[mt][1], al[mt][2], al[mt][3]);
            }
            #pragma unroll
            for (int p = 0; p < 2; p++) {
                const u32 eoff = (u32)((n_base + p*16 + b_r) * PAD + koff + b_kh*8) * 2;
                ldmx4(sb + TILE_E*4 + eoff, bh[2*p][0], bh[2*p][1], bh[2*p+1][0], bh[2*p+1][1]);
                ldmx4(sb + TILE_E*6 + eoff, bl[2*p][0], bl[2*p][1], bl[2*p+1][0], bl[2*p+1][1]);
            }
            // product-major: all 16 accs get hh, then hl, then lh.
            // per-acc add order unchanged (hh->hl->lh) => bitwise identical.
            #pragma unroll
            for (int mt = 0; mt < 4; mt++)
                #pragma unroll
                for (int nt = 0; nt < 4; nt++)
                    mma16816(acc[mt][nt], ah[mt], bh[nt]);
            #pragma unroll
            for (int mt = 0; mt < 4; mt++)
                #pragma unroll
                for (int nt = 0; nt < 4; nt++)
                    mma16816(acc[mt][nt], ah[mt], bl[nt]);
            #pragma unroll
            for (int mt = 0; mt < 4; mt++)
                #pragma unroll
                for (int nt = 0; nt < 4; nt++)
                    mma16816(acc[mt][nt], al[mt], bh[nt]);
        }
        if (ch < 7) {
            __nv_bfloat16* st = smx + (cur ^ 1) * (4*TILE_E);
            #pragma unroll
            for (int i = 0; i < 4; i++) {
                const int off = (lrow + i * 32) * PAD + lcg * 4;
                u64 hi, lo;
                cvt4(ra[i], hi, lo);
                *(u64*)(st + off) = hi;  *(u64*)(st + TILE_E + off) = lo;
                cvt4(rb[i], hi, lo);
                *(u64*)(st + 2*TILE_E + off) = hi;  *(u64*)(st + 3*TILE_E + off) = lo;
            }
            __syncthreads();
        }
    }

    const int qr = lid >> 2;
    const int qc = (lid & 3) * 2;
    #pragma unroll
    for (int mt = 0; mt < 4; mt++) {
        const int row0 = t0 + m_base + mt*16 + qr;
        #pragma unroll
        for (int nt = 0; nt < 4; nt++) {
            const int col = jn0 + n_base + nt*8 + qc;
            const float b0 = bias[col], b1 = bias[col+1];
            float2 v0 = make_float2(acc[mt][nt][0] + b0, acc[mt][nt][1] + b1);
            float2 v1 = make_float2(acc[mt][nt][2] + b0, acc[mt][nt][3] + b1);
            *(float2*)(O + (size_t)row0 * ostride + col)       = v0;
            *(float2*)(O + (size_t)(row0+8) * ostride + col)   = v1;
        }
    }
}

// ------------------------------ pooling ------------------------------------
__global__ __launch_bounds__(768) void k_pool()
{
    const int b = blockIdx.y;
    const int nwin = blockIdx.x;
    const int tid = threadIdx.x;
    const float* base = g_qkv[b] + (size_t)nwin * W2 * QKVC + tid;

    float s[16];
    #pragma unroll
    for (int i = 0; i < 16; i++) s[i] = 0.f;
    #pragma unroll 4
    for (int py = 0; py < 16; py++) {
        const int sr = (py >> 2) << 2;
        #pragma unroll
        for (int px = 0; px < 16; px++)
            s[sr + (px >> 2)] += base[(size_t)(py*16 + px) * QKVC];
    }
    float tot = 0.f;
    #pragma unroll
    for (int i = 0; i < 16; i++) tot += s[i];

    if (tid < QK) {
        g_qwin[b][nwin*QK + tid] = tot * (1.f/256.f);
    } else {
        const int c = tid - QK;
        #pragma unroll
        for (int i = 0; i < 16; i++)
            g_pool[b][(size_t)(nwin*W2KV + i)*CKV + c] = s[i] * (1.f/16.f);
        if (c < QK)
            g_kwin[b][nwin*QK + c] = tot * (1.f/256.f);
    }
}

// ------------------------------ routing ------------------------------------
__global__ void k_route()
{
    const int ib = blockIdx.z;
    const int qb = 1 ^ ib, kb = ib;
    const int i = blockIdx.x;
    const int n = blockIdx.y;
    const int j = threadIdx.x;
    const float* qp = g_qwin[qb] + (size_t)(n*P2 + i)*QK;
    const float* kp = g_kwin[kb] + (size_t)(n*P2 + j)*QK;
    float s = 0.f;
    for (int c = 0; c < QK; c++) s += qp[c]*kp[c];
    s *= SCALEF;
    if (j == i) s = 1.0f;
    __shared__ float lg[P2];
    lg[j] = s;
    __syncthreads();
    if (j == 0) {
        #pragma unroll
        for (int t = 0; t < TOPK; t++) {
            float best = -1e30f; int bi = 0;
            for (int u = 0; u < P2; u++)
                if (lg[u] > best) { best = lg[u]; bi = u; }
            g_idx[ib][(n*P2 + i)*TOPK + t] = bi;
            lg[bi] = -1e30f;
        }
    }
}

// ----------------------------- attention (HMMA) -----------------------------
#define APQ 40
#define APK 40
#define APV 72
#define OQ_H 0
#define OQ_L (OQ_H + 256*APQ)
#define OK_HH (OQ_L + 256*APQ)
#define OK_LL (OK_HH + 64*APK)
#define OV_HH (OK_LL + 64*APK)
#define OV_LL (OV_HH + 32*APV)
#define ATT_SMEM ((OV_LL + 32*APV)*2)

__global__ __launch_bounds__(256, 2) void k_attend()
{
    extern __shared__ __nv_bfloat16 sma[];
    __shared__ int sel[TOPK];

    const int z = blockIdx.z;
    const int qb = 1 ^ z, kvb = z, ib = z;
    const int nwin = blockIdx.x;
    const int head = blockIdx.y;
    const int n   = nwin >> 6;
    const int win = nwin & 63;
    const int tid = threadIdx.x;
    const int wid = tid >> 5;
    const int lid = tid & 31;

    if (tid < TOPK) sel[tid] = g_idx[ib][nwin*TOPK + tid];
    __syncthreads();

    for (int e = tid; e < 64*32; e += 256) {
        const int tkn = e >> 5, c = e & 31;
        const int sw  = sel[tkn >> 4];
        const float* pp = g_pool[kvb] + (size_t)((n*P2 + sw)*W2KV + (tkn & 15))*CKV;
        const float kv = pp[head*DH + c];
        const float vv = pp[QK + head*DH + c];
        const __nv_bfloat16 kh = __float2bfloat16_rn(kv);
        sma[OK_HH + tkn*APK + c] = kh;
        sma[OK_LL + tkn*APK + c] = __float2bfloat16_rn(kv - __bfloat162float(kh));
        const __nv_bfloat16 vh = __float2bfloat16_rn(vv);
        sma[OV_HH + c*APV + tkn] = vh;
        sma[OV_LL + c*APV + tkn] = __float2bfloat16_rn(vv - __bfloat162float(vh));
    }
    {
        const float* qp = g_qkv[qb] + (size_t)(nwin*W2 + tid)*QKVC + head*DH;
        #pragma unroll
        for (int cg = 0; cg < 8; cg++) {
            float4 v = *(const float4*)(qp + cg*4);
            v.x *= SCALEF; v.y *= SCALEF; v.z *= SCALEF; v.w *= SCALEF;
            u64 hi, lo; cvt4(v, hi, lo);
            *(u64*)(&sma[OQ_H + tid*APQ + cg*4]) = hi;
            *(u64*)(&sma[OQ_L + tid*APQ + cg*4]) = lo;
        }
    }
    __syncthreads();

    const u32 su = smem_u32(sma);
    const int a_r  = lid & 15;
    const int a_kh = lid >> 4;
    const int b_r  = (lid & 7) | ((lid >> 4) << 3);
    const int b_kh = (lid >> 3) & 1;
    const int m_base = wid * 32;

    float oacc[2][4][4];
    #pragma unroll
    for (int mt = 0; mt < 2; mt++)
        #pragma unroll
        for (int nt = 0; nt < 4; nt++)
            #pragma unroll
            for (int r = 0; r < 4; r++) oacc[mt][nt][r] = 0.f;
    float den0[2] = {0.f, 0.f}, den1[2] = {0.f, 0.f};

    for (int chn = 0; chn < 4; chn++) {
        float sacc[2][2][4];
        #pragma unroll
        for (int mt = 0; mt < 2; mt++)
            #pragma unroll
            for (int p = 0; p < 2; p++)
                #pragma unroll
                for (int r = 0; r < 4; r++) sacc[mt][p][r] = 0.f;

        #pragma unroll
        for (int ks = 0; ks < 2; ks++) {
            u32 qh[2][4], ql[2][4];
            #pragma unroll
            for (int mt = 0; mt < 2; mt++) {
                const u32 qoff = (u32)((m_base + mt*16 + a_r)*APQ + ks*16 + a_kh*8) * 2;
                ldmx4(su + OQ_H*2 + qoff, qh[mt][0], qh[mt][1], qh[mt][2], qh[mt][3]);
                ldmx4(su + OQ_L*2 + qoff, ql[mt][0], ql[mt][1], ql[mt][2], ql[mt][3]);
            }
            u32 kh[2][2], kl[2][2];
            const u32 koff = (u32)((chn*16 + b_r)*APK + ks*16 + b_kh*8) * 2;
            ldmx4(su + OK_HH*2 + koff, kh[0][0], kh[0][1], kh[1][0], kh[1][1]);
            ldmx4(su + OK_LL*2 + koff, kl[0][0], kl[0][1], kl[1][0], kl[1][1]);
            // product-major (per-acc order qh*kh -> qh*kl -> ql*kh preserved)
            #pragma unroll
            for (int mt = 0; mt < 2; mt++)
                #pragma unroll
                for (int p = 0; p < 2; p++)
                    mma16816(sacc[mt][p], qh[mt], kh[p]);
            #pragma unroll
            for (int mt = 0; mt < 2; mt++)
                #pragma unroll
                for (int p = 0; p < 2; p++)
                    mma16816(sacc[mt][p], qh[mt], kl[p]);
            #pragma unroll
            for (int mt = 0; mt < 2; mt++)
                #pragma unroll
                for (int p = 0; p < 2; p++)
                    mma16816(sacc[mt][p], ql[mt], kh[p]);
        }

        u32 pa_h[2][4], pa_l[2][4];
        #pragma unroll
        for (int mt = 0; mt < 2; mt++) {
            float e[2][4];
            #pragma unroll
            for (int p = 0; p < 2; p++)
                #pragma unroll
                for (int r = 0; r < 4; r++)
                    e[p][r] = __expf(sacc[mt][p][r]);
            den0[mt] += (e[0][0] + e[0][1]) + (e[1][0] + e[1][1]);
            den1[mt] += (e[0][2] + e[0][3]) + (e[1][2] + e[1][3]);
            float hf[2][4], lf[2][4];
            #pragma unroll
            for (int p = 0; p < 2; p++)
                #pragma unroll
                for (int r = 0; r < 4; r++) {
                    hf[p][r] = __bfloat162float(__float2bfloat16_rn(e[p][r]));
                    lf[p][r] = e[p][r] - hf[p][r];
                }
            pa_h[mt][0] = pkbf(hf[0][0], hf[0][1]);
            pa_h[mt][1] = pkbf(hf[0][2], hf[0][3]);
            pa_h[mt][2] = pkbf(hf[1][0], hf[1][1]);
            pa_h[mt][3] = pkbf(hf[1][2], hf[1][3]);
            pa_l[mt][0] = pkbf(lf[0][0], lf[0][1]);
            pa_l[mt][1] = pkbf(lf[0][2], lf[0][3]);
            pa_l[mt][2] = pkbf(lf[1][0], lf[1][1]);
            pa_l[mt][3] = pkbf(lf[1][2], lf[1][3]);
        }

        u32 vh[4][2], vl[4][2];
        #pragma unroll
        for (int p = 0; p < 2; p++) {
            const u32 voff = (u32)((p*16 + b_r)*APV + chn*16 + b_kh*8) * 2;
            ldmx4(su + OV_HH*2 + voff, vh[2*p][0], vh[2*p][1], vh[2*p+1][0], vh[2*p+1][1]);
            ldmx4(su + OV_LL*2 + voff, vl[2*p][0], vl[2*p][1], vl[2*p+1][0], vl[2*p+1][1]);
        }
        // product-major PV
        #pragma unroll
        for (int mt = 0; mt < 2; mt++)
            #pragma unroll
            for (int nt = 0; nt < 4; nt++)
                mma16816(oacc[mt][nt], pa_h[mt], vh[nt]);
        #pragma unroll
        for (int mt = 0; mt < 2; mt++)
            #pragma unroll
            for (int nt = 0; nt < 4; nt++)
                mma16816(oacc[mt][nt], pa_h[mt], vl[nt]);
        #pragma unroll
        for (int mt = 0; mt < 2; mt++)
            #pragma unroll
            for (int nt = 0; nt < 4; nt++)
                mma16816(oacc[mt][nt], pa_l[mt], vh[nt]);
    }

    #pragma unroll
    for (int mt = 0; mt < 2; mt++) {
        den0[mt] += __shfl_xor_sync(0xffffffffu, den0[mt], 1);
        den0[mt] += __shfl_xor_sync(0xffffffffu, den0[mt], 2);
        den1[mt] += __shfl_xor_sync(0xffffffffu, den1[mt], 1);
        den1[mt] += __shfl_xor_sync(0xffffffffu, den1[mt], 2);
    }

    const int g = lid >> 2;
    const int t = lid & 3;
    #pragma unroll
    for (int mt = 0; mt < 2; mt++) {
        const float i0 = 1.f / den0[mt];
        const float i1 = 1.f / den1[mt];
        const int pr0 = m_base + mt*16 + g;
        const int pr1 = pr0 + 8;
        const int h0 = ((win >> 3) << 4) | (pr0 >> 4);
        const int w0 = ((win & 7)  << 4) | (pr0 & 15);
        const int h1 = ((win >> 3) << 4) | (pr1 >> 4);
        const int w1 = ((win & 7)  << 4) | (pr1 & 15);
        float* op0 = g_att[z] + (size_t)(((n << 7) + h0)*WW + w0)*DIM + head*DH;
        float* op1 = g_att[z] + (size_t)(((n << 7) + h1)*WW + w1)*DIM + head*DH;
        #pragma unroll
        for (int nt = 0; nt < 4; nt++) {
            *(float2*)(op0 + nt*8 + 2*t) =
                make_float2(oacc[mt][nt][0] * i0, oacc[mt][nt][1] * i0);
            *(float2*)(op1 + nt*8 + 2*t) =
                make_float2(oacc[mt][nt][2] * i1, oacc[mt][nt][3] * i1);
        }
    }
}

// --------------------------- lepe (depthwise 3x3) --------------------------
__global__ __launch_bounds__(256) void k_lepe(
    const float* __restrict__ lw, const float* __restrict__ lb)
{
    const int vb = blockIdx.z, ob = blockIdx.z;
    __shared__ float swt[DIM*9];
    const int blk = blockIdx.x;
    const int c = threadIdx.x;
    for (int e = c; e < DIM*9; e += 256) swt[e] = lw[e];
    __syncthreads();

    const int n  = blk >> 12;
    const int r  = blk & 4095;
    const int h  = r >> 5;
    const int w0 = (r & 31) << 2;

    const float* wrow = &swt[c*9];
    float acc[4];
    {
        float* op = g_att[ob] + (size_t)((((n << 7) + h) << 7) + w0)*DIM + c;
        const float bb = lb[c];
        #pragma unroll
        for (int k = 0; k < 4; k++) acc[k] = op[k*DIM] + bb;
    }

    #pragma unroll
    for (int dy = 0; dy < 3; dy++) {
        const int hh = h + dy - 1;
        if ((unsigned)hh >= (unsigned)HH) continue;
        #pragma unroll
        for (int cc = 0; cc < 6; cc++) {
            const int ww = w0 - 1 + cc;
            if ((unsigned)ww >= (unsigned)WW) continue;
            const int vwin = ((hh >> 4) << 3) | (ww >> 4);
            const int vpix = ((hh & 15) << 4) | (ww & 15);
            const float v = g_qkv[vb]
                [(size_t)(((n << 6) | vwin)*W2 + vpix)*QKVC + CKV + c];
            #pragma unroll
            for (int k = 0; k < 4; k++) {
                const int dx = cc - k;
                if (dx >= 0 && dx <= 2)
                    acc[k] += v * wrow[dy*3 + dx];
            }
        }
    }

    float* op = g_att[ob] + (size_t)((((n << 7) + h) << 7) + w0)*DIM + c;
    #pragma unroll
    for (int k = 0; k < 4; k++) op[k*DIM] = acc[k];
}

// ------------------------------- launch ------------------------------------
extern "C" void kernel_launch(void* const* d_in, const int* in_sizes, int n_in,
                              void* d_out, int out_size)
{
    const float* x1   = (const float*)d_in[0];
    const float* x2   = (const float*)d_in[1];
    const float* Wqkv = (const float*)d_in[2];
    const float* bqkv = (const float*)d_in[3];
    const float* lw   = (const float*)d_in[4];
    const float* lb   = (const float*)d_in[5];
    const float* Wo   = (const float*)d_in[6];
    const float* bo   = (const float*)d_in[7];
    float* out = (float*)d_out;

    cudaFuncSetAttribute(k_mma_gemm,
        cudaFuncAttributeMaxDynamicSharedMemorySize, GEMM_SMEM);
    cudaFuncSetAttribute(k_attend,
        cudaFuncAttributeMaxDynamicSharedMemorySize, ATT_SMEM);

    k_mma_gemm<<<dim3(QKVC/128, TOK/128, 2), 256, GEMM_SMEM>>>(
        x1, x2, 0, Wqkv, bqkv, nullptr, QKVC);

    k_pool<<<dim3(NB*P2, 2), 768>>>();

    k_route<<<dim3(P2, NB, 2), 64>>>();

    k_attend<<<dim3(NB*P2, HEADS, 2), 256, ATT_SMEM>>>();

    k_lepe<<<dim3(NB*HH*WW/4, 1, 2), 256>>>(lw, lb);

    k_mma_gemm<<<dim3(DIM/128, TOK/128, 2), 256, GEMM_SMEM>>>(
        nullptr, nullptr, 1, Wo, bo, out, DIM);
}

// round 13
// speedup vs baseline: 1.5881x; 1.0357x over previous
#include <cuda_runtime.h>
#include <cuda_bf16.h>
#include <cstdint>

// ---------------------------------------------------------------------------
// SpatialEncoder: bi-level routing attention.
// All fp32->bf16(hi/lo) splits hoisted into k_cvtx/k_cvtw/k_lepe epilogue;
// GEMMs are pure ldg->sts->ldmatrix->mma (3-product split, product-major).
// ---------------------------------------------------------------------------

#define NB    4
#define HH    128
#define WW    128
#define DIM   256
#define QK    256
#define CKV   512
#define QKVC  768
#define NW    8
#define P2    64
#define W2    256
#define W2KV  16
#define TOPK  4
#define HEADS 8
#define DH    32
#define TOK   (NB*P2*W2)
#define SCALEF 0.0625f

typedef unsigned long long u64;
typedef unsigned int u32;

// ---- packed f32x2 helpers --------------------------------------------------
__device__ __forceinline__ u64 pack2(float x, float y){
    u64 r; asm("mov.b64 %0,{%1,%2};" : "=l"(r) : "f"(x), "f"(y)); return r;
}
__device__ __forceinline__ u64 dup2(float x){
    u64 r; asm("mov.b64 %0,{%1,%1};" : "=l"(r) : "f"(x)); return r;
}
__device__ __forceinline__ void fma2(u64 &a, u64 b, u64 c){
    asm("fma.rn.f32x2 %0,%1,%2,%0;" : "+l"(a) : "l"(b), "l"(c));
}
__device__ __forceinline__ u64 mul2(u64 a, u64 b){
    u64 r; asm("mul.rn.f32x2 %0,%1,%2;" : "=l"(r) : "l"(a), "l"(b)); return r;
}
__device__ __forceinline__ float2 unp2(u64 v){
    float lo, hi; asm("mov.b64 {%0,%1},%2;" : "=f"(lo), "=f"(hi) : "l"(v));
    return make_float2(lo, hi);
}

__device__ __forceinline__ u32 smem_u32(const void* p){
    u32 a; asm("{ .reg .u64 t; cvta.to.shared.u64 t, %1; cvt.u32.u64 %0, t; }"
               : "=r"(a) : "l"(p));
    return a;
}

// fp32 -> (bf16 hi, bf16 lo) for a float4, packed as two u64 (4 bf16 each)
__device__ __forceinline__ void cvt4(float4 v, u64& hi, u64& lo){
    float f0=v.x, f1=v.y, f2=v.z, f3=v.w;
    __nv_bfloat16 h0=__float2bfloat16_rn(f0), h1=__float2bfloat16_rn(f1);
    __nv_bfloat16 h2=__float2bfloat16_rn(f2), h3=__float2bfloat16_rn(f3);
    unsigned short a0=__bfloat16_as_ushort(h0), a1=__bfloat16_as_ushort(h1);
    unsigned short a2=__bfloat16_as_ushort(h2), a3=__bfloat16_as_ushort(h3);
    hi = (u64)a0 | ((u64)a1<<16) | ((u64)a2<<32) | ((u64)a3<<48);
    unsigned short b0=__bfloat16_as_ushort(__float2bfloat16_rn(f0-__bfloat162float(h0)));
    unsigned short b1=__bfloat16_as_ushort(__float2bfloat16_rn(f1-__bfloat162float(h1)));
    unsigned short b2=__bfloat16_as_ushort(__float2bfloat16_rn(f2-__bfloat162float(h2)));
    unsigned short b3=__bfloat16_as_ushort(__float2bfloat16_rn(f3-__bfloat162float(h3)));
    lo = (u64)b0 | ((u64)b1<<16) | ((u64)b2<<32) | ((u64)b3<<48);
}

// pack two f32 into bf16x2: low half = lo, high half = hi
__device__ __forceinline__ u32 pkbf(float lo, float hi){
    u32 d; asm("cvt.rn.bf16x2.f32 %0,%1,%2;" : "=r"(d) : "f"(hi), "f"(lo));
    return d;
}

__device__ __forceinline__ void ldmx4(u32 addr, u32& r0, u32& r1, u32& r2, u32& r3){
    asm volatile("ldmatrix.sync.aligned.m8n8.x4.shared.b16 {%0,%1,%2,%3},[%4];"
                 : "=r"(r0),"=r"(r1),"=r"(r2),"=r"(r3) : "r"(addr));
}
__device__ __forceinline__ void mma16816(float* c, const u32* a, const u32* b){
    asm volatile("mma.sync.aligned.m16n8k16.row.col.f32.bf16.bf16.f32 "
        "{%0,%1,%2,%3},{%4,%5,%6,%7},{%8,%9},{%0,%1,%2,%3};"
        : "+f"(c[0]),"+f"(c[1]),"+f"(c[2]),"+f"(c[3])
        : "r"(a[0]),"r"(a[1]),"r"(a[2]),"r"(a[3]),"r"(b[0]),"r"(b[1]));
}

// -------- scratch -----------------------------------------------------------
__device__ float g_qkv [2][(size_t)TOK*QKVC];
__device__ float g_pool[2][NB*P2*W2KV*CKV];
__device__ float g_qwin[2][NB*P2*QK];
__device__ float g_kwin[2][NB*P2*QK];
__device__ int   g_idx [2][NB*P2*TOPK];
__device__ float g_att [2][(size_t)NB*HH*WW*DIM];
// bf16 hi/lo staging
__device__ __nv_bfloat16 g_xh[2][(size_t)TOK*DIM];   // x, window-token-major
__device__ __nv_bfloat16 g_xl[2][(size_t)TOK*DIM];
__device__ __nv_bfloat16 g_oh[2][(size_t)TOK*DIM];   // attn+lepe, image-major
__device__ __nv_bfloat16 g_ol[2][(size_t)TOK*DIM];
__device__ __nv_bfloat16 g_wqh[QKVC*DIM], g_wql[QKVC*DIM];
__device__ __nv_bfloat16 g_woh[DIM*DIM],  g_wol[DIM*DIM];

// ---------------------- input conversion kernels ---------------------------
__global__ __launch_bounds__(256) void k_cvtx(
    const float* __restrict__ x1, const float* __restrict__ x2)
{
    const int z = blockIdx.z;
    const float* X = z ? x2 : x1;
    const int e = blockIdx.x * 256 + threadIdx.x;   // float4 index
    const int t  = e >> 6;                          // window-major token
    const int cg = e & 63;
    const int n = t >> 14, r = t & 16383;
    const int win = r >> 8, pix = r & 255;
    const int h = ((win >> 3) << 4) | (pix >> 4);
    const int w = ((win & 7) << 4) | (pix & 15);
    float4 v = *(const float4*)(X + ((size_t)(((n << 7) + h) << 7) + w) * DIM + cg * 4);
    u64 hi, lo; cvt4(v, hi, lo);
    *(u64*)(&g_xh[z][(size_t)t*DIM + cg*4]) = hi;
    *(u64*)(&g_xl[z][(size_t)t*DIM + cg*4]) = lo;
}

__global__ __launch_bounds__(256) void k_cvtw(
    const float* __restrict__ Wqkv, const float* __restrict__ Wo)
{
    const int e = blockIdx.x * 256 + threadIdx.x;   // float4 index
    if (e < QKVC*DIM/4) {
        float4 v = *(const float4*)(Wqkv + e*4);
        u64 hi, lo; cvt4(v, hi, lo);
        *(u64*)(&g_wqh[e*4]) = hi;
        *(u64*)(&g_wql[e*4]) = lo;
    } else {
        const int f = e - QKVC*DIM/4;
        float4 v = *(const float4*)(Wo + f*4);
        u64 hi, lo; cvt4(v, hi, lo);
        *(u64*)(&g_woh[f*4]) = hi;
        *(u64*)(&g_wol[f*4]) = lo;
    }
}

// ------------------------- HMMA split-bf16 GEMM -----------------------------
#define PAD    40
#define TILE_E (128*PAD)
#define STAGE_B (4*TILE_E*2)
#define GEMM_SMEM (2*STAGE_B)

__global__ __launch_bounds__(256) void k_mma_gemm(
    const __nv_bfloat16* __restrict__ Ah, const __nv_bfloat16* __restrict__ Al,
    const __nv_bfloat16* __restrict__ Wh, const __nv_bfloat16* __restrict__ Wl,
    const float* __restrict__ bias,
    float* __restrict__ Oext, int mode, int ostride)
{
    extern __shared__ __nv_bfloat16 smx[];

    const int z   = blockIdx.z;
    const int tid = threadIdx.x;
    const int wid = tid >> 5;
    const int lid = tid & 31;
    const int t0  = blockIdx.y * 128;
    const int jn0 = blockIdx.x * 128;

    const size_t zoff = (size_t)z * ((size_t)TOK * DIM);
    const __nv_bfloat16* Azh = Ah + zoff;
    const __nv_bfloat16* Azl = Al + zoff;
    float* O = (mode == 0) ? g_qkv[z] : (Oext + zoff);

    const int m_base = (wid >> 2) * 64;
    const int n_base = (wid & 3) * 32;

    const int lrow = tid >> 3;
    const int lcg  = tid & 7;

    // linear row pointers (bf16, row stride 256)
    const __nv_bfloat16 *arh[4], *arl[4], *brh[4], *brl[4];
    #pragma unroll
    for (int i = 0; i < 4; i++) {
        const size_t ao = (size_t)(t0 + lrow + i*32) * DIM + lcg*4;
        arh[i] = Azh + ao;  arl[i] = Azl + ao;
        const size_t bo = (size_t)(jn0 + lrow + i*32) * DIM + lcg*4;
        brh[i] = Wh + bo;   brl[i] = Wl + bo;
    }

    const u32 su = smem_u32(smx);

    const int a_r  = lid & 15;
    const int a_kh = lid >> 4;
    const int b_r  = (lid & 7) | ((lid >> 4) << 3);
    const int b_kh = (lid >> 3) & 1;

    float acc[4][4][4];
    #pragma unroll
    for (int mt = 0; mt < 4; mt++)
        #pragma unroll
        for (int nt = 0; nt < 4; nt++)
            #pragma unroll
            for (int r = 0; r < 4; r++) acc[mt][nt][r] = 0.f;

    u64 rah[4], ral[4], rbh[4], rbl[4];
    #pragma unroll
    for (int i = 0; i < 4; i++) {
        rah[i] = *(const u64*)(arh[i]); ral[i] = *(const u64*)(arl[i]);
        rbh[i] = *(const u64*)(brh[i]); rbl[i] = *(const u64*)(brl[i]);
    }

    {
        __nv_bfloat16* st = smx;
        #pragma unroll
        for (int i = 0; i < 4; i++) {
            const int off = (lrow + i * 32) * PAD + lcg * 4;
            *(u64*)(st + off)            = rah[i];
            *(u64*)(st + TILE_E + off)   = ral[i];
            *(u64*)(st + 2*TILE_E + off) = rbh[i];
            *(u64*)(st + 3*TILE_E + off) = rbl[i];
        }
    }
    __syncthreads();

    for (int ch = 0; ch < 8; ch++) {
        const int cur = ch & 1;
        if (ch < 7) {
            const int k1 = (ch + 1) * 32;
            #pragma unroll
            for (int i = 0; i < 4; i++) {
                rah[i] = *(const u64*)(arh[i] + k1); ral[i] = *(const u64*)(arl[i] + k1);
                rbh[i] = *(const u64*)(brh[i] + k1); rbl[i] = *(const u64*)(brl[i] + k1);
            }
        }
        const u32 sb = su + cur * STAGE_B;
        #pragma unroll
        for (int s = 0; s < 2; s++) {
            const int koff = s * 16;
            u32 ah[4][4], al[4][4], bh[4][2], bl[4][2];
            #pragma unroll
            for (int mt = 0; mt < 4; mt++) {
                const u32 eoff = (u32)((m_base + mt*16 + a_r) * PAD + koff + a_kh*8) * 2;
                ldmx4(sb + eoff,              ah[mt][0], ah[mt][1], ah[mt][2], ah[mt][3]);
                ldmx4(sb + TILE_E*2 + eoff,   al[mt][0], al[mt][1], al[mt][2], al[mt][3]);
            }
            #pragma unroll
            for (int p = 0; p < 2; p++) {
                const u32 eoff = (u32)((n_base + p*16 + b_r) * PAD + koff + b_kh*8) * 2;
                ldmx4(sb + TILE_E*4 + eoff, bh[2*p][0], bh[2*p][1], bh[2*p+1][0], bh[2*p+1][1]);
                ldmx4(sb + TILE_E*6 + eoff, bl[2*p][0], bl[2*p][1], bl[2*p+1][0], bl[2*p+1][1]);
            }
            // product-major, per-acc order hh->hl->lh (bitwise stable)
            #pragma unroll
            for (int mt = 0; mt < 4; mt++)
                #pragma unroll
                for (int nt = 0; nt < 4; nt++)
                    mma16816(acc[mt][nt], ah[mt], bh[nt]);
            #pragma unroll
            for (int mt = 0; mt < 4; mt++)
                #pragma unroll
                for (int nt = 0; nt < 4; nt++)
                    mma16816(acc[mt][nt], ah[mt], bl[nt]);
            #pragma unroll
            for (int mt = 0; mt < 4; mt++)
                #pragma unroll
                for (int nt = 0; nt < 4; nt++)
                    mma16816(acc[mt][nt], al[mt], bh[nt]);
        }
        if (ch < 7) {
            __nv_bfloat16* st = smx + (cur ^ 1) * (4*TILE_E);
            #pragma unroll
            for (int i = 0; i < 4; i++) {
                const int off = (lrow + i * 32) * PAD + lcg * 4;
                *(u64*)(st + off)            = rah[i];
                *(u64*)(st + TILE_E + off)   = ral[i];
                *(u64*)(st + 2*TILE_E + off) = rbh[i];
                *(u64*)(st + 3*TILE_E + off) = rbl[i];
            }
            __syncthreads();
        }
    }

    const int qr = lid >> 2;
    const int qc = (lid & 3) * 2;
    #pragma unroll
    for (int mt = 0; mt < 4; mt++) {
        const int row0 = t0 + m_base + mt*16 + qr;
        #pragma unroll
        for (int nt = 0; nt < 4; nt++) {
            const int col = jn0 + n_base + nt*8 + qc;
            const float b0 = bias[col], b1 = bias[col+1];
            float2 v0 = make_float2(acc[mt][nt][0] + b0, acc[mt][nt][1] + b1);
            float2 v1 = make_float2(acc[mt][nt][2] + b0, acc[mt][nt][3] + b1);
            *(float2*)(O + (size_t)row0 * ostride + col)       = v0;
            *(float2*)(O + (size_t)(row0+8) * ostride + col)   = v1;
        }
    }
}

// ------------------------------ pooling ------------------------------------
__global__ __launch_bounds__(768) void k_pool()
{
    const int b = blockIdx.y;
    const int nwin = blockIdx.x;
    const int tid = threadIdx.x;
    const float* base = g_qkv[b] + (size_t)nwin * W2 * QKVC + tid;

    float s[16];
    #pragma unroll
    for (int i = 0; i < 16; i++) s[i] = 0.f;
    #pragma unroll 4
    for (int py = 0; py < 16; py++) {
        const int sr = (py >> 2) << 2;
        #pragma unroll
        for (int px = 0; px < 16; px++)
            s[sr + (px >> 2)] += base[(size_t)(py*16 + px) * QKVC];
    }
    float tot = 0.f;
    #pragma unroll
    for (int i = 0; i < 16; i++) tot += s[i];

    if (tid < QK) {
        g_qwin[b][nwin*QK + tid] = tot * (1.f/256.f);
    } else {
        const int c = tid - QK;
        #pragma unroll
        for (int i = 0; i < 16; i++)
            g_pool[b][(size_t)(nwin*W2KV + i)*CKV + c] = s[i] * (1.f/16.f);
        if (c < QK)
            g_kwin[b][nwin*QK + c] = tot * (1.f/256.f);
    }
}

// ------------------------------ routing ------------------------------------
__global__ void k_route()
{
    const int ib = blockIdx.z;
    const int qb = 1 ^ ib, kb = ib;
    const int i = blockIdx.x;
    const int n = blockIdx.y;
    const int j = threadIdx.x;
    const float* qp = g_qwin[qb] + (size_t)(n*P2 + i)*QK;
    const float* kp = g_kwin[kb] + (size_t)(n*P2 + j)*QK;
    float s = 0.f;
    for (int c = 0; c < QK; c++) s += qp[c]*kp[c];
    s *= SCALEF;
    if (j == i) s = 1.0f;
    __shared__ float lg[P2];
    lg[j] = s;
    __syncthreads();
    if (j == 0) {
        #pragma unroll
        for (int t = 0; t < TOPK; t++) {
            float best = -1e30f; int bi = 0;
            for (int u = 0; u < P2; u++)
                if (lg[u] > best) { best = lg[u]; bi = u; }
            g_idx[ib][(n*P2 + i)*TOPK + t] = bi;
            lg[bi] = -1e30f;
        }
    }
}

// ----------------------------- attention (HMMA) -----------------------------
#define APQ 40
#define APK 40
#define APV 72
#define OQ_H 0
#define OQ_L (OQ_H + 256*APQ)
#define OK_HH (OQ_L + 256*APQ)
#define OK_LL (OK_HH + 64*APK)
#define OV_HH (OK_LL + 64*APK)
#define OV_LL (OV_HH + 32*APV)
#define ATT_SMEM ((OV_LL + 32*APV)*2)

__global__ __launch_bounds__(256, 2) void k_attend()
{
    extern __shared__ __nv_bfloat16 sma[];
    __shared__ int sel[TOPK];

    const int z = blockIdx.z;
    const int qb = 1 ^ z, kvb = z, ib = z;
    const int nwin = blockIdx.x;
    const int head = blockIdx.y;
    const int n   = nwin >> 6;
    const int win = nwin & 63;
    const int tid = threadIdx.x;
    const int wid = tid >> 5;
    const int lid = tid & 31;

    if (tid < TOPK) sel[tid] = g_idx[ib][nwin*TOPK + tid];
    __syncthreads();

    for (int e = tid; e < 64*32; e += 256) {
        const int tkn = e >> 5, c = e & 31;
        const int sw  = sel[tkn >> 4];
        const float* pp = g_pool[kvb] + (size_t)((n*P2 + sw)*W2KV + (tkn & 15))*CKV;
        const float kv = pp[head*DH + c];
        const float vv = pp[QK + head*DH + c];
        const __nv_bfloat16 kh = __float2bfloat16_rn(kv);
        sma[OK_HH + tkn*APK + c] = kh;
        sma[OK_LL + tkn*APK + c] = __float2bfloat16_rn(kv - __bfloat162float(kh));
        const __nv_bfloat16 vh = __float2bfloat16_rn(vv);
        sma[OV_HH + c*APV + tkn] = vh;
        sma[OV_LL + c*APV + tkn] = __float2bfloat16_rn(vv - __bfloat162float(vh));
    }
    {
        const float* qp = g_qkv[qb] + (size_t)(nwin*W2 + tid)*QKVC + head*DH;
        #pragma unroll
        for (int cg = 0; cg < 8; cg++) {
            float4 v = *(const float4*)(qp + cg*4);
            v.x *= SCALEF; v.y *= SCALEF; v.z *= SCALEF; v.w *= SCALEF;
            u64 hi, lo; cvt4(v, hi, lo);
            *(u64*)(&sma[OQ_H + tid*APQ + cg*4]) = hi;
            *(u64*)(&sma[OQ_L + tid*APQ + cg*4]) = lo;
        }
    }
    __syncthreads();

    const u32 su = smem_u32(sma);
    const int a_r  = lid & 15;
    const int a_kh = lid >> 4;
    const int b_r  = (lid & 7) | ((lid >> 4) << 3);
    const int b_kh = (lid >> 3) & 1;
    const int m_base = wid * 32;

    float oacc[2][4][4];
    #pragma unroll
    for (int mt = 0; mt < 2; mt++)
        #pragma unroll
        for (int nt = 0; nt < 4; nt++)
            #pragma unroll
            for (int r = 0; r < 4; r++) oacc[mt][nt][r] = 0.f;
    float den0[2] = {0.f, 0.f}, den1[2] = {0.f, 0.f};

    for (int chn = 0; chn < 4; chn++) {
        float sacc[2][2][4];
        #pragma unroll
        for (int mt = 0; mt < 2; mt++)
            #pragma unroll
            for (int p = 0; p < 2; p++)
                #pragma unroll
                for (int r = 0; r < 4; r++) sacc[mt][p][r] = 0.f;

        #pragma unroll
        for (int ks = 0; ks < 2; ks++) {
            u32 qh[2][4], ql[2][4];
            #pragma unroll
            for (int mt = 0; mt < 2; mt++) {
                const u32 qoff = (u32)((m_base + mt*16 + a_r)*APQ + ks*16 + a_kh*8) * 2;
                ldmx4(su + OQ_H*2 + qoff, qh[mt][0], qh[mt][1], qh[mt][2], qh[mt][3]);
                ldmx4(su + OQ_L*2 + qoff, ql[mt][0], ql[mt][1], ql[mt][2], ql[mt][3]);
            }
            u32 kh[2][2], kl[2][2];
            const u32 koff = (u32)((chn*16 + b_r)*APK + ks*16 + b_kh*8) * 2;
            ldmx4(su + OK_HH*2 + koff, kh[0][0], kh[0][1], kh[1][0], kh[1][1]);
            ldmx4(su + OK_LL*2 + koff, kl[0][0], kl[0][1], kl[1][0], kl[1][1]);
            #pragma unroll
            for (int mt = 0; mt < 2; mt++)
                #pragma unroll
                for (int p = 0; p < 2; p++)
                    mma16816(sacc[mt][p], qh[mt], kh[p]);
            #pragma unroll
            for (int mt = 0; mt < 2; mt++)
                #pragma unroll
                for (int p = 0; p < 2; p++)
                    mma16816(sacc[mt][p], qh[mt], kl[p]);
            #pragma unroll
            for (int mt = 0; mt < 2; mt++)
                #pragma unroll
                for (int p = 0; p < 2; p++)
                    mma16816(sacc[mt][p], ql[mt], kh[p]);
        }

        u32 pa_h[2][4], pa_l[2][4];
        #pragma unroll
        for (int mt = 0; mt < 2; mt++) {
            float e[2][4];
            #pragma unroll
            for (int p = 0; p < 2; p++)
                #pragma unroll
                for (int r = 0; r < 4; r++)
                    e[p][r] = __expf(sacc[mt][p][r]);
            den0[mt] += (e[0][0] + e[0][1]) + (e[1][0] + e[1][1]);
            den1[mt] += (e[0][2] + e[0][3]) + (e[1][2] + e[1][3]);
            float hf[2][4], lf[2][4];
            #pragma unroll
            for (int p = 0; p < 2; p++)
                #pragma unroll
                for (int r = 0; r < 4; r++) {
                    hf[p][r] = __bfloat162float(__float2bfloat16_rn(e[p][r]));
                    lf[p][r] = e[p][r] - hf[p][r];
                }
            pa_h[mt][0] = pkbf(hf[0][0], hf[0][1]);
            pa_h[mt][1] = pkbf(hf[0][2], hf[0][3]);
            pa_h[mt][2] = pkbf(hf[1][0], hf[1][1]);
            pa_h[mt][3] = pkbf(hf[1][2], hf[1][3]);
            pa_l[mt][0] = pkbf(lf[0][0], lf[0][1]);
            pa_l[mt][1] = pkbf(lf[0][2], lf[0][3]);
            pa_l[mt][2] = pkbf(lf[1][0], lf[1][1]);
            pa_l[mt][3] = pkbf(lf[1][2], lf[1][3]);
        }

        u32 vh[4][2], vl[4][2];
        #pragma unroll
        for (int p = 0; p < 2; p++) {
            const u32 voff = (u32)((p*16 + b_r)*APV + chn*16 + b_kh*8) * 2;
            ldmx4(su + OV_HH*2 + voff, vh[2*p][0], vh[2*p][1], vh[2*p+1][0], vh[2*p+1][1]);
            ldmx4(su + OV_LL*2 + voff, vl[2*p][0], vl[2*p][1], vl[2*p+1][0], vl[2*p+1][1]);
        }
        #pragma unroll
        for (int mt = 0; mt < 2; mt++)
            #pragma unroll
            for (int nt = 0; nt < 4; nt++)
                mma16816(oacc[mt][nt], pa_h[mt], vh[nt]);
        #pragma unroll
        for (int mt = 0; mt < 2; mt++)
            #pragma unroll
            for (int nt = 0; nt < 4; nt++)
                mma16816(oacc[mt][nt], pa_h[mt], vl[nt]);
        #pragma unroll
        for (int mt = 0; mt < 2; mt++)
            #pragma unroll
            for (int nt = 0; nt < 4; nt++)
                mma16816(oacc[mt][nt], pa_l[mt], vh[nt]);
    }

    #pragma unroll
    for (int mt = 0; mt < 2; mt++) {
        den0[mt] += __shfl_xor_sync(0xffffffffu, den0[mt], 1);
        den0[mt] += __shfl_xor_sync(0xffffffffu, den0[mt], 2);
        den1[mt] += __shfl_xor_sync(0xffffffffu, den1[mt], 1);
        den1[mt] += __shfl_xor_sync(0xffffffffu, den1[mt], 2);
    }

    const int g = lid >> 2;
    const int t = lid & 3;
    #pragma unroll
    for (int mt = 0; mt < 2; mt++) {
        const float i0 = 1.f / den0[mt];
        const float i1 = 1.f / den1[mt];
        const int pr0 = m_base + mt*16 + g;
        const int pr1 = pr0 + 8;
        const int h0 = ((win >> 3) << 4) | (pr0 >> 4);
        const int w0 = ((win & 7)  << 4) | (pr0 & 15);
        const int h1 = ((win >> 3) << 4) | (pr1 >> 4);
        const int w1 = ((win & 7)  << 4) | (pr1 & 15);
        float* op0 = g_att[z] + (size_t)(((n << 7) + h0)*WW + w0)*DIM + head*DH;
        float* op1 = g_att[z] + (size_t)(((n << 7) + h1)*WW + w1)*DIM + head*DH;
        #pragma unroll
        for (int nt = 0; nt < 4; nt++) {
            *(float2*)(op0 + nt*8 + 2*t) =
                make_float2(oacc[mt][nt][0] * i0, oacc[mt][nt][1] * i0);
            *(float2*)(op1 + nt*8 + 2*t) =
                make_float2(oacc[mt][nt][2] * i1, oacc[mt][nt][3] * i1);
        }
    }
}

// --------------------------- lepe (depthwise 3x3) --------------------------
// writes attn+lepe result as bf16 hi/lo (the same split proj needs).
__global__ __launch_bounds__(256) void k_lepe(
    const float* __restrict__ lw, const float* __restrict__ lb)
{
    const int vb = blockIdx.z, ob = blockIdx.z;
    __shared__ float swt[DIM*9];
    const int blk = blockIdx.x;
    const int c = threadIdx.x;
    for (int e = c; e < DIM*9; e += 256) swt[e] = lw[e];
    __syncthreads();

    const int n  = blk >> 12;
    const int r  = blk & 4095;
    const int h  = r >> 5;
    const int w0 = (r & 31) << 2;

    const float* wrow = &swt[c*9];
    const size_t pbase = (size_t)((((n << 7) + h) << 7) + w0);
    float acc[4];
    {
        const float* op = g_att[ob] + pbase*DIM + c;
        const float bb = lb[c];
        #pragma unroll
        for (int k = 0; k < 4; k++) acc[k] = op[k*DIM] + bb;
    }

    #pragma unroll
    for (int dy = 0; dy < 3; dy++) {
        const int hh = h + dy - 1;
        if ((unsigned)hh >= (unsigned)HH) continue;
        #pragma unroll
        for (int cc = 0; cc < 6; cc++) {
            const int ww = w0 - 1 + cc;
            if ((unsigned)ww >= (unsigned)WW) continue;
            const int vwin = ((hh >> 4) << 3) | (ww >> 4);
            const int vpix = ((hh & 15) << 4) | (ww & 15);
            const float v = g_qkv[vb]
                [(size_t)(((n << 6) | vwin)*W2 + vpix)*QKVC + CKV + c];
            #pragma unroll
            for (int k = 0; k < 4; k++) {
                const int dx = cc - k;
                if (dx >= 0 && dx <= 2)
                    acc[k] += v * wrow[dy*3 + dx];
            }
        }
    }

    #pragma unroll
    for (int k = 0; k < 4; k++) {
        const __nv_bfloat16 hv = __float2bfloat16_rn(acc[k]);
        g_oh[ob][(pbase + k)*DIM + c] = hv;
        g_ol[ob][(pbase + k)*DIM + c] = __float2bfloat16_rn(acc[k] - __bfloat162float(hv));
    }
}

// ------------------------------- launch ------------------------------------
extern "C" void kernel_launch(void* const* d_in, const int* in_sizes, int n_in,
                              void* d_out, int out_size)
{
    const float* x1   = (const float*)d_in[0];
    const float* x2   = (const float*)d_in[1];
    const float* Wqkv = (const float*)d_in[2];
    const float* bqkv = (const float*)d_in[3];
    const float* lw   = (const float*)d_in[4];
    const float* lb   = (const float*)d_in[5];
    const float* Wo   = (const float*)d_in[6];
    const float* bo   = (const float*)d_in[7];
    float* out = (float*)d_out;

    cudaFuncSetAttribute(k_mma_gemm,
        cudaFuncAttributeMaxDynamicSharedMemorySize, GEMM_SMEM);
    cudaFuncSetAttribute(k_attend,
        cudaFuncAttributeMaxDynamicSharedMemorySize, ATT_SMEM);

    // resolve device-global addresses (host side, graph-safe)
    __nv_bfloat16 *xh, *xl, *oh, *ol, *wqh, *wql, *woh, *wol;
    cudaGetSymbolAddress((void**)&xh, g_xh);
    cudaGetSymbolAddress((void**)&xl, g_xl);
    cudaGetSymbolAddress((void**)&oh, g_oh);
    cudaGetSymbolAddress((void**)&ol, g_ol);
    cudaGetSymbolAddress((void**)&wqh, g_wqh);
    cudaGetSymbolAddress((void**)&wql, g_wql);
    cudaGetSymbolAddress((void**)&woh, g_woh);
    cudaGetSymbolAddress((void**)&wol, g_wol);

    k_cvtx<<<dim3(TOK*DIM/4/256, 1, 2), 256>>>(x1, x2);
    k_cvtw<<<(QKVC*DIM/4 + DIM*DIM/4)/256, 256>>>(Wqkv, Wo);

    k_mma_gemm<<<dim3(QKVC/128, TOK/128, 2), 256, GEMM_SMEM>>>(
        xh, xl, wqh, wql, bqkv, nullptr, 0, QKVC);

    k_pool<<<dim3(NB*P2, 2), 768>>>();

    k_route<<<dim3(P2, NB, 2), 64>>>();

    k_attend<<<dim3(NB*P2, HEADS, 2), 256, ATT_SMEM>>>();

    k_lepe<<<dim3(NB*HH*WW/4, 1, 2), 256>>>(lw, lb);

    k_mma_gemm<<<dim3(DIM/128, TOK/128, 2), 256, GEMM_SMEM>>>(
        oh, ol, woh, wol, bo, out, 1, DIM);
}

// round 16
// speedup vs baseline: 1.8893x; 1.1896x over previous
#include <cuda_runtime.h>
#include <cuda_bf16.h>
#include <cuda_fp16.h>
#include <cstdint>

// ---------------------------------------------------------------------------
// SpatialEncoder: bi-level routing attention.
// Routing logits computed EXACTLY from window-means of x (affine identity),
// so the big GEMMs can run fp16 2-product (A split, W single) at 2/3 mma cost.
// attend: HMMA flash-style bf16 3-product (unchanged).
// ---------------------------------------------------------------------------

#define NB    4
#define HH    128
#define WW    128
#define DIM   256
#define QK    256
#define CKV   512
#define QKVC  768
#define NW    8
#define P2    64
#define W2    256
#define W2KV  16
#define TOPK  4
#define HEADS 8
#define DH    32
#define TOK   (NB*P2*W2)
#define SCALEF 0.0625f

typedef unsigned long long u64;
typedef unsigned int u32;

__device__ __forceinline__ u32 smem_u32(const void* p){
    u32 a; asm("{ .reg .u64 t; cvta.to.shared.u64 t, %1; cvt.u32.u64 %0, t; }"
               : "=r"(a) : "l"(p));
    return a;
}

// fp32 float4 -> fp16 hi u64 + fp16 lo u64
__device__ __forceinline__ void cvt4h(float4 v, u64& hi, u64& lo){
    __half h0=__float2half_rn(v.x), h1=__float2half_rn(v.y);
    __half h2=__float2half_rn(v.z), h3=__float2half_rn(v.w);
    unsigned short a0=__half_as_ushort(h0), a1=__half_as_ushort(h1);
    unsigned short a2=__half_as_ushort(h2), a3=__half_as_ushort(h3);
    hi = (u64)a0 | ((u64)a1<<16) | ((u64)a2<<32) | ((u64)a3<<48);
    unsigned short b0=__half_as_ushort(__float2half_rn(v.x-__half2float(h0)));
    unsigned short b1=__half_as_ushort(__float2half_rn(v.y-__half2float(h1)));
    unsigned short b2=__half_as_ushort(__float2half_rn(v.z-__half2float(h2)));
    unsigned short b3=__half_as_ushort(__float2half_rn(v.w-__half2float(h3)));
    lo = (u64)b0 | ((u64)b1<<16) | ((u64)b2<<32) | ((u64)b3<<48);
}

// fp32 float4 -> bf16 hi/lo (attend path)
__device__ __forceinline__ void cvt4(float4 v, u64& hi, u64& lo){
    __nv_bfloat16 h0=__float2bfloat16_rn(v.x), h1=__float2bfloat16_rn(v.y);
    __nv_bfloat16 h2=__float2bfloat16_rn(v.z), h3=__float2bfloat16_rn(v.w);
    unsigned short a0=__bfloat16_as_ushort(h0), a1=__bfloat16_as_ushort(h1);
    unsigned short a2=__bfloat16_as_ushort(h2), a3=__bfloat16_as_ushort(h3);
    hi = (u64)a0 | ((u64)a1<<16) | ((u64)a2<<32) | ((u64)a3<<48);
    unsigned short b0=__bfloat16_as_ushort(__float2bfloat16_rn(v.x-__bfloat162float(h0)));
    unsigned short b1=__bfloat16_as_ushort(__float2bfloat16_rn(v.y-__bfloat162float(h1)));
    unsigned short b2=__bfloat16_as_ushort(__float2bfloat16_rn(v.z-__bfloat162float(h2)));
    unsigned short b3=__bfloat16_as_ushort(__float2bfloat16_rn(v.w-__bfloat162float(h3)));
    lo = (u64)b0 | ((u64)b1<<16) | ((u64)b2<<32) | ((u64)b3<<48);
}

__device__ __forceinline__ u32 pkbf(float lo, float hi){
    u32 d; asm("cvt.rn.bf16x2.f32 %0,%1,%2;" : "=r"(d) : "f"(hi), "f"(lo));
    return d;
}

__device__ __forceinline__ void ldmx4(u32 addr, u32& r0, u32& r1, u32& r2, u32& r3){
    asm volatile("ldmatrix.sync.aligned.m8n8.x4.shared.b16 {%0,%1,%2,%3},[%4];"
                 : "=r"(r0),"=r"(r1),"=r"(r2),"=r"(r3) : "r"(addr));
}
__device__ __forceinline__ void mma_bf(float* c, const u32* a, const u32* b){
    asm volatile("mma.sync.aligned.m16n8k16.row.col.f32.bf16.bf16.f32 "
        "{%0,%1,%2,%3},{%4,%5,%6,%7},{%8,%9},{%0,%1,%2,%3};"
        : "+f"(c[0]),"+f"(c[1]),"+f"(c[2]),"+f"(c[3])
        : "r"(a[0]),"r"(a[1]),"r"(a[2]),"r"(a[3]),"r"(b[0]),"r"(b[1]));
}
__device__ __forceinline__ void mma_f16(float* c, const u32* a, const u32* b){
    asm volatile("mma.sync.aligned.m16n8k16.row.col.f32.f16.f16.f32 "
        "{%0,%1,%2,%3},{%4,%5,%6,%7},{%8,%9},{%0,%1,%2,%3};"
        : "+f"(c[0]),"+f"(c[1]),"+f"(c[2]),"+f"(c[3])
        : "r"(a[0]),"r"(a[1]),"r"(a[2]),"r"(a[3]),"r"(b[0]),"r"(b[1]));
}

// -------- scratch -----------------------------------------------------------
__device__ float g_qkv [2][(size_t)TOK*QKVC];
__device__ float g_pool[2][NB*P2*W2KV*CKV];
__device__ float g_mx  [2][NB*P2*DIM];      // window means of x
__device__ float g_qwin[2][NB*P2*QK];
__device__ float g_kwin[2][NB*P2*QK];
__device__ int   g_idx [2][NB*P2*TOPK];
__device__ float g_att [2][(size_t)NB*HH*WW*DIM];
// fp16 hi/lo staging for GEMMs
__device__ __half g_xh[2][(size_t)TOK*DIM];
__device__ __half g_xl[2][(size_t)TOK*DIM];
__device__ __half g_oh[2][(size_t)TOK*DIM];
__device__ __half g_ol[2][(size_t)TOK*DIM];
__device__ __half g_wqh[QKVC*DIM];
__device__ __half g_woh[DIM*DIM];

// ---------------------- input conversion kernels ---------------------------
__global__ __launch_bounds__(256) void k_cvtx(
    const float* __restrict__ x1, const float* __restrict__ x2)
{
    const int z = blockIdx.z;
    const float* X = z ? x2 : x1;
    const int e = blockIdx.x * 256 + threadIdx.x;
    const int t  = e >> 6;
    const int cg = e & 63;
    const int n = t >> 14, r = t & 16383;
    const int win = r >> 8, pix = r & 255;
    const int h = ((win >> 3) << 4) | (pix >> 4);
    const int w = ((win & 7) << 4) | (pix & 15);
    float4 v = *(const float4*)(X + ((size_t)(((n << 7) + h) << 7) + w) * DIM + cg * 4);
    u64 hi, lo; cvt4h(v, hi, lo);
    *(u64*)(&g_xh[z][(size_t)t*DIM + cg*4]) = hi;
    *(u64*)(&g_xl[z][(size_t)t*DIM + cg*4]) = lo;
}

__global__ __launch_bounds__(256) void k_cvtw(
    const float* __restrict__ Wqkv, const float* __restrict__ Wo)
{
    const int e = blockIdx.x * 256 + threadIdx.x;
    if (e < QKVC*DIM/4) {
        float4 v = *(const float4*)(Wqkv + e*4);
        __half2 p0 = __floats2half2_rn(v.x, v.y);
        __half2 p1 = __floats2half2_rn(v.z, v.w);
        *(u64*)(&g_wqh[e*4]) = (u64)*(u32*)&p0 | ((u64)*(u32*)&p1 << 32);
    } else {
        const int f = e - QKVC*DIM/4;
        float4 v = *(const float4*)(Wo + f*4);
        __half2 p0 = __floats2half2_rn(v.x, v.y);
        __half2 p1 = __floats2half2_rn(v.z, v.w);
        *(u64*)(&g_woh[f*4]) = (u64)*(u32*)&p0 | ((u64)*(u32*)&p1 << 32);
    }
}

// ----------------------- exact routing path --------------------------------
// window means of x (fp32, exact up to fp add order)
__global__ __launch_bounds__(256) void k_wmean(
    const float* __restrict__ x1, const float* __restrict__ x2)
{
    const int z = blockIdx.y;
    const float* X = z ? x2 : x1;
    const int nwin = blockIdx.x;
    const int c = threadIdx.x;
    const int n = nwin >> 6, win = nwin & 63;
    const int h0 = (win >> 3) << 4, w0 = (win & 7) << 4;
    const float* base = X + ((size_t)(((n << 7) + h0) << 7) + w0) * DIM + c;
    float s = 0.f;
    #pragma unroll 4
    for (int p = 0; p < 256; p++) {
        const int ph = p >> 4, pw = p & 15;
        s += base[(size_t)(ph*128 + pw) * DIM];
    }
    g_mx[z][nwin*DIM + c] = s * (1.f/256.f);
}

// q_win / k_win = mx @ Wq^T + bq, mx @ Wk^T + bk  (fp32, 4 windows per block)
__global__ __launch_bounds__(256) void k_rwin(
    const float* __restrict__ Wqkv, const float* __restrict__ bqkv)
{
    const int z = blockIdx.y;
    const int wb = blockIdx.x * 4;
    const int j = threadIdx.x;
    __shared__ float smx[4][DIM];
    #pragma unroll
    for (int k = 0; k < 4; k++) smx[k][j] = g_mx[z][(wb + k)*DIM + j];
    __syncthreads();

    const float* wq = Wqkv + (size_t)j*DIM;
    const float* wk = Wqkv + (size_t)(QK + j)*DIM;
    float sq[4] = {0,0,0,0}, sk[4] = {0,0,0,0};
    for (int c = 0; c < DIM; c++) {
        const float wqc = wq[c], wkc = wk[c];
        #pragma unroll
        for (int k = 0; k < 4; k++) {
            sq[k] += smx[k][c] * wqc;
            sk[k] += smx[k][c] * wkc;
        }
    }
    const float bq = bqkv[j], bk = bqkv[QK + j];
    #pragma unroll
    for (int k = 0; k < 4; k++) {
        g_qwin[z][(wb + k)*QK + j] = sq[k] + bq;
        g_kwin[z][(wb + k)*QK + j] = sk[k] + bk;
    }
}

// --------------------- HMMA fp16 2-product GEMM ----------------------------
#define PAD    40
#define TILE_E (128*PAD)
#define TILE_B (TILE_E*2)
#define STAGE_B (3*TILE_B)
#define GEMM_SMEM (2*STAGE_B)    // 60 KB

__global__ __launch_bounds__(256) void k_mma_gemm(
    const __half* __restrict__ Ah, const __half* __restrict__ Al,
    const __half* __restrict__ Wh,
    const float* __restrict__ bias,
    float* __restrict__ Oext, int mode, int ostride)
{
    extern __shared__ __half smx[];

    const int z   = blockIdx.z;
    const int tid = threadIdx.x;
    const int wid = tid >> 5;
    const int lid = tid & 31;
    const int t0  = blockIdx.y * 128;
    const int jn0 = blockIdx.x * 128;

    const size_t zoff = (size_t)z * ((size_t)TOK * DIM);
    const __half* Azh = Ah + zoff;
    const __half* Azl = Al + zoff;
    float* O = (mode == 0) ? g_qkv[z] : (Oext + zoff);

    const int m_base = (wid >> 2) * 64;
    const int n_base = (wid & 3) * 32;

    const int lrow = tid >> 3;
    const int lcg  = tid & 7;

    const __half *arh[4], *arl[4], *brh[4];
    #pragma unroll
    for (int i = 0; i < 4; i++) {
        const size_t ao = (size_t)(t0 + lrow + i*32) * DIM + lcg*4;
        arh[i] = Azh + ao;  arl[i] = Azl + ao;
        brh[i] = Wh + (size_t)(jn0 + lrow + i*32) * DIM + lcg*4;
    }

    const u32 su = smem_u32(smx);

    const int a_r  = lid & 15;
    const int a_kh = lid >> 4;
    const int b_r  = (lid & 7) | ((lid >> 4) << 3);
    const int b_kh = (lid >> 3) & 1;

    float acc[4][4][4];
    #pragma unroll
    for (int mt = 0; mt < 4; mt++)
        #pragma unroll
        for (int nt = 0; nt < 4; nt++)
            #pragma unroll
            for (int r = 0; r < 4; r++) acc[mt][nt][r] = 0.f;

    u64 rah[4], ral[4], rbh[4];
    #pragma unroll
    for (int i = 0; i < 4; i++) {
        rah[i] = *(const u64*)(arh[i]); ral[i] = *(const u64*)(arl[i]);
        rbh[i] = *(const u64*)(brh[i]);
    }

    {
        __half* st = smx;
        #pragma unroll
        for (int i = 0; i < 4; i++) {
            const int off = (lrow + i * 32) * PAD + lcg * 4;
            *(u64*)(st + off)            = rah[i];
            *(u64*)(st + TILE_E + off)   = ral[i];
            *(u64*)(st + 2*TILE_E + off) = rbh[i];
        }
    }
    __syncthreads();

    for (int ch = 0; ch < 8; ch++) {
        const int cur = ch & 1;
        if (ch < 7) {
            const int k1 = (ch + 1) * 32;
            #pragma unroll
            for (int i = 0; i < 4; i++) {
                rah[i] = *(const u64*)(arh[i] + k1);
                ral[i] = *(const u64*)(arl[i] + k1);
                rbh[i] = *(const u64*)(brh[i] + k1);
            }
        }
        const u32 sb = su + cur * STAGE_B;
        #pragma unroll
        for (int s = 0; s < 2; s++) {
            const int koff = s * 16;
            u32 ah[4][4], al[4][4], bh[4][2];
            #pragma unroll
            for (int mt = 0; mt < 4; mt++) {
                const u32 eoff = (u32)((m_base + mt*16 + a_r) * PAD + koff + a_kh*8) * 2;
                ldmx4(sb + eoff,          ah[mt][0], ah[mt][1], ah[mt][2], ah[mt][3]);
                ldmx4(sb + TILE_B + eoff, al[mt][0], al[mt][1], al[mt][2], al[mt][3]);
            }
            #pragma unroll
            for (int p = 0; p < 2; p++) {
                const u32 eoff = (u32)((n_base + p*16 + b_r) * PAD + koff + b_kh*8) * 2;
                ldmx4(sb + 2*TILE_B + eoff, bh[2*p][0], bh[2*p][1], bh[2*p+1][0], bh[2*p+1][1]);
            }
            #pragma unroll
            for (int mt = 0; mt < 4; mt++)
                #pragma unroll
                for (int nt = 0; nt < 4; nt++)
                    mma_f16(acc[mt][nt], ah[mt], bh[nt]);
            #pragma unroll
            for (int mt = 0; mt < 4; mt++)
                #pragma unroll
                for (int nt = 0; nt < 4; nt++)
                    mma_f16(acc[mt][nt], al[mt], bh[nt]);
        }
        if (ch < 7) {
            __half* st = smx + (cur ^ 1) * (3*TILE_E);
            #pragma unroll
            for (int i = 0; i < 4; i++) {
                const int off = (lrow + i * 32) * PAD + lcg * 4;
                *(u64*)(st + off)            = rah[i];
                *(u64*)(st + TILE_E + off)   = ral[i];
                *(u64*)(st + 2*TILE_E + off) = rbh[i];
            }
            __syncthreads();
        }
    }

    const int qr = lid >> 2;
    const int qc = (lid & 3) * 2;
    #pragma unroll
    for (int mt = 0; mt < 4; mt++) {
        const int row0 = t0 + m_base + mt*16 + qr;
        #pragma unroll
        for (int nt = 0; nt < 4; nt++) {
            const int col = jn0 + n_base + nt*8 + qc;
            const float b0 = bias[col], b1 = bias[col+1];
            float2 v0 = make_float2(acc[mt][nt][0] + b0, acc[mt][nt][1] + b1);
            float2 v1 = make_float2(acc[mt][nt][2] + b0, acc[mt][nt][3] + b1);
            *(float2*)(O + (size_t)row0 * ostride + col)       = v0;
            *(float2*)(O + (size_t)(row0+8) * ostride + col)   = v1;
        }
    }
}

// ------------------------------ kv pooling ----------------------------------
__global__ __launch_bounds__(512) void k_pool()
{
    const int b = blockIdx.y;
    const int nwin = blockIdx.x;
    const int c = threadIdx.x;            // kv channel
    const float* base = g_qkv[b] + (size_t)nwin * W2 * QKVC + QK + c;

    float s[16];
    #pragma unroll
    for (int i = 0; i < 16; i++) s[i] = 0.f;
    #pragma unroll 4
    for (int py = 0; py < 16; py++) {
        const int sr = (py >> 2) << 2;
        #pragma unroll
        for (int px = 0; px < 16; px++)
            s[sr + (px >> 2)] += base[(size_t)(py*16 + px) * QKVC];
    }
    #pragma unroll
    for (int i = 0; i < 16; i++)
        g_pool[b][(size_t)(nwin*W2KV + i)*CKV + c] = s[i] * (1.f/16.f);
}

// ------------------------------ routing ------------------------------------
__global__ void k_route()
{
    const int ib = blockIdx.z;
    const int qb = 1 ^ ib, kb = ib;
    const int i = blockIdx.x;
    const int n = blockIdx.y;
    const int j = threadIdx.x;
    const float* qp = g_qwin[qb] + (size_t)(n*P2 + i)*QK;
    const float* kp = g_kwin[kb] + (size_t)(n*P2 + j)*QK;
    float s = 0.f;
    for (int c = 0; c < QK; c++) s += qp[c]*kp[c];
    s *= SCALEF;
    if (j == i) s = 1.0f;
    __shared__ float lg[P2];
    lg[j] = s;
    __syncthreads();
    if (j == 0) {
        #pragma unroll
        for (int t = 0; t < TOPK; t++) {
            float best = -1e30f; int bi = 0;
            for (int u = 0; u < P2; u++)
                if (lg[u] > best) { best = lg[u]; bi = u; }
            g_idx[ib][(n*P2 + i)*TOPK + t] = bi;
            lg[bi] = -1e30f;
        }
    }
}

// ----------------------------- attention (HMMA, bf16 3-product) -------------
#define APQ 40
#define APK 40
#define APV 72
#define OQ_H 0
#define OQ_L (OQ_H + 256*APQ)
#define OK_HH (OQ_L + 256*APQ)
#define OK_LL (OK_HH + 64*APK)
#define OV_HH (OK_LL + 64*APK)
#define OV_LL (OV_HH + 32*APV)
#define ATT_SMEM ((OV_LL + 32*APV)*2)

__global__ __launch_bounds__(256, 2) void k_attend()
{
    extern __shared__ __nv_bfloat16 sma[];
    __shared__ int sel[TOPK];

    const int z = blockIdx.z;
    const int qb = 1 ^ z, kvb = z, ib = z;
    const int nwin = blockIdx.x;
    const int head = blockIdx.y;
    const int n   = nwin >> 6;
    const int win = nwin & 63;
    const int tid = threadIdx.x;
    const int wid = tid >> 5;
    const int lid = tid & 31;

    if (tid < TOPK) sel[tid] = g_idx[ib][nwin*TOPK + tid];
    __syncthreads();

    for (int e = tid; e < 64*32; e += 256) {
        const int tkn = e >> 5, c = e & 31;
        const int sw  = sel[tkn >> 4];
        const float* pp = g_pool[kvb] + (size_t)((n*P2 + sw)*W2KV + (tkn & 15))*CKV;
        const float kv = pp[head*DH + c];
        const float vv = pp[QK + head*DH + c];
        const __nv_bfloat16 kh = __float2bfloat16_rn(kv);
        sma[OK_HH + tkn*APK + c] = kh;
        sma[OK_LL + tkn*APK + c] = __float2bfloat16_rn(kv - __bfloat162float(kh));
        const __nv_bfloat16 vh = __float2bfloat16_rn(vv);
        sma[OV_HH + c*APV + tkn] = vh;
        sma[OV_LL + c*APV + tkn] = __float2bfloat16_rn(vv - __bfloat162float(vh));
    }
    {
        const float* qp = g_qkv[qb] + (size_t)(nwin*W2 + tid)*QKVC + head*DH;
        #pragma unroll
        for (int cg = 0; cg < 8; cg++) {
            float4 v = *(const float4*)(qp + cg*4);
            v.x *= SCALEF; v.y *= SCALEF; v.z *= SCALEF; v.w *= SCALEF;
            u64 hi, lo; cvt4(v, hi, lo);
            *(u64*)(&sma[OQ_H + tid*APQ + cg*4]) = hi;
            *(u64*)(&sma[OQ_L + tid*APQ + cg*4]) = lo;
        }
    }
    __syncthreads();

    const u32 su = smem_u32(sma);
    const int a_r  = lid & 15;
    const int a_kh = lid >> 4;
    const int b_r  = (lid & 7) | ((lid >> 4) << 3);
    const int b_kh = (lid >> 3) & 1;
    const int m_base = wid * 32;

    float oacc[2][4][4];
    #pragma unroll
    for (int mt = 0; mt < 2; mt++)
        #pragma unroll
        for (int nt = 0; nt < 4; nt++)
            #pragma unroll
            for (int r = 0; r < 4; r++) oacc[mt][nt][r] = 0.f;
    float den0[2] = {0.f, 0.f}, den1[2] = {0.f, 0.f};

    for (int chn = 0; chn < 4; chn++) {
        float sacc[2][2][4];
        #pragma unroll
        for (int mt = 0; mt < 2; mt++)
            #pragma unroll
            for (int p = 0; p < 2; p++)
                #pragma unroll
                for (int r = 0; r < 4; r++) sacc[mt][p][r] = 0.f;

        #pragma unroll
        for (int ks = 0; ks < 2; ks++) {
            u32 qh[2][4], ql[2][4];
            #pragma unroll
            for (int mt = 0; mt < 2; mt++) {
                const u32 qoff = (u32)((m_base + mt*16 + a_r)*APQ + ks*16 + a_kh*8) * 2;
                ldmx4(su + OQ_H*2 + qoff, qh[mt][0], qh[mt][1], qh[mt][2], qh[mt][3]);
                ldmx4(su + OQ_L*2 + qoff, ql[mt][0], ql[mt][1], ql[mt][2], ql[mt][3]);
            }
            u32 kh[2][2], kl[2][2];
            const u32 koff = (u32)((chn*16 + b_r)*APK + ks*16 + b_kh*8) * 2;
            ldmx4(su + OK_HH*2 + koff, kh[0][0], kh[0][1], kh[1][0], kh[1][1]);
            ldmx4(su + OK_LL*2 + koff, kl[0][0], kl[0][1], kl[1][0], kl[1][1]);
            #pragma unroll
            for (int mt = 0; mt < 2; mt++)
                #pragma unroll
                for (int p = 0; p < 2; p++)
                    mma_bf(sacc[mt][p], qh[mt], kh[p]);
            #pragma unroll
            for (int mt = 0; mt < 2; mt++)
                #pragma unroll
                for (int p = 0; p < 2; p++)
                    mma_bf(sacc[mt][p], qh[mt], kl[p]);
            #pragma unroll
            for (int mt = 0; mt < 2; mt++)
                #pragma unroll
                for (int p = 0; p < 2; p++)
                    mma_bf(sacc[mt][p], ql[mt], kh[p]);
        }

        u32 pa_h[2][4], pa_l[2][4];
        #pragma unroll
        for (int mt = 0; mt < 2; mt++) {
            float e[2][4];
            #pragma unroll
            for (int p = 0; p < 2; p++)
                #pragma unroll
                for (int r = 0; r < 4; r++)
                    e[p][r] = __expf(sacc[mt][p][r]);
            den0[mt] += (e[0][0] + e[0][1]) + (e[1][0] + e[1][1]);
            den1[mt] += (e[0][2] + e[0][3]) + (e[1][2] + e[1][3]);
            float hf[2][4], lf[2][4];
            #pragma unroll
            for (int p = 0; p < 2; p++)
                #pragma unroll
                for (int r = 0; r < 4; r++) {
                    hf[p][r] = __bfloat162float(__float2bfloat16_rn(e[p][r]));
                    lf[p][r] = e[p][r] - hf[p][r];
                }
            pa_h[mt][0] = pkbf(hf[0][0], hf[0][1]);
            pa_h[mt][1] = pkbf(hf[0][2], hf[0][3]);
            pa_h[mt][2] = pkbf(hf[1][0], hf[1][1]);
            pa_h[mt][3] = pkbf(hf[1][2], hf[1][3]);
            pa_l[mt][0] = pkbf(lf[0][0], lf[0][1]);
            pa_l[mt][1] = pkbf(lf[0][2], lf[0][3]);
            pa_l[mt][2] = pkbf(lf[1][0], lf[1][1]);
            pa_l[mt][3] = pkbf(lf[1][2], lf[1][3]);
        }

        u32 vh[4][2], vl[4][2];
        #pragma unroll
        for (int p = 0; p < 2; p++) {
            const u32 voff = (u32)((p*16 + b_r)*APV + chn*16 + b_kh*8) * 2;
            ldmx4(su + OV_HH*2 + voff, vh[2*p][0], vh[2*p][1], vh[2*p+1][0], vh[2*p+1][1]);
            ldmx4(su + OV_LL*2 + voff, vl[2*p][0], vl[2*p][1], vl[2*p+1][0], vl[2*p+1][1]);
        }
        #pragma unroll
        for (int mt = 0; mt < 2; mt++)
            #pragma unroll
            for (int nt = 0; nt < 4; nt++)
                mma_bf(oacc[mt][nt], pa_h[mt], vh[nt]);
        #pragma unroll
        for (int mt = 0; mt < 2; mt++)
            #pragma unroll
            for (int nt = 0; nt < 4; nt++)
                mma_bf(oacc[mt][nt], pa_h[mt], vl[nt]);
        #pragma unroll
        for (int mt = 0; mt < 2; mt++)
            #pragma unroll
            for (int nt = 0; nt < 4; nt++)
                mma_bf(oacc[mt][nt], pa_l[mt], vh[nt]);
    }

    #pragma unroll
    for (int mt = 0; mt < 2; mt++) {
        den0[mt] += __shfl_xor_sync(0xffffffffu, den0[mt], 1);
        den0[mt] += __shfl_xor_sync(0xffffffffu, den0[mt], 2);
        den1[mt] += __shfl_xor_sync(0xffffffffu, den1[mt], 1);
        den1[mt] += __shfl_xor_sync(0xffffffffu, den1[mt], 2);
    }

    const int g = lid >> 2;
    const int t = lid & 3;
    #pragma unroll
    for (int mt = 0; mt < 2; mt++) {
        const float i0 = 1.f / den0[mt];
        const float i1 = 1.f / den1[mt];
        const int pr0 = m_base + mt*16 + g;
        const int pr1 = pr0 + 8;
        const int h0 = ((win >> 3) << 4) | (pr0 >> 4);
        const int w0 = ((win & 7)  << 4) | (pr0 & 15);
        const int h1 = ((win >> 3) << 4) | (pr1 >> 4);
        const int w1 = ((win & 7)  << 4) | (pr1 & 15);
        float* op0 = g_att[z] + (size_t)(((n << 7) + h0)*WW + w0)*DIM + head*DH;
        float* op1 = g_att[z] + (size_t)(((n << 7) + h1)*WW + w1)*DIM + head*DH;
        #pragma unroll
        for (int nt = 0; nt < 4; nt++) {
            *(float2*)(op0 + nt*8 + 2*t) =
                make_float2(oacc[mt][nt][0] * i0, oacc[mt][nt][1] * i0);
            *(float2*)(op1 + nt*8 + 2*t) =
                make_float2(oacc[mt][nt][2] * i1, oacc[mt][nt][3] * i1);
        }
    }
}

// --------------------------- lepe (depthwise 3x3) --------------------------
__global__ __launch_bounds__(256) void k_lepe(
    const float* __restrict__ lw, const float* __restrict__ lb)
{
    const int vb = blockIdx.z, ob = blockIdx.z;
    __shared__ float swt[DIM*9];
    const int blk = blockIdx.x;
    const int c = threadIdx.x;
    for (int e = c; e < DIM*9; e += 256) swt[e] = lw[e];
    __syncthreads();

    const int n  = blk >> 12;
    const int r  = blk & 4095;
    const int h  = r >> 5;
    const int w0 = (r & 31) << 2;

    const float* wrow = &swt[c*9];
    const size_t pbase = (size_t)((((n << 7) + h) << 7) + w0);
    float acc[4];
    {
        const float* op = g_att[ob] + pbase*DIM + c;
        const float bb = lb[c];
        #pragma unroll
        for (int k = 0; k < 4; k++) acc[k] = op[k*DIM] + bb;
    }

    #pragma unroll
    for (int dy = 0; dy < 3; dy++) {
        const int hh = h + dy - 1;
        if ((unsigned)hh >= (unsigned)HH) continue;
        #pragma unroll
        for (int cc = 0; cc < 6; cc++) {
            const int ww = w0 - 1 + cc;
            if ((unsigned)ww >= (unsigned)WW) continue;
            const int vwin = ((hh >> 4) << 3) | (ww >> 4);
            const int vpix = ((hh & 15) << 4) | (ww & 15);
            const float v = g_qkv[vb]
                [(size_t)(((n << 6) | vwin)*W2 + vpix)*QKVC + CKV + c];
            #pragma unroll
            for (int k = 0; k < 4; k++) {
                const int dx = cc - k;
                if (dx >= 0 && dx <= 2)
                    acc[k] += v * wrow[dy*3 + dx];
            }
        }
    }

    #pragma unroll
    for (int k = 0; k < 4; k++) {
        const __half hv = __float2half_rn(acc[k]);
        g_oh[ob][(pbase + k)*DIM + c] = hv;
        g_ol[ob][(pbase + k)*DIM + c] = __float2half_rn(acc[k] - __half2float(hv));
    }
}

// ------------------------------- launch ------------------------------------
extern "C" void kernel_launch(void* const* d_in, const int* in_sizes, int n_in,
                              void* d_out, int out_size)
{
    const float* x1   = (const float*)d_in[0];
    const float* x2   = (const float*)d_in[1];
    const float* Wqkv = (const float*)d_in[2];
    const float* bqkv = (const float*)d_in[3];
    const float* lw   = (const float*)d_in[4];
    const float* lb   = (const float*)d_in[5];
    const float* Wo   = (const float*)d_in[6];
    const float* bo   = (const float*)d_in[7];
    float* out = (float*)d_out;

    cudaFuncSetAttribute(k_mma_gemm,
        cudaFuncAttributeMaxDynamicSharedMemorySize, GEMM_SMEM);
    cudaFuncSetAttribute(k_attend,
        cudaFuncAttributeMaxDynamicSharedMemorySize, ATT_SMEM);

    __half *xh, *xl, *oh, *ol, *wqh, *woh;
    cudaGetSymbolAddress((void**)&xh, g_xh);
    cudaGetSymbolAddress((void**)&xl, g_xl);
    cudaGetSymbolAddress((void**)&oh, g_oh);
    cudaGetSymbolAddress((void**)&ol, g_ol);
    cudaGetSymbolAddress((void**)&wqh, g_wqh);
    cudaGetSymbolAddress((void**)&woh, g_woh);

    k_cvtx<<<dim3(TOK*DIM/4/256, 1, 2), 256>>>(x1, x2);
    k_cvtw<<<(QKVC*DIM/4 + DIM*DIM/4)/256, 256>>>(Wqkv, Wo);

    // exact routing path (independent of the fp16 GEMMs)
    k_wmean<<<dim3(NB*P2, 2), 256>>>(x1, x2);
    k_rwin<<<dim3(NB*P2/4, 2), 256>>>(Wqkv, bqkv);

    k_mma_gemm<<<dim3(QKVC/128, TOK/128, 2), 256, GEMM_SMEM>>>(
        xh, xl, wqh, bqkv, nullptr, 0, QKVC);

    k_pool<<<dim3(NB*P2, 2), 512>>>();

    k_route<<<dim3(P2, NB, 2), 64>>>();

    k_attend<<<dim3(NB*P2, HEADS, 2), 256, ATT_SMEM>>>();

    k_lepe<<<dim3(NB*HH*WW/4, 1, 2), 256>>>(lw, lb);

    k_mma_gemm<<<dim3(DIM/128, TOK/128, 2), 256, GEMM_SMEM>>>(
        oh, ol, woh, bo, out, 1, DIM);
}

// round 17
// speedup vs baseline: 2.2888x; 1.2115x over previous
#include <cuda_runtime.h>
#include <cuda_bf16.h>
#include <cuda_fp16.h>
#include <cstdint>

// ---------------------------------------------------------------------------
// SpatialEncoder: bi-level routing attention.
// Pooling commutes with the affine QKV projection:
//   - routing q_win/k_win computed EXACTLY from window means of x (fp32)
//   - pooled K,V computed from 4x4-sector means of x via a tiny fp16 GEMM
//   - the big GEMM computes only Q,V per token (N=512 instead of 768)
// GEMMs: mma.sync fp16 2-product (A split, W single). attend: bf16 3-product.
// ---------------------------------------------------------------------------

#define NB    4
#define HH    128
#define WW    128
#define DIM   256
#define QK    256
#define CKV   512
#define QVC   512
#define NW    8
#define P2    64
#define W2    256
#define W2KV  16
#define TOPK  4
#define HEADS 8
#define DH    32
#define TOK   (NB*P2*W2)
#define POOLM (NB*P2*W2KV)      // 4096 pooled rows per branch
#define SCALEF 0.0625f

typedef unsigned long long u64;
typedef unsigned int u32;

__device__ __forceinline__ u32 smem_u32(const void* p){
    u32 a; asm("{ .reg .u64 t; cvta.to.shared.u64 t, %1; cvt.u32.u64 %0, t; }"
               : "=r"(a) : "l"(p));
    return a;
}

// fp32 float4 -> fp16 hi u64 + fp16 lo u64
__device__ __forceinline__ void cvt4h(float4 v, u64& hi, u64& lo){
    __half h0=__float2half_rn(v.x), h1=__float2half_rn(v.y);
    __half h2=__float2half_rn(v.z), h3=__float2half_rn(v.w);
    unsigned short a0=__half_as_ushort(h0), a1=__half_as_ushort(h1);
    unsigned short a2=__half_as_ushort(h2), a3=__half_as_ushort(h3);
    hi = (u64)a0 | ((u64)a1<<16) | ((u64)a2<<32) | ((u64)a3<<48);
    unsigned short b0=__half_as_ushort(__float2half_rn(v.x-__half2float(h0)));
    unsigned short b1=__half_as_ushort(__float2half_rn(v.y-__half2float(h1)));
    unsigned short b2=__half_as_ushort(__float2half_rn(v.z-__half2float(h2)));
    unsigned short b3=__half_as_ushort(__float2half_rn(v.w-__half2float(h3)));
    lo = (u64)b0 | ((u64)b1<<16) | ((u64)b2<<32) | ((u64)b3<<48);
}

// fp32 float4 -> bf16 hi/lo (attend path)
__device__ __forceinline__ void cvt4(float4 v, u64& hi, u64& lo){
    __nv_bfloat16 h0=__float2bfloat16_rn(v.x), h1=__float2bfloat16_rn(v.y);
    __nv_bfloat16 h2=__float2bfloat16_rn(v.z), h3=__float2bfloat16_rn(v.w);
    unsigned short a0=__bfloat16_as_ushort(h0), a1=__bfloat16_as_ushort(h1);
    unsigned short a2=__bfloat16_as_ushort(h2), a3=__bfloat16_as_ushort(h3);
    hi = (u64)a0 | ((u64)a1<<16) | ((u64)a2<<32) | ((u64)a3<<48);
    unsigned short b0=__bfloat16_as_ushort(__float2bfloat16_rn(v.x-__bfloat162float(h0)));
    unsigned short b1=__bfloat16_as_ushort(__float2bfloat16_rn(v.y-__bfloat162float(h1)));
    unsigned short b2=__bfloat16_as_ushort(__float2bfloat16_rn(v.z-__bfloat162float(h2)));
    unsigned short b3=__bfloat16_as_ushort(__float2bfloat16_rn(v.w-__bfloat162float(h3)));
    lo = (u64)b0 | ((u64)b1<<16) | ((u64)b2<<32) | ((u64)b3<<48);
}

__device__ __forceinline__ u32 pkbf(float lo, float hi){
    u32 d; asm("cvt.rn.bf16x2.f32 %0,%1,%2;" : "=r"(d) : "f"(hi), "f"(lo));
    return d;
}

__device__ __forceinline__ void ldmx4(u32 addr, u32& r0, u32& r1, u32& r2, u32& r3){
    asm volatile("ldmatrix.sync.aligned.m8n8.x4.shared.b16 {%0,%1,%2,%3},[%4];"
                 : "=r"(r0),"=r"(r1),"=r"(r2),"=r"(r3) : "r"(addr));
}
__device__ __forceinline__ void mma_bf(float* c, const u32* a, const u32* b){
    asm volatile("mma.sync.aligned.m16n8k16.row.col.f32.bf16.bf16.f32 "
        "{%0,%1,%2,%3},{%4,%5,%6,%7},{%8,%9},{%0,%1,%2,%3};"
        : "+f"(c[0]),"+f"(c[1]),"+f"(c[2]),"+f"(c[3])
        : "r"(a[0]),"r"(a[1]),"r"(a[2]),"r"(a[3]),"r"(b[0]),"r"(b[1]));
}
__device__ __forceinline__ void mma_f16(float* c, const u32* a, const u32* b){
    asm volatile("mma.sync.aligned.m16n8k16.row.col.f32.f16.f16.f32 "
        "{%0,%1,%2,%3},{%4,%5,%6,%7},{%8,%9},{%0,%1,%2,%3};"
        : "+f"(c[0]),"+f"(c[1]),"+f"(c[2]),"+f"(c[3])
        : "r"(a[0]),"r"(a[1]),"r"(a[2]),"r"(a[3]),"r"(b[0]),"r"(b[1]));
}

// -------- scratch -----------------------------------------------------------
__device__ float g_qv  [2][(size_t)TOK*QVC];    // Q (0..255), V (256..511)
__device__ float g_pool[2][POOLM*CKV];          // pooled K (0..255), V (256..511)
__device__ float g_mx  [2][NB*P2*DIM];          // window means of x (fp32)
__device__ float g_qwin[2][NB*P2*QK];
__device__ float g_kwin[2][NB*P2*QK];
__device__ int   g_idx [2][NB*P2*TOPK];
__device__ float g_att [2][(size_t)NB*HH*WW*DIM];
// fp16 hi/lo staging
__device__ __half g_xh [2][(size_t)TOK*DIM];
__device__ __half g_xl [2][(size_t)TOK*DIM];
__device__ __half g_pxh[2][POOLM*DIM];          // sector means of x
__device__ __half g_pxl[2][POOLM*DIM];
__device__ __half g_oh [2][(size_t)TOK*DIM];
__device__ __half g_ol [2][(size_t)TOK*DIM];
__device__ __half g_wqvh[QVC*DIM];              // Q rows 0..255 + V rows 512..767
__device__ __half g_wkvh[CKV*DIM];              // KV rows 256..767
__device__ __half g_woh [DIM*DIM];
__device__ float  g_bqv [QVC];                  // bias for QV GEMM

// ---------------------- input conversion kernels ---------------------------
__global__ __launch_bounds__(256) void k_cvtx(
    const float* __restrict__ x1, const float* __restrict__ x2)
{
    const int z = blockIdx.z;
    const float* X = z ? x2 : x1;
    const int e = blockIdx.x * 256 + threadIdx.x;
    const int t  = e >> 6;
    const int cg = e & 63;
    const int n = t >> 14, r = t & 16383;
    const int win = r >> 8, pix = r & 255;
    const int h = ((win >> 3) << 4) | (pix >> 4);
    const int w = ((win & 7) << 4) | (pix & 15);
    float4 v = *(const float4*)(X + ((size_t)(((n << 7) + h) << 7) + w) * DIM + cg * 4);
    u64 hi, lo; cvt4h(v, hi, lo);
    *(u64*)(&g_xh[z][(size_t)t*DIM + cg*4]) = hi;
    *(u64*)(&g_xl[z][(size_t)t*DIM + cg*4]) = lo;
}

__global__ __launch_bounds__(256) void k_cvtw(
    const float* __restrict__ Wqkv, const float* __restrict__ bqkv,
    const float* __restrict__ Wo)
{
    const int g = blockIdx.x * 256 + threadIdx.x;
    if (g < QVC) g_bqv[g] = bqkv[g < QK ? g : g + 256];

    const int e = g;                               // float4 index
    const int NQV = QVC*DIM/4, NKV = CKV*DIM/4, NWO = DIM*DIM/4;
    if (e < NQV) {
        const int row = e >> 6;
        const int src = (row < QK) ? row : row + 256;
        float4 v = *(const float4*)(Wqkv + (size_t)src*DIM + (e & 63)*4);
        __half2 p0 = __floats2half2_rn(v.x, v.y);
        __half2 p1 = __floats2half2_rn(v.z, v.w);
        *(u64*)(&g_wqvh[e*4]) = (u64)*(u32*)&p0 | ((u64)*(u32*)&p1 << 32);
    } else if (e < NQV + NKV) {
        const int f = e - NQV;
        float4 v = *(const float4*)(Wqkv + (size_t)QK*DIM + f*4);
        __half2 p0 = __floats2half2_rn(v.x, v.y);
        __half2 p1 = __floats2half2_rn(v.z, v.w);
        *(u64*)(&g_wkvh[f*4]) = (u64)*(u32*)&p0 | ((u64)*(u32*)&p1 << 32);
    } else if (e < NQV + NKV + NWO) {
        const int f = e - NQV - NKV;
        float4 v = *(const float4*)(Wo + f*4);
        __half2 p0 = __floats2half2_rn(v.x, v.y);
        __half2 p1 = __floats2half2_rn(v.z, v.w);
        *(u64*)(&g_woh[f*4]) = (u64)*(u32*)&p0 | ((u64)*(u32*)&p1 << 32);
    }
}

// -------------------- sector means of x + window means ----------------------
__global__ __launch_bounds__(256) void k_pxm(
    const float* __restrict__ x1, const float* __restrict__ x2)
{
    const int z = blockIdx.y;
    const float* X = z ? x2 : x1;
    const int nwin = blockIdx.x;
    const int c = threadIdx.x;
    const int n = nwin >> 6, win = nwin & 63;
    const int h0 = (win >> 3) << 4, w0 = (win & 7) << 4;
    const float* base = X + ((size_t)(((n << 7) + h0) << 7) + w0) * DIM + c;

    float s[16];
    #pragma unroll
    for (int i = 0; i < 16; i++) s[i] = 0.f;
    #pragma unroll 4
    for (int py = 0; py < 16; py++) {
        const int sr = (py >> 2) << 2;
        #pragma unroll
        for (int px = 0; px < 16; px++)
            s[sr + (px >> 2)] += base[(size_t)(py*128 + px) * DIM];
    }
    float tot = 0.f;
    #pragma unroll
    for (int i = 0; i < 16; i++) tot += s[i];
    g_mx[z][nwin*DIM + c] = tot * (1.f/256.f);

    #pragma unroll
    for (int i = 0; i < 16; i++) {
        const float pv = s[i] * (1.f/16.f);
        const __half hv = __float2half_rn(pv);
        const size_t o = (size_t)(nwin*W2KV + i)*DIM + c;
        g_pxh[z][o] = hv;
        g_pxl[z][o] = __float2half_rn(pv - __half2float(hv));
    }
}

// --------------- routing q_win/k_win (exact, warp-cooperative) --------------
__global__ __launch_bounds__(256) void k_rwin(
    const float* __restrict__ Wqkv, const float* __restrict__ bqkv)
{
    const int z = blockIdx.y;
    const int wb = blockIdx.x * 4;
    const int tid = threadIdx.x;
    const int w = tid >> 5, lane = tid & 31;
    __shared__ float smx[4][DIM];
    #pragma unroll
    for (int k = 0; k < 4; k++) smx[k][tid] = g_mx[z][(wb + k)*DIM + tid];
    __syncthreads();

    for (int j = w; j < 512; j += 8) {
        const float* wr = Wqkv + (size_t)j*DIM + lane;
        float a0=0.f, a1=0.f, a2=0.f, a3=0.f;
        #pragma unroll
        for (int k8 = 0; k8 < 8; k8++) {
            const float wv = wr[k8*32];
            const int c = lane + k8*32;
            a0 += smx[0][c]*wv; a1 += smx[1][c]*wv;
            a2 += smx[2][c]*wv; a3 += smx[3][c]*wv;
        }
        #pragma unroll
        for (int off = 16; off; off >>= 1) {
            a0 += __shfl_xor_sync(0xffffffffu, a0, off);
            a1 += __shfl_xor_sync(0xffffffffu, a1, off);
            a2 += __shfl_xor_sync(0xffffffffu, a2, off);
            a3 += __shfl_xor_sync(0xffffffffu, a3, off);
        }
        if (lane == 0) {
            const float b = bqkv[j];
            if (j < QK) {
                g_qwin[z][(wb+0)*QK + j] = a0 + b;
                g_qwin[z][(wb+1)*QK + j] = a1 + b;
                g_qwin[z][(wb+2)*QK + j] = a2 + b;
                g_qwin[z][(wb+3)*QK + j] = a3 + b;
            } else {
                const int jk = j - QK;
                g_kwin[z][(wb+0)*QK + jk] = a0 + b;
                g_kwin[z][(wb+1)*QK + jk] = a1 + b;
                g_kwin[z][(wb+2)*QK + jk] = a2 + b;
                g_kwin[z][(wb+3)*QK + jk] = a3 + b;
            }
        }
    }
}

// --------------------- HMMA fp16 2-product GEMM ----------------------------
#define PAD    40
#define TILE_E (128*PAD)
#define TILE_B (TILE_E*2)
#define STAGE_B (3*TILE_B)
#define GEMM_SMEM (2*STAGE_B)    // 60 KB

__global__ __launch_bounds__(256) void k_mma_gemm(
    const __half* __restrict__ Ah, const __half* __restrict__ Al,
    size_t a_zstride,
    const __half* __restrict__ Wh,
    const float* __restrict__ bias,
    float* __restrict__ Oext, int mode, int ostride)
{
    extern __shared__ __half smx[];

    const int z   = blockIdx.z;
    const int tid = threadIdx.x;
    const int wid = tid >> 5;
    const int lid = tid & 31;
    const int t0  = blockIdx.y * 128;
    const int jn0 = blockIdx.x * 128;

    const __half* Azh = Ah + (size_t)z * a_zstride;
    const __half* Azl = Al + (size_t)z * a_zstride;
    float* O;
    if (mode == 0)      O = g_qv[z];
    else if (mode == 1) O = Oext + (size_t)z * ((size_t)TOK * DIM);
    else                O = g_pool[z];

    const int m_base = (wid >> 2) * 64;
    const int n_base = (wid & 3) * 32;

    const int lrow = tid >> 3;
    const int lcg  = tid & 7;

    const __half *arh[4], *arl[4], *brh[4];
    #pragma unroll
    for (int i = 0; i < 4; i++) {
        const size_t ao = (size_t)(t0 + lrow + i*32) * DIM + lcg*4;
        arh[i] = Azh + ao;  arl[i] = Azl + ao;
        brh[i] = Wh + (size_t)(jn0 + lrow + i*32) * DIM + lcg*4;
    }

    const u32 su = smem_u32(smx);

    const int a_r  = lid & 15;
    const int a_kh = lid >> 4;
    const int b_r  = (lid & 7) | ((lid >> 4) << 3);
    const int b_kh = (lid >> 3) & 1;

    float acc[4][4][4];
    #pragma unroll
    for (int mt = 0; mt < 4; mt++)
        #pragma unroll
        for (int nt = 0; nt < 4; nt++)
            #pragma unroll
            for (int r = 0; r < 4; r++) acc[mt][nt][r] = 0.f;

    u64 rah[4], ral[4], rbh[4];
    #pragma unroll
    for (int i = 0; i < 4; i++) {
        rah[i] = *(const u64*)(arh[i]); ral[i] = *(const u64*)(arl[i]);
        rbh[i] = *(const u64*)(brh[i]);
    }

    {
        __half* st = smx;
        #pragma unroll
        for (int i = 0; i < 4; i++) {
            const int off = (lrow + i * 32) * PAD + lcg * 4;
            *(u64*)(st + off)            = rah[i];
            *(u64*)(st + TILE_E + off)   = ral[i];
            *(u64*)(st + 2*TILE_E + off) = rbh[i];
        }
    }
    __syncthreads();

    for (int ch = 0; ch < 8; ch++) {
        const int cur = ch & 1;
        if (ch < 7) {
            const int k1 = (ch + 1) * 32;
            #pragma unroll
            for (int i = 0; i < 4; i++) {
                rah[i] = *(const u64*)(arh[i] + k1);
                ral[i] = *(const u64*)(arl[i] + k1);
                rbh[i] = *(const u64*)(brh[i] + k1);
            }
        }
        const u32 sb = su + cur * STAGE_B;
        #pragma unroll
        for (int s = 0; s < 2; s++) {
            const int koff = s * 16;
            u32 ah[4][4], al[4][4], bh[4][2];
            #pragma unroll
            for (int mt = 0; mt < 4; mt++) {
                const u32 eoff = (u32)((m_base + mt*16 + a_r) * PAD + koff + a_kh*8) * 2;
                ldmx4(sb + eoff,          ah[mt][0], ah[mt][1], ah[mt][2], ah[mt][3]);
                ldmx4(sb + TILE_B + eoff, al[mt][0], al[mt][1], al[mt][2], al[mt][3]);
            }
            #pragma unroll
            for (int p = 0; p < 2; p++) {
                const u32 eoff = (u32)((n_base + p*16 + b_r) * PAD + koff + b_kh*8) * 2;
                ldmx4(sb + 2*TILE_B + eoff, bh[2*p][0], bh[2*p][1], bh[2*p+1][0], bh[2*p+1][1]);
            }
            #pragma unroll
            for (int mt = 0; mt < 4; mt++)
                #pragma unroll
                for (int nt = 0; nt < 4; nt++)
                    mma_f16(acc[mt][nt], ah[mt], bh[nt]);
            #pragma unroll
            for (int mt = 0; mt < 4; mt++)
                #pragma unroll
                for (int nt = 0; nt < 4; nt++)
                    mma_f16(acc[mt][nt], al[mt], bh[nt]);
        }
        if (ch < 7) {
            __half* st = smx + (cur ^ 1) * (3*TILE_E);
            #pragma unroll
            for (int i = 0; i < 4; i++) {
                const int off = (lrow + i * 32) * PAD + lcg * 4;
                *(u64*)(st + off)            = rah[i];
                *(u64*)(st + TILE_E + off)   = ral[i];
                *(u64*)(st + 2*TILE_E + off) = rbh[i];
            }
            __syncthreads();
        }
    }

    const int qr = lid >> 2;
    const int qc = (lid & 3) * 2;
    #pragma unroll
    for (int mt = 0; mt < 4; mt++) {
        const int row0 = t0 + m_base + mt*16 + qr;
        #pragma unroll
        for (int nt = 0; nt < 4; nt++) {
            const int col = jn0 + n_base + nt*8 + qc;
            const float b0 = bias[col], b1 = bias[col+1];
            float2 v0 = make_float2(acc[mt][nt][0] + b0, acc[mt][nt][1] + b1);
            float2 v1 = make_float2(acc[mt][nt][2] + b0, acc[mt][nt][3] + b1);
            *(float2*)(O + (size_t)row0 * ostride + col)       = v0;
            *(float2*)(O + (size_t)(row0+8) * ostride + col)   = v1;
        }
    }
}

// ------------------------------ routing ------------------------------------
__global__ void k_route()
{
    const int ib = blockIdx.z;
    const int qb = 1 ^ ib, kb = ib;
    const int i = blockIdx.x;
    const int n = blockIdx.y;
    const int j = threadIdx.x;
    const float* qp = g_qwin[qb] + (size_t)(n*P2 + i)*QK;
    const float* kp = g_kwin[kb] + (size_t)(n*P2 + j)*QK;
    float s = 0.f;
    for (int c = 0; c < QK; c++) s += qp[c]*kp[c];
    s *= SCALEF;
    if (j == i) s = 1.0f;
    __shared__ float lg[P2];
    lg[j] = s;
    __syncthreads();
    if (j == 0) {
        #pragma unroll
        for (int t = 0; t < TOPK; t++) {
            float best = -1e30f; int bi = 0;
            for (int u = 0; u < P2; u++)
                if (lg[u] > best) { best = lg[u]; bi = u; }
            g_idx[ib][(n*P2 + i)*TOPK + t] = bi;
            lg[bi] = -1e30f;
        }
    }
}

// ----------------------------- attention (HMMA, bf16 3-product) -------------
#define APQ 40
#define APK 40
#define APV 72
#define OQ_H 0
#define OQ_L (OQ_H + 256*APQ)
#define OK_HH (OQ_L + 256*APQ)
#define OK_LL (OK_HH + 64*APK)
#define OV_HH (OK_LL + 64*APK)
#define OV_LL (OV_HH + 32*APV)
#define ATT_SMEM ((OV_LL + 32*APV)*2)

__global__ __launch_bounds__(256, 2) void k_attend()
{
    extern __shared__ __nv_bfloat16 sma[];
    __shared__ int sel[TOPK];

    const int z = blockIdx.z;
    const int qb = 1 ^ z, kvb = z, ib = z;
    const int nwin = blockIdx.x;
    const int head = blockIdx.y;
    const int n   = nwin >> 6;
    const int win = nwin & 63;
    const int tid = threadIdx.x;
    const int wid = tid >> 5;
    const int lid = tid & 31;

    if (tid < TOPK) sel[tid] = g_idx[ib][nwin*TOPK + tid];
    __syncthreads();

    for (int e = tid; e < 64*32; e += 256) {
        const int tkn = e >> 5, c = e & 31;
        const int sw  = sel[tkn >> 4];
        const float* pp = g_pool[kvb] + (size_t)((n*P2 + sw)*W2KV + (tkn & 15))*CKV;
        const float kv = pp[head*DH + c];
        const float vv = pp[QK + head*DH + c];
        const __nv_bfloat16 kh = __float2bfloat16_rn(kv);
        sma[OK_HH + tkn*APK + c] = kh;
        sma[OK_LL + tkn*APK + c] = __float2bfloat16_rn(kv - __bfloat162float(kh));
        const __nv_bfloat16 vh = __float2bfloat16_rn(vv);
        sma[OV_HH + c*APV + tkn] = vh;
        sma[OV_LL + c*APV + tkn] = __float2bfloat16_rn(vv - __bfloat162float(vh));
    }
    {
        const float* qp = g_qv[qb] + (size_t)(nwin*W2 + tid)*QVC + head*DH;
        #pragma unroll
        for (int cg = 0; cg < 8; cg++) {
            float4 v = *(const float4*)(qp + cg*4);
            v.x *= SCALEF; v.y *= SCALEF; v.z *= SCALEF; v.w *= SCALEF;
            u64 hi, lo; cvt4(v, hi, lo);
            *(u64*)(&sma[OQ_H + tid*APQ + cg*4]) = hi;
            *(u64*)(&sma[OQ_L + tid*APQ + cg*4]) = lo;
        }
    }
    __syncthreads();

    const u32 su = smem_u32(sma);
    const int a_r  = lid & 15;
    const int a_kh = lid >> 4;
    const int b_r  = (lid & 7) | ((lid >> 4) << 3);
    const int b_kh = (lid >> 3) & 1;
    const int m_base = wid * 32;

    float oacc[2][4][4];
    #pragma unroll
    for (int mt = 0; mt < 2; mt++)
        #pragma unroll
        for (int nt = 0; nt < 4; nt++)
            #pragma unroll
            for (int r = 0; r < 4; r++) oacc[mt][nt][r] = 0.f;
    float den0[2] = {0.f, 0.f}, den1[2] = {0.f, 0.f};

    for (int chn = 0; chn < 4; chn++) {
        float sacc[2][2][4];
        #pragma unroll
        for (int mt = 0; mt < 2; mt++)
            #pragma unroll
            for (int p = 0; p < 2; p++)
                #pragma unroll
                for (int r = 0; r < 4; r++) sacc[mt][p][r] = 0.f;

        #pragma unroll
        for (int ks = 0; ks < 2; ks++) {
            u32 qh[2][4], ql[2][4];
            #pragma unroll
            for (int mt = 0; mt < 2; mt++) {
                const u32 qoff = (u32)((m_base + mt*16 + a_r)*APQ + ks*16 + a_kh*8) * 2;
                ldmx4(su + OQ_H*2 + qoff, qh[mt][0], qh[mt][1], qh[mt][2], qh[mt][3]);
                ldmx4(su + OQ_L*2 + qoff, ql[mt][0], ql[mt][1], ql[mt][2], ql[mt][3]);
            }
            u32 kh[2][2], kl[2][2];
            const u32 koff = (u32)((chn*16 + b_r)*APK + ks*16 + b_kh*8) * 2;
            ldmx4(su + OK_HH*2 + koff, kh[0][0], kh[0][1], kh[1][0], kh[1][1]);
            ldmx4(su + OK_LL*2 + koff, kl[0][0], kl[0][1], kl[1][0], kl[1][1]);
            #pragma unroll
            for (int mt = 0; mt < 2; mt++)
                #pragma unroll
                for (int p = 0; p < 2; p++)
                    mma_bf(sacc[mt][p], qh[mt], kh[p]);
            #pragma unroll
            for (int mt = 0; mt < 2; mt++)
                #pragma unroll
                for (int p = 0; p < 2; p++)
                    mma_bf(sacc[mt][p], qh[mt], kl[p]);
            #pragma unroll
            for (int mt = 0; mt < 2; mt++)
                #pragma unroll
                for (int p = 0; p < 2; p++)
                    mma_bf(sacc[mt][p], ql[mt], kh[p]);
        }

        u32 pa_h[2][4], pa_l[2][4];
        #pragma unroll
        for (int mt = 0; mt < 2; mt++) {
            float e[2][4];
            #pragma unroll
            for (int p = 0; p < 2; p++)
                #pragma unroll
                for (int r = 0; r < 4; r++)
                    e[p][r] = __expf(sacc[mt][p][r]);
            den0[mt] += (e[0][0] + e[0][1]) + (e[1][0] + e[1][1]);
            den1[mt] += (e[0][2] + e[0][3]) + (e[1][2] + e[1][3]);
            float hf[2][4], lf[2][4];
            #pragma unroll
            for (int p = 0; p < 2; p++)
                #pragma unroll
                for (int r = 0; r < 4; r++) {
                    hf[p][r] = __bfloat162float(__float2bfloat16_rn(e[p][r]));
                    lf[p][r] = e[p][r] - hf[p][r];
                }
            pa_h[mt][0] = pkbf(hf[0][0], hf[0][1]);
            pa_h[mt][1] = pkbf(hf[0][2], hf[0][3]);
            pa_h[mt][2] = pkbf(hf[1][0], hf[1][1]);
            pa_h[mt][3] = pkbf(hf[1][2], hf[1][3]);
            pa_l[mt][0] = pkbf(lf[0][0], lf[0][1]);
            pa_l[mt][1] = pkbf(lf[0][2], lf[0][3]);
            pa_l[mt][2] = pkbf(lf[1][0], lf[1][1]);
            pa_l[mt][3] = pkbf(lf[1][2], lf[1][3]);
        }

        u32 vh[4][2], vl[4][2];
        #pragma unroll
        for (int p = 0; p < 2; p++) {
            const u32 voff = (u32)((p*16 + b_r)*APV + chn*16 + b_kh*8) * 2;
            ldmx4(su + OV_HH*2 + voff, vh[2*p][0], vh[2*p][1], vh[2*p+1][0], vh[2*p+1][1]);
            ldmx4(su + OV_LL*2 + voff, vl[2*p][0], vl[2*p][1], vl[2*p+1][0], vl[2*p+1][1]);
        }
        #pragma unroll
        for (int mt = 0; mt < 2; mt++)
            #pragma unroll
            for (int nt = 0; nt < 4; nt++)
                mma_bf(oacc[mt][nt], pa_h[mt], vh[nt]);
        #pragma unroll
        for (int mt = 0; mt < 2; mt++)
            #pragma unroll
            for (int nt = 0; nt < 4; nt++)
                mma_bf(oacc[mt][nt], pa_h[mt], vl[nt]);
        #pragma unroll
        for (int mt = 0; mt < 2; mt++)
            #pragma unroll
            for (int nt = 0; nt < 4; nt++)
                mma_bf(oacc[mt][nt], pa_l[mt], vh[nt]);
    }

    #pragma unroll
    for (int mt = 0; mt < 2; mt++) {
        den0[mt] += __shfl_xor_sync(0xffffffffu, den0[mt], 1);
        den0[mt] += __shfl_xor_sync(0xffffffffu, den0[mt], 2);
        den1[mt] += __shfl_xor_sync(0xffffffffu, den1[mt], 1);
        den1[mt] += __shfl_xor_sync(0xffffffffu, den1[mt], 2);
    }

    const int g = lid >> 2;
    const int t = lid & 3;
    #pragma unroll
    for (int mt = 0; mt < 2; mt++) {
        const float i0 = 1.f / den0[mt];
        const float i1 = 1.f / den1[mt];
        const int pr0 = m_base + mt*16 + g;
        const int pr1 = pr0 + 8;
        const int h0 = ((win >> 3) << 4) | (pr0 >> 4);
        const int w0 = ((win & 7)  << 4) | (pr0 & 15);
        const int h1 = ((win >> 3) << 4) | (pr1 >> 4);
        const int w1 = ((win & 7)  << 4) | (pr1 & 15);
        float* op0 = g_att[z] + (size_t)(((n << 7) + h0)*WW + w0)*DIM + head*DH;
        float* op1 = g_att[z] + (size_t)(((n << 7) + h1)*WW + w1)*DIM + head*DH;
        #pragma unroll
        for (int nt = 0; nt < 4; nt++) {
            *(float2*)(op0 + nt*8 + 2*t) =
                make_float2(oacc[mt][nt][0] * i0, oacc[mt][nt][1] * i0);
            *(float2*)(op1 + nt*8 + 2*t) =
                make_float2(oacc[mt][nt][2] * i1, oacc[mt][nt][3] * i1);
        }
    }
}

// --------------------------- lepe (depthwise 3x3) --------------------------
__global__ __launch_bounds__(256) void k_lepe(
    const float* __restrict__ lw, const float* __restrict__ lb)
{
    const int vb = blockIdx.z, ob = blockIdx.z;
    __shared__ float swt[DIM*9];
    const int blk = blockIdx.x;
    const int c = threadIdx.x;
    for (int e = c; e < DIM*9; e += 256) swt[e] = lw[e];
    __syncthreads();

    const int n  = blk >> 12;
    const int r  = blk & 4095;
    const int h  = r >> 5;
    const int w0 = (r & 31) << 2;

    const float* wrow = &swt[c*9];
    const size_t pbase = (size_t)((((n << 7) + h) << 7) + w0);
    float acc[4];
    {
        const float* op = g_att[ob] + pbase*DIM + c;
        const float bb = lb[c];
        #pragma unroll
        for (int k = 0; k < 4; k++) acc[k] = op[k*DIM] + bb;
    }

    #pragma unroll
    for (int dy = 0; dy < 3; dy++) {
        const int hh = h + dy - 1;
        if ((unsigned)hh >= (unsigned)HH) continue;
        #pragma unroll
        for (int cc = 0; cc < 6; cc++) {
            const int ww = w0 - 1 + cc;
            if ((unsigned)ww >= (unsigned)WW) continue;
            const int vwin = ((hh >> 4) << 3) | (ww >> 4);
            const int vpix = ((hh & 15) << 4) | (ww & 15);
            const float v = g_qv[vb]
                [(size_t)(((n << 6) | vwin)*W2 + vpix)*QVC + QK + c];
            #pragma unroll
            for (int k = 0; k < 4; k++) {
                const int dx = cc - k;
                if (dx >= 0 && dx <= 2)
                    acc[k] += v * wrow[dy*3 + dx];
            }
        }
    }

    #pragma unroll
    for (int k = 0; k < 4; k++) {
        const __half hv = __float2half_rn(acc[k]);
        g_oh[ob][(pbase + k)*DIM + c] = hv;
        g_ol[ob][(pbase + k)*DIM + c] = __float2half_rn(acc[k] - __half2float(hv));
    }
}

// ------------------------------- launch ------------------------------------
extern "C" void kernel_launch(void* const* d_in, const int* in_sizes, int n_in,
                              void* d_out, int out_size)
{
    const float* x1   = (const float*)d_in[0];
    const float* x2   = (const float*)d_in[1];
    const float* Wqkv = (const float*)d_in[2];
    const float* bqkv = (const float*)d_in[3];
    const float* lw   = (const float*)d_in[4];
    const float* lb   = (const float*)d_in[5];
    const float* Wo   = (const float*)d_in[6];
    const float* bo   = (const float*)d_in[7];
    float* out = (float*)d_out;

    cudaFuncSetAttribute(k_mma_gemm,
        cudaFuncAttributeMaxDynamicSharedMemorySize, GEMM_SMEM);
    cudaFuncSetAttribute(k_attend,
        cudaFuncAttributeMaxDynamicSharedMemorySize, ATT_SMEM);

    __half *xh, *xl, *oh, *ol, *pxh, *pxl, *wqvh, *wkvh, *woh;
    float *bqv;
    cudaGetSymbolAddress((void**)&xh,  g_xh);
    cudaGetSymbolAddress((void**)&xl,  g_xl);
    cudaGetSymbolAddress((void**)&oh,  g_oh);
    cudaGetSymbolAddress((void**)&ol,  g_ol);
    cudaGetSymbolAddress((void**)&pxh, g_pxh);
    cudaGetSymbolAddress((void**)&pxl, g_pxl);
    cudaGetSymbolAddress((void**)&wqvh, g_wqvh);
    cudaGetSymbolAddress((void**)&wkvh, g_wkvh);
    cudaGetSymbolAddress((void**)&woh,  g_woh);
    cudaGetSymbolAddress((void**)&bqv,  g_bqv);

    k_cvtx<<<dim3(TOK*DIM/4/256, 1, 2), 256>>>(x1, x2);
    k_cvtw<<<(QVC*DIM/4 + CKV*DIM/4 + DIM*DIM/4)/256, 256>>>(Wqkv, bqkv, Wo);

    // sector means + window means (exact) and routing windows
    k_pxm<<<dim3(NB*P2, 2), 256>>>(x1, x2);
    k_rwin<<<dim3(NB*P2/4, 2), 256>>>(Wqkv, bqkv);

    // Q,V per token (N=512)
    k_mma_gemm<<<dim3(QVC/128, TOK/128, 2), 256, GEMM_SMEM>>>(
        xh, xl, (size_t)TOK*DIM, wqvh, bqv, nullptr, 0, QVC);

    // pooled K,V directly from sector means (M=4096 per branch)
    k_mma_gemm<<<dim3(CKV/128, POOLM/128, 2), 256, GEMM_SMEM>>>(
        pxh, pxl, (size_t)POOLM*DIM, wkvh, bqkv + QK, nullptr, 2, CKV);

    k_route<<<dim3(P2, NB, 2), 64>>>();

    k_attend<<<dim3(NB*P2, HEADS, 2), 256, ATT_SMEM>>>();

    k_lepe<<<dim3(NB*HH*WW/4, 1, 2), 256>>>(lw, lb);

    k_mma_gemm<<<dim3(DIM/128, TOK/128, 2), 256, GEMM_SMEM>>>(
        oh, ol, (size_t)TOK*DIM, woh, bo, out, 1, DIM);
}